// round 11
// baseline (speedup 1.0000x reference)
#include <cuda_runtime.h>
#include <cuda_bf16.h>
#include <math.h>
#include <stdint.h>

// ---------------------------------------------------------------------------
// Problem constants
// ---------------------------------------------------------------------------
#define BATCH   2
#define NSEQ    2048
#define DMODEL  1024
#define HEADS   16
#define DH      64
#define INNER   1024
#define NROWS   (BATCH*NSEQ)   // 4096
#define SCALE   0.125f
#define SC2     (0.125f * 1.4426950408889634f)   // SCALE * log2(e)
#define LN_EPS  1e-5f

// ---------------------------------------------------------------------------
// Scratch (__device__ globals; no allocs allowed)
// ---------------------------------------------------------------------------
__device__ __nv_bfloat16 g_xn_h [(size_t)NROWS * DMODEL];
__device__ __nv_bfloat16 g_xn_l [(size_t)NROWS * DMODEL];
__device__ __nv_bfloat16 g_wq_h [(size_t)3*INNER * DMODEL];   // Wqkv^T [3072][1024]
__device__ __nv_bfloat16 g_wq_l [(size_t)3*INNER * DMODEL];
__device__ __nv_bfloat16 g_wo_h [(size_t)DMODEL * INNER];     // Wout^T
__device__ __nv_bfloat16 g_wo_l [(size_t)DMODEL * INNER];
__device__ __nv_bfloat16 g_qkv_h[(size_t)NROWS * 3 * INNER];  // bf16 hi QKV
__device__ __nv_bfloat16 g_qkv_l[(size_t)NROWS * 3 * INNER];  // bf16 lo QKV
__device__ __nv_bfloat16 g_ctx_h[(size_t)NROWS * INNER];
__device__ __nv_bfloat16 g_ctx_l[(size_t)NROWS * INNER];

// ---------------------------------------------------------------------------
// Helpers
// ---------------------------------------------------------------------------
__device__ __forceinline__ void split1(float v, __nv_bfloat16& h, __nv_bfloat16& l) {
    h = __float2bfloat16(v);
    l = __float2bfloat16(v - __bfloat162float(h));
}

__device__ __forceinline__ float ex2(float x) {
    float y;
    asm("ex2.approx.ftz.f32 %0, %1;" : "=f"(y) : "f"(x));
    return y;
}

__device__ __forceinline__ void ldsm4(uint32_t* r, uint32_t addr) {
    asm volatile("ldmatrix.sync.aligned.m8n8.x4.shared.b16 {%0,%1,%2,%3}, [%4];"
                 : "=r"(r[0]), "=r"(r[1]), "=r"(r[2]), "=r"(r[3]) : "r"(addr));
}

__device__ __forceinline__ void ldsm4t(uint32_t* r, uint32_t addr) {
    asm volatile("ldmatrix.sync.aligned.m8n8.x4.trans.shared.b16 {%0,%1,%2,%3}, [%4];"
                 : "=r"(r[0]), "=r"(r[1]), "=r"(r[2]), "=r"(r[3]) : "r"(addr));
}

__device__ __forceinline__ void mma16816(float* d, const uint32_t* a,
                                         const uint32_t* b) {
    asm volatile(
        "mma.sync.aligned.m16n8k16.row.col.f32.bf16.bf16.f32 "
        "{%0,%1,%2,%3}, {%4,%5,%6,%7}, {%8,%9}, {%0,%1,%2,%3};"
        : "+f"(d[0]), "+f"(d[1]), "+f"(d[2]), "+f"(d[3])
        : "r"(a[0]), "r"(a[1]), "r"(a[2]), "r"(a[3]), "r"(b[0]), "r"(b[1]));
}

__device__ __forceinline__ void cp16(uint32_t dst, const void* src) {
    asm volatile("cp.async.cg.shared.global [%0], [%1], 16;"
                 :: "r"(dst), "l"(__cvta_generic_to_global(src)));
}

__device__ __forceinline__ uint32_t packbf2(float a, float b) {
    __nv_bfloat162 t = __floats2bfloat162_rn(a, b);
    return *(uint32_t*)&t;
}

// ---------------------------------------------------------------------------
// Kernel 1: LayerNorm fused with bf16 hi/lo split output
// ---------------------------------------------------------------------------
__global__ __launch_bounds__(256) void ln_kernel(
    const float* __restrict__ x, const float* __restrict__ gamma,
    const float* __restrict__ beta,
    __nv_bfloat16* __restrict__ xh, __nv_bfloat16* __restrict__ xl)
{
    int row = blockIdx.x;
    int tid = threadIdx.x;
    const float4* xr = (const float4*)(x + (size_t)row * DMODEL);
    float4 v = xr[tid];

    float s  = v.x + v.y + v.z + v.w;
    float ss = v.x*v.x + v.y*v.y + v.z*v.z + v.w*v.w;
    #pragma unroll
    for (int off = 16; off; off >>= 1) {
        s  += __shfl_xor_sync(0xffffffffu, s,  off);
        ss += __shfl_xor_sync(0xffffffffu, ss, off);
    }
    __shared__ float sbuf[8], ssbuf[8];
    int warp = tid >> 5, lane = tid & 31;
    if (lane == 0) { sbuf[warp] = s; ssbuf[warp] = ss; }
    __syncthreads();
    s = 0.f; ss = 0.f;
    #pragma unroll
    for (int w = 0; w < 8; w++) { s += sbuf[w]; ss += ssbuf[w]; }

    float mu  = s * (1.0f / DMODEL);
    float var = ss * (1.0f / DMODEL) - mu * mu;
    float inv = rsqrtf(var + LN_EPS);

    float4 g  = ((const float4*)gamma)[tid];
    float4 be = ((const float4*)beta)[tid];
    float o0 = (v.x - mu) * inv * g.x + be.x;
    float o1 = (v.y - mu) * inv * g.y + be.y;
    float o2 = (v.z - mu) * inv * g.z + be.z;
    float o3 = (v.w - mu) * inv * g.w + be.w;

    __nv_bfloat16 h0,h1,h2,h3,l0,l1,l2,l3;
    split1(o0,h0,l0); split1(o1,h1,l1); split1(o2,h2,l2); split1(o3,h3,l3);
    size_t off = (size_t)row * DMODEL + tid * 4;
    ushort4 hv = { __bfloat16_as_ushort(h0), __bfloat16_as_ushort(h1),
                   __bfloat16_as_ushort(h2), __bfloat16_as_ushort(h3) };
    ushort4 lv = { __bfloat16_as_ushort(l0), __bfloat16_as_ushort(l1),
                   __bfloat16_as_ushort(l2), __bfloat16_as_ushort(l3) };
    *(ushort4*)(xh + off) = hv;
    *(ushort4*)(xl + off) = lv;
}

// ---------------------------------------------------------------------------
// Kernel 2: transpose + bf16 split for weights
// ---------------------------------------------------------------------------
__global__ __launch_bounds__(256) void splitT_kernel(
    const float* __restrict__ W,
    __nv_bfloat16* __restrict__ Th, __nv_bfloat16* __restrict__ Tl,
    int K, int N)
{
    __shared__ float t[32][33];
    int n0 = blockIdx.x * 32, k0 = blockIdx.y * 32;
    int tx = threadIdx.x, ty = threadIdx.y;
    #pragma unroll
    for (int j = 0; j < 4; j++) {
        int r = ty + j * 8;
        t[r][tx] = W[(size_t)(k0 + r) * N + n0 + tx];
    }
    __syncthreads();
    #pragma unroll
    for (int j = 0; j < 4; j++) {
        int r = ty + j * 8;
        float v = t[tx][r];
        __nv_bfloat16 h, l;
        split1(v, h, l);
        size_t o = (size_t)(n0 + r) * K + k0 + tx;
        Th[o] = h; Tl[o] = l;
    }
}

// ---------------------------------------------------------------------------
// Kernel 3: bf16x3-split GEMM on mma.sync.
// 3-stage cp.async pipeline, ONE __syncthreads per k-iteration, 2 CTAs/SM.
// Smem layout: 64-byte rows (32 bf16), XOR chunk swizzle c^=((row>>1)&3).
// ---------------------------------------------------------------------------
#define GK    1024
#define GBK   32
#define GARR  (128 * 64)              // 8192 B per array (128 rows x 64 B)
#define GBLK  (4 * GARR)              // 32768 B per stage {Ah,Al,Bh,Bl}
#define GSMEM (3 * GBLK)              // 98304 B

__global__ __launch_bounds__(256, 2) void mma_gemm(
    const __nv_bfloat16* __restrict__ Ah, const __nv_bfloat16* __restrict__ Al,
    const __nv_bfloat16* __restrict__ Bh, const __nv_bfloat16* __restrict__ Bl,
    float* __restrict__ Cf,
    __nv_bfloat16* __restrict__ Ch, __nv_bfloat16* __restrict__ Cl,
    int N)
{
    extern __shared__ char smg[];
    const uint32_t sb = (uint32_t)__cvta_generic_to_shared(smg);

    const int tid  = threadIdx.x;
    const int lane = tid & 31, wid = tid >> 5;
    const int wm = wid >> 2, wn = wid & 3;
    const int m0 = blockIdx.y * 128, n0 = blockIdx.x * 128;

    const int cr0 = (tid)       >> 2, cc0 = (tid)       & 3;
    const int cr1 = (tid + 256) >> 2, cc1 = (tid + 256) & 3;
    const uint32_t cd0 = (uint32_t)(cr0 * 64 + ((cc0 ^ ((cr0 >> 1) & 3)) << 4));
    const uint32_t cd1 = (uint32_t)(cr1 * 64 + ((cc1 ^ ((cr1 >> 1) & 3)) << 4));

    float acc[4][4][4];
    #pragma unroll
    for (int f = 0; f < 4; f++)
        #pragma unroll
        for (int j = 0; j < 4; j++)
            #pragma unroll
            for (int e = 0; e < 4; e++) acc[f][j][e] = 0.f;

    const int arow = wm * 64 + (lane & 15);
    const uint32_t abase = (uint32_t)(arow * 64);
    const uint32_t axor  = (uint32_t)(((arow >> 1) & 3) << 4);
    const uint32_t achk  = (uint32_t)(lane >> 4);            // + ks*2

    const int brow = wn * 32 + (lane & 7) + ((lane >> 4) << 3);
    const uint32_t bbase = (uint32_t)(brow * 64);
    const uint32_t bxor  = (uint32_t)(((brow >> 1) & 3) << 4);
    const uint32_t bchk  = (uint32_t)((lane >> 3) & 1);      // + ks*2

#define STAGE_COPY(st, kc)                                                      \
    do {                                                                        \
        uint32_t so = sb + (uint32_t)(st) * GBLK;                               \
        size_t ga0 = (size_t)(m0 + cr0) * GK + (kc) + cc0 * 8;                  \
        size_t ga1 = (size_t)(m0 + cr1) * GK + (kc) + cc1 * 8;                  \
        size_t gb0 = (size_t)(n0 + cr0) * GK + (kc) + cc0 * 8;                  \
        size_t gb1 = (size_t)(n0 + cr1) * GK + (kc) + cc1 * 8;                  \
        cp16(so + cd0,            Ah + ga0); cp16(so + cd1,            Ah + ga1); \
        cp16(so + GARR + cd0,     Al + ga0); cp16(so + GARR + cd1,     Al + ga1); \
        cp16(so + 2*GARR + cd0,   Bh + gb0); cp16(so + 2*GARR + cd1,   Bh + gb1); \
        cp16(so + 3*GARR + cd0,   Bl + gb0); cp16(so + 3*GARR + cd1,   Bl + gb1); \
    } while (0)

    STAGE_COPY(0, 0);
    asm volatile("cp.async.commit_group;" ::: "memory");
    STAGE_COPY(1, GBK);
    asm volatile("cp.async.commit_group;" ::: "memory");

    const int nk = GK / GBK;   // 32
    for (int kt = 0; kt < nk; kt++) {
        const int st = kt % 3;
        asm volatile("cp.async.wait_group 1;" ::: "memory");
        __syncthreads();

        if (kt + 2 < nk) { STAGE_COPY((kt + 2) % 3, (kt + 2) * GBK); }
        asm volatile("cp.async.commit_group;" ::: "memory");

        const uint32_t so = sb + (uint32_t)st * GBLK;
        #pragma unroll
        for (int ks = 0; ks < 2; ks++) {
            uint32_t bh[2][4], bl[2][4];
            #pragma unroll
            for (int p = 0; p < 2; p++) {
                uint32_t o = so + 2*GARR + bbase + (uint32_t)(p * 16 * 64)
                           + ((((bchk + ks*2)) << 4) ^ bxor);
                ldsm4(bh[p], o);
                ldsm4(bl[p], o + GARR);
            }
            #pragma unroll
            for (int f = 0; f < 4; f++) {
                uint32_t ah[4], al[4];
                uint32_t o = so + abase + (uint32_t)(f * 16 * 64)
                           + ((((achk + ks*2)) << 4) ^ axor);
                ldsm4(ah, o);
                ldsm4(al, o + GARR);
                #pragma unroll
                for (int j = 0; j < 4; j++) {
                    const int p = j >> 1, sub = (j & 1) * 2;
                    uint32_t bhp[2] = { bh[p][sub], bh[p][sub + 1] };
                    uint32_t blp[2] = { bl[p][sub], bl[p][sub + 1] };
                    mma16816(acc[f][j], ah, bhp);
                    mma16816(acc[f][j], ah, blp);
                    mma16816(acc[f][j], al, bhp);
                }
            }
        }
    }

    const int erow = m0 + wm * 64 + (lane >> 2);
    const int ecol = n0 + wn * 32 + (lane & 3) * 2;
    if (Cf) {
        #pragma unroll
        for (int f = 0; f < 4; f++) {
            #pragma unroll
            for (int j = 0; j < 4; j++) {
                float* d0 = Cf + (size_t)(erow + f * 16)     * N + ecol + j * 8;
                float* d1 = Cf + (size_t)(erow + f * 16 + 8) * N + ecol + j * 8;
                *(float2*)d0 = make_float2(acc[f][j][0], acc[f][j][1]);
                *(float2*)d1 = make_float2(acc[f][j][2], acc[f][j][3]);
            }
        }
    } else {
        #pragma unroll
        for (int f = 0; f < 4; f++) {
            #pragma unroll
            for (int j = 0; j < 4; j++) {
                #pragma unroll
                for (int half = 0; half < 2; half++) {
                    size_t o = (size_t)(erow + f*16 + half*8) * N + ecol + j*8;
                    float v0 = acc[f][j][half*2], v1 = acc[f][j][half*2 + 1];
                    __nv_bfloat16 h0,l0,h1,l1;
                    split1(v0,h0,l0); split1(v1,h1,l1);
                    ushort2 hv = { __bfloat16_as_ushort(h0), __bfloat16_as_ushort(h1) };
                    ushort2 lv = { __bfloat16_as_ushort(l0), __bfloat16_as_ushort(l1) };
                    *(ushort2*)(Ch + o) = hv;
                    *(ushort2*)(Cl + o) = lv;
                }
            }
        }
    }
#undef STAGE_COPY
}

// ---------------------------------------------------------------------------
// Kernel 4: flash attention on mma.sync, bf16x3 split.
// 3-stage KV ring, stage 2 aliases the (dead after kt=0) Q region.
// S accumulators are PRE-LOADED with the mask tile: loads issue before the
// 96 S-MMAs and their latency is fully hidden; S = QK^T + m for free.
// ---------------------------------------------------------------------------
#define AST   72                       // smem row stride (bf16 elems)
#define AKB   (64 * AST * 2)           // 9216 B per K/V array
#define AKVST (4 * AKB)                // 36864 B per KV stage {Kh,Kl,Vh,Vl}
#define AQB   (128 * AST * 2)          // 18432 B per Q array
#define ASMEM (3 * AKVST)              // 110592 B; Q region == stage 2

__global__ __launch_bounds__(256, 2) void attn_mma_kernel(
    const __nv_bfloat16* __restrict__ qh_g, const __nv_bfloat16* __restrict__ ql_g,
    const float* __restrict__ mask,
    __nv_bfloat16* __restrict__ ctxh, __nv_bfloat16* __restrict__ ctxl)
{
    extern __shared__ char sma[];
    const uint32_t sb  = (uint32_t)__cvta_generic_to_shared(sma);
    const uint32_t uQh = sb + 2 * AKVST;      // aliases KV stage 2
    const uint32_t uQl = uQh + AQB;

    const int tid = threadIdx.x, lane = tid & 31, wq = tid >> 5;
    const int qt = blockIdx.x, h = blockIdx.y, b = blockIdx.z;
    const int q0 = qt * 128;
    const size_t rowbase = (size_t)b * NSEQ;
    const size_t qkstride = 3 * INNER;

#define KV_COPY(st, kc)                                                        \
    do {                                                                       \
        uint32_t so = sb + (uint32_t)(st) * AKVST;                             \
        _Pragma("unroll")                                                      \
        for (int t = 0; t < 2; t++) {                                          \
            int idx = tid + t * 256;                                           \
            int r = idx >> 3, c = idx & 7;                                     \
            uint32_t d = (uint32_t)(r * AST + c * 8) * 2;                      \
            size_t gk = (rowbase + (kc) + r) * qkstride + INNER   + h*DH + c*8;\
            size_t gv = (rowbase + (kc) + r) * qkstride + 2*INNER + h*DH + c*8;\
            cp16(so + d,         qh_g + gk);                                   \
            cp16(so + AKB + d,   ql_g + gk);                                   \
            cp16(so + 2*AKB + d, qh_g + gv);                                   \
            cp16(so + 3*AKB + d, ql_g + gv);                                   \
        }                                                                      \
    } while (0)

    // prologue: group0 = Q + KV stage0; group1 = KV stage1
    {
        #pragma unroll
        for (int t = 0; t < 4; t++) {
            int idx = tid + t * 256;
            int r = idx >> 3, c = idx & 7;
            uint32_t d = (uint32_t)(r * AST + c * 8) * 2;
            size_t g = (rowbase + q0 + r) * qkstride + h * DH + c * 8;
            cp16(uQh + d, qh_g + g);
            cp16(uQl + d, ql_g + g);
        }
    }
    KV_COPY(0, 0);
    asm volatile("cp.async.commit_group;" ::: "memory");
    KV_COPY(1, 64);
    asm volatile("cp.async.commit_group;" ::: "memory");

    uint32_t qfh[4][4], qfl[4][4];
    float oacc[8][4];
    #pragma unroll
    for (int j = 0; j < 8; j++)
        #pragma unroll
        for (int e = 0; e < 4; e++) oacc[j][e] = 0.f;
    float rmax0 = -1e30f, rmax1 = -1e30f, rsum0 = 0.f, rsum1 = 0.f;

    const uint32_t qoffb = (uint32_t)((wq*16 + (lane & 15)) * AST
                           + (lane >> 4) * 8) * 2;
    const uint32_t koffb = (uint32_t)(((lane & 7) + ((lane >> 4) << 3)) * AST
                           + ((lane >> 3) & 1) * 8) * 2;
    const uint32_t voffb = (uint32_t)(((lane & 15)) * AST + (lane >> 4) * 8) * 2;

    const int mrow = q0 + wq * 16 + (lane >> 2);
    const float* mrow_p = mask + ((size_t)b * NSEQ + mrow) * NSEQ + (lane & 3) * 2;

    const int nk = NSEQ / 64;   // 32
    for (int kt = 0; kt < nk; kt++) {
        const int st = kt % 3;
        asm volatile("cp.async.wait_group 1;" ::: "memory");
        __syncthreads();

        if (kt == 0) {
            // extract Q fragments; barrier before stage-2 copy overwrites Q
            #pragma unroll
            for (int kk = 0; kk < 4; kk++) {
                ldsm4(qfh[kk], uQh + qoffb + (uint32_t)(kk * 16) * 2);
                ldsm4(qfl[kk], uQl + qoffb + (uint32_t)(kk * 16) * 2);
            }
            __syncthreads();
        }

        if (kt + 2 < nk) { KV_COPY((kt + 2) % 3, (kt + 2) * 64); }
        asm volatile("cp.async.commit_group;" ::: "memory");

        const uint32_t so = sb + (uint32_t)st * AKVST;   // Kh base
        const uint32_t sV = so + 2 * AKB;

        // ---- S accumulators pre-loaded with mask (loads hidden under MMAs)
        float sacc[8][4];
        {
            const float* mg = mrow_p + kt * 64;
            #pragma unroll
            for (int j = 0; j < 8; j++) {
                float2 m0 = *(const float2*)(mg + j * 8);
                float2 m1 = *(const float2*)(mg + 8 * NSEQ + j * 8);
                sacc[j][0] = m0.x; sacc[j][1] = m0.y;
                sacc[j][2] = m1.x; sacc[j][3] = m1.y;
            }
        }

        // ---- S = QK^T + m (3-term)
        #pragma unroll
        for (int kk = 0; kk < 4; kk++) {
            #pragma unroll
            for (int jb = 0; jb < 4; jb++) {
                uint32_t kbh[4], kbl[4];
                uint32_t o = so + koffb + (uint32_t)(jb * 16 * AST + kk * 16) * 2;
                ldsm4(kbh, o);
                ldsm4(kbl, o + AKB);
                #pragma unroll
                for (int sub = 0; sub < 2; sub++) {
                    int j = jb * 2 + sub;
                    uint32_t bh[2] = { kbh[sub*2], kbh[sub*2+1] };
                    uint32_t bl[2] = { kbl[sub*2], kbl[sub*2+1] };
                    mma16816(sacc[j], qfh[kk], bh);
                    mma16816(sacc[j], qfh[kk], bl);
                    mma16816(sacc[j], qfl[kk], bh);
                }
            }
        }

        // ---- scale into exp2 domain
        #pragma unroll
        for (int j = 0; j < 8; j++) {
            sacc[j][0] *= SC2; sacc[j][1] *= SC2;
            sacc[j][2] *= SC2; sacc[j][3] *= SC2;
        }

        // ---- online softmax (exp2 domain, MUFU.EX2)
        float tm0 = -1e30f, tm1 = -1e30f;
        #pragma unroll
        for (int j = 0; j < 8; j++) {
            tm0 = fmaxf(tm0, fmaxf(sacc[j][0], sacc[j][1]));
            tm1 = fmaxf(tm1, fmaxf(sacc[j][2], sacc[j][3]));
        }
        #pragma unroll
        for (int off = 1; off <= 2; off <<= 1) {
            tm0 = fmaxf(tm0, __shfl_xor_sync(0xffffffffu, tm0, off));
            tm1 = fmaxf(tm1, __shfl_xor_sync(0xffffffffu, tm1, off));
        }
        float nm0 = fmaxf(rmax0, tm0), nm1 = fmaxf(rmax1, tm1);
        float corr0 = ex2(rmax0 - nm0), corr1 = ex2(rmax1 - nm1);
        rmax0 = nm0; rmax1 = nm1;

        float ps0 = 0.f, ps1 = 0.f;
        #pragma unroll
        for (int j = 0; j < 8; j++) {
            sacc[j][0] = ex2(sacc[j][0] - nm0);
            sacc[j][1] = ex2(sacc[j][1] - nm0);
            sacc[j][2] = ex2(sacc[j][2] - nm1);
            sacc[j][3] = ex2(sacc[j][3] - nm1);
            ps0 += sacc[j][0] + sacc[j][1];
            ps1 += sacc[j][2] + sacc[j][3];
        }
        #pragma unroll
        for (int off = 1; off <= 2; off <<= 1) {
            ps0 += __shfl_xor_sync(0xffffffffu, ps0, off);
            ps1 += __shfl_xor_sync(0xffffffffu, ps1, off);
        }
        rsum0 = rsum0 * corr0 + ps0;
        rsum1 = rsum1 * corr1 + ps1;

        #pragma unroll
        for (int j = 0; j < 8; j++) {
            oacc[j][0] *= corr0; oacc[j][1] *= corr0;
            oacc[j][2] *= corr1; oacc[j][3] *= corr1;
        }

        // ---- O += P V (3-term); pack P per-kp to bound register pressure
        #pragma unroll
        for (int kp = 0; kp < 4; kp++) {
            uint32_t pah[4], pal[4];
            {
                const int j0 = kp * 2, j1 = kp * 2 + 1;
                float p00 = sacc[j0][0], p01 = sacc[j0][1];
                float p02 = sacc[j0][2], p03 = sacc[j0][3];
                float p10 = sacc[j1][0], p11 = sacc[j1][1];
                float p12 = sacc[j1][2], p13 = sacc[j1][3];
                pah[0] = packbf2(p00, p01);
                pah[1] = packbf2(p02, p03);
                pah[2] = packbf2(p10, p11);
                pah[3] = packbf2(p12, p13);
                __nv_bfloat162* hp;
                hp = (__nv_bfloat162*)&pah[0];
                pal[0] = packbf2(p00 - __bfloat162float(hp->x), p01 - __bfloat162float(hp->y));
                hp = (__nv_bfloat162*)&pah[1];
                pal[1] = packbf2(p02 - __bfloat162float(hp->x), p03 - __bfloat162float(hp->y));
                hp = (__nv_bfloat162*)&pah[2];
                pal[2] = packbf2(p10 - __bfloat162float(hp->x), p11 - __bfloat162float(hp->y));
                hp = (__nv_bfloat162*)&pah[3];
                pal[3] = packbf2(p12 - __bfloat162float(hp->x), p13 - __bfloat162float(hp->y));
            }
            #pragma unroll
            for (int db = 0; db < 4; db++) {
                uint32_t vbh[4], vbl[4];
                uint32_t o = sV + voffb + (uint32_t)(kp * 16 * AST + db * 16) * 2;
                ldsm4t(vbh, o);
                ldsm4t(vbl, o + AKB);
                #pragma unroll
                for (int sub = 0; sub < 2; sub++) {
                    int j = db * 2 + sub;
                    uint32_t bh[2] = { vbh[sub*2], vbh[sub*2+1] };
                    uint32_t bl[2] = { vbl[sub*2], vbl[sub*2+1] };
                    mma16816(oacc[j], pah, bh);
                    mma16816(oacc[j], pah, bl);
                    mma16816(oacc[j], pal, bh);
                }
            }
        }
    }
#undef KV_COPY

    // ---- normalize + write ctx (bf16 hi/lo)
    const float inv0 = 1.0f / rsum0, inv1 = 1.0f / rsum1;
    const int row0 = q0 + wq * 16 + (lane >> 2);
    #pragma unroll
    for (int j = 0; j < 8; j++) {
        const int col = h * DH + j * 8 + (lane & 3) * 2;
        float v0 = oacc[j][0] * inv0, v1 = oacc[j][1] * inv0;
        float v2 = oacc[j][2] * inv1, v3 = oacc[j][3] * inv1;
        __nv_bfloat16 h0,l0,h1,l1,h2,l2,h3,l3;
        split1(v0,h0,l0); split1(v1,h1,l1); split1(v2,h2,l2); split1(v3,h3,l3);
        size_t o0 = (rowbase + row0)     * (size_t)INNER + col;
        size_t o1 = (rowbase + row0 + 8) * (size_t)INNER + col;
        ushort2 a0 = { __bfloat16_as_ushort(h0), __bfloat16_as_ushort(h1) };
        ushort2 b0 = { __bfloat16_as_ushort(l0), __bfloat16_as_ushort(l1) };
        ushort2 a1 = { __bfloat16_as_ushort(h2), __bfloat16_as_ushort(h3) };
        ushort2 b1 = { __bfloat16_as_ushort(l2), __bfloat16_as_ushort(l3) };
        *(ushort2*)(ctxh + o0) = a0;
        *(ushort2*)(ctxl + o0) = b0;
        *(ushort2*)(ctxh + o1) = a1;
        *(ushort2*)(ctxl + o1) = b1;
    }
}

// ---------------------------------------------------------------------------
// launch
// ---------------------------------------------------------------------------
extern "C" void kernel_launch(void* const* d_in, const int* in_sizes, int n_in,
                              void* d_out, int out_size)
{
    const float* x     = (const float*)d_in[0];
    const float* m     = (const float*)d_in[1];
    const float* gamma = (const float*)d_in[2];
    const float* beta  = (const float*)d_in[3];
    const float* Wqkv  = (const float*)d_in[4];
    const float* Wout  = (const float*)d_in[5];
    float* out = (float*)d_out;

    __nv_bfloat16 *xnh, *xnl, *wqh, *wql, *woh, *wol, *qkvh, *qkvl, *ctxh, *ctxl;
    cudaGetSymbolAddress((void**)&xnh,  g_xn_h);
    cudaGetSymbolAddress((void**)&xnl,  g_xn_l);
    cudaGetSymbolAddress((void**)&wqh,  g_wq_h);
    cudaGetSymbolAddress((void**)&wql,  g_wq_l);
    cudaGetSymbolAddress((void**)&woh,  g_wo_h);
    cudaGetSymbolAddress((void**)&wol,  g_wo_l);
    cudaGetSymbolAddress((void**)&qkvh, g_qkv_h);
    cudaGetSymbolAddress((void**)&qkvl, g_qkv_l);
    cudaGetSymbolAddress((void**)&ctxh, g_ctx_h);
    cudaGetSymbolAddress((void**)&ctxl, g_ctx_l);

    cudaFuncSetAttribute(mma_gemm,
                         cudaFuncAttributeMaxDynamicSharedMemorySize, GSMEM);
    cudaFuncSetAttribute(attn_mma_kernel,
                         cudaFuncAttributeMaxDynamicSharedMemorySize, ASMEM);

    // 1. LayerNorm (+ bf16 split)
    ln_kernel<<<NROWS, 256>>>(x, gamma, beta, xnh, xnl);

    // 2. weight transpose + split
    splitT_kernel<<<dim3(3*INNER/32, DMODEL/32), dim3(32,8)>>>(Wqkv, wqh, wql, DMODEL, 3*INNER);
    splitT_kernel<<<dim3(DMODEL/32,  INNER/32),  dim3(32,8)>>>(Wout, woh, wol, INNER, DMODEL);

    // 3. QKV projection -> bf16 hi/lo qkv
    mma_gemm<<<dim3(3*INNER/128, NROWS/128), 256, GSMEM>>>(
        xnh, xnl, wqh, wql, nullptr, qkvh, qkvl, 3*INNER);

    // 4. masked flash attention on tensor cores
    attn_mma_kernel<<<dim3(NSEQ/128, HEADS, BATCH), 256, ASMEM>>>(
        qkvh, qkvl, m, ctxh, ctxl);

    // 5. output projection -> fp32 out
    mma_gemm<<<dim3(DMODEL/128, NROWS/128), 256, GSMEM>>>(
        ctxh, ctxl, woh, wol, out, nullptr, nullptr, DMODEL);
}

// round 12
// speedup vs baseline: 1.0342x; 1.0342x over previous
#include <cuda_runtime.h>
#include <cuda_bf16.h>
#include <math.h>
#include <stdint.h>

// ---------------------------------------------------------------------------
// Problem constants
// ---------------------------------------------------------------------------
#define BATCH   2
#define NSEQ    2048
#define DMODEL  1024
#define HEADS   16
#define DH      64
#define INNER   1024
#define NROWS   (BATCH*NSEQ)   // 4096
#define SCALE   0.125f
#define SC2     (0.125f * 1.4426950408889634f)   // SCALE * log2(e)
#define LN_EPS  1e-5f

// ---------------------------------------------------------------------------
// Scratch (__device__ globals; no allocs allowed)
// ---------------------------------------------------------------------------
__device__ __nv_bfloat16 g_xn_h [(size_t)NROWS * DMODEL];
__device__ __nv_bfloat16 g_xn_l [(size_t)NROWS * DMODEL];
__device__ __nv_bfloat16 g_wq_h [(size_t)3*INNER * DMODEL];   // Wqkv^T [3072][1024]
__device__ __nv_bfloat16 g_wq_l [(size_t)3*INNER * DMODEL];
__device__ __nv_bfloat16 g_wo_h [(size_t)DMODEL * INNER];     // Wout^T
__device__ __nv_bfloat16 g_wo_l [(size_t)DMODEL * INNER];
__device__ __nv_bfloat16 g_qkv_h[(size_t)NROWS * 3 * INNER];  // bf16 hi QKV
__device__ __nv_bfloat16 g_qkv_l[(size_t)NROWS * 3 * INNER];  // bf16 lo QKV
__device__ __nv_bfloat16 g_ctx_h[(size_t)NROWS * INNER];
__device__ __nv_bfloat16 g_ctx_l[(size_t)NROWS * INNER];

// ---------------------------------------------------------------------------
// Helpers
// ---------------------------------------------------------------------------
__device__ __forceinline__ void split1(float v, __nv_bfloat16& h, __nv_bfloat16& l) {
    h = __float2bfloat16(v);
    l = __float2bfloat16(v - __bfloat162float(h));
}

__device__ __forceinline__ float ex2(float x) {
    float y;
    asm("ex2.approx.ftz.f32 %0, %1;" : "=f"(y) : "f"(x));
    return y;
}

__device__ __forceinline__ void ldsm4(uint32_t* r, uint32_t addr) {
    asm volatile("ldmatrix.sync.aligned.m8n8.x4.shared.b16 {%0,%1,%2,%3}, [%4];"
                 : "=r"(r[0]), "=r"(r[1]), "=r"(r[2]), "=r"(r[3]) : "r"(addr));
}

__device__ __forceinline__ void ldsm4t(uint32_t* r, uint32_t addr) {
    asm volatile("ldmatrix.sync.aligned.m8n8.x4.trans.shared.b16 {%0,%1,%2,%3}, [%4];"
                 : "=r"(r[0]), "=r"(r[1]), "=r"(r[2]), "=r"(r[3]) : "r"(addr));
}

__device__ __forceinline__ void mma16816(float* d, const uint32_t* a,
                                         const uint32_t* b) {
    asm volatile(
        "mma.sync.aligned.m16n8k16.row.col.f32.bf16.bf16.f32 "
        "{%0,%1,%2,%3}, {%4,%5,%6,%7}, {%8,%9}, {%0,%1,%2,%3};"
        : "+f"(d[0]), "+f"(d[1]), "+f"(d[2]), "+f"(d[3])
        : "r"(a[0]), "r"(a[1]), "r"(a[2]), "r"(a[3]), "r"(b[0]), "r"(b[1]));
}

__device__ __forceinline__ void cp16(uint32_t dst, const void* src) {
    asm volatile("cp.async.cg.shared.global [%0], [%1], 16;"
                 :: "r"(dst), "l"(__cvta_generic_to_global(src)));
}

__device__ __forceinline__ uint32_t packbf2(float a, float b) {
    __nv_bfloat162 t = __floats2bfloat162_rn(a, b);
    return *(uint32_t*)&t;
}

// ---------------------------------------------------------------------------
// Kernel 1: LayerNorm fused with bf16 hi/lo split output
// ---------------------------------------------------------------------------
__global__ __launch_bounds__(256) void ln_kernel(
    const float* __restrict__ x, const float* __restrict__ gamma,
    const float* __restrict__ beta,
    __nv_bfloat16* __restrict__ xh, __nv_bfloat16* __restrict__ xl)
{
    int row = blockIdx.x;
    int tid = threadIdx.x;
    const float4* xr = (const float4*)(x + (size_t)row * DMODEL);
    float4 v = xr[tid];

    float s  = v.x + v.y + v.z + v.w;
    float ss = v.x*v.x + v.y*v.y + v.z*v.z + v.w*v.w;
    #pragma unroll
    for (int off = 16; off; off >>= 1) {
        s  += __shfl_xor_sync(0xffffffffu, s,  off);
        ss += __shfl_xor_sync(0xffffffffu, ss, off);
    }
    __shared__ float sbuf[8], ssbuf[8];
    int warp = tid >> 5, lane = tid & 31;
    if (lane == 0) { sbuf[warp] = s; ssbuf[warp] = ss; }
    __syncthreads();
    s = 0.f; ss = 0.f;
    #pragma unroll
    for (int w = 0; w < 8; w++) { s += sbuf[w]; ss += ssbuf[w]; }

    float mu  = s * (1.0f / DMODEL);
    float var = ss * (1.0f / DMODEL) - mu * mu;
    float inv = rsqrtf(var + LN_EPS);

    float4 g  = ((const float4*)gamma)[tid];
    float4 be = ((const float4*)beta)[tid];
    float o0 = (v.x - mu) * inv * g.x + be.x;
    float o1 = (v.y - mu) * inv * g.y + be.y;
    float o2 = (v.z - mu) * inv * g.z + be.z;
    float o3 = (v.w - mu) * inv * g.w + be.w;

    __nv_bfloat16 h0,h1,h2,h3,l0,l1,l2,l3;
    split1(o0,h0,l0); split1(o1,h1,l1); split1(o2,h2,l2); split1(o3,h3,l3);
    size_t off = (size_t)row * DMODEL + tid * 4;
    ushort4 hv = { __bfloat16_as_ushort(h0), __bfloat16_as_ushort(h1),
                   __bfloat16_as_ushort(h2), __bfloat16_as_ushort(h3) };
    ushort4 lv = { __bfloat16_as_ushort(l0), __bfloat16_as_ushort(l1),
                   __bfloat16_as_ushort(l2), __bfloat16_as_ushort(l3) };
    *(ushort4*)(xh + off) = hv;
    *(ushort4*)(xl + off) = lv;
}

// ---------------------------------------------------------------------------
// Kernel 2: transpose + bf16 split for weights
// ---------------------------------------------------------------------------
__global__ __launch_bounds__(256) void splitT_kernel(
    const float* __restrict__ W,
    __nv_bfloat16* __restrict__ Th, __nv_bfloat16* __restrict__ Tl,
    int K, int N)
{
    __shared__ float t[32][33];
    int n0 = blockIdx.x * 32, k0 = blockIdx.y * 32;
    int tx = threadIdx.x, ty = threadIdx.y;
    #pragma unroll
    for (int j = 0; j < 4; j++) {
        int r = ty + j * 8;
        t[r][tx] = W[(size_t)(k0 + r) * N + n0 + tx];
    }
    __syncthreads();
    #pragma unroll
    for (int j = 0; j < 4; j++) {
        int r = ty + j * 8;
        float v = t[tx][r];
        __nv_bfloat16 h, l;
        split1(v, h, l);
        size_t o = (size_t)(n0 + r) * K + k0 + tx;
        Th[o] = h; Tl[o] = l;
    }
}

// ---------------------------------------------------------------------------
// Kernel 3: bf16x3-split GEMM on mma.sync.
// 3-stage cp.async pipeline, ONE __syncthreads per k-iteration, 2 CTAs/SM.
// MMA issue is TERM-OUTER: each split term sweeps all 4 j-accumulators
// before the next term touches them again (RAW distance 4, not 1).
// ---------------------------------------------------------------------------
#define GK    1024
#define GBK   32
#define GARR  (128 * 64)              // 8192 B per array (128 rows x 64 B)
#define GBLK  (4 * GARR)              // 32768 B per stage {Ah,Al,Bh,Bl}
#define GSMEM (3 * GBLK)              // 98304 B

__global__ __launch_bounds__(256, 2) void mma_gemm(
    const __nv_bfloat16* __restrict__ Ah, const __nv_bfloat16* __restrict__ Al,
    const __nv_bfloat16* __restrict__ Bh, const __nv_bfloat16* __restrict__ Bl,
    float* __restrict__ Cf,
    __nv_bfloat16* __restrict__ Ch, __nv_bfloat16* __restrict__ Cl,
    int N)
{
    extern __shared__ char smg[];
    const uint32_t sb = (uint32_t)__cvta_generic_to_shared(smg);

    const int tid  = threadIdx.x;
    const int lane = tid & 31, wid = tid >> 5;
    const int wm = wid >> 2, wn = wid & 3;
    const int m0 = blockIdx.y * 128, n0 = blockIdx.x * 128;

    const int cr0 = (tid)       >> 2, cc0 = (tid)       & 3;
    const int cr1 = (tid + 256) >> 2, cc1 = (tid + 256) & 3;
    const uint32_t cd0 = (uint32_t)(cr0 * 64 + ((cc0 ^ ((cr0 >> 1) & 3)) << 4));
    const uint32_t cd1 = (uint32_t)(cr1 * 64 + ((cc1 ^ ((cr1 >> 1) & 3)) << 4));

    float acc[4][4][4];
    #pragma unroll
    for (int f = 0; f < 4; f++)
        #pragma unroll
        for (int j = 0; j < 4; j++)
            #pragma unroll
            for (int e = 0; e < 4; e++) acc[f][j][e] = 0.f;

    const int arow = wm * 64 + (lane & 15);
    const uint32_t abase = (uint32_t)(arow * 64);
    const uint32_t axor  = (uint32_t)(((arow >> 1) & 3) << 4);
    const uint32_t achk  = (uint32_t)(lane >> 4);            // + ks*2

    const int brow = wn * 32 + (lane & 7) + ((lane >> 4) << 3);
    const uint32_t bbase = (uint32_t)(brow * 64);
    const uint32_t bxor  = (uint32_t)(((brow >> 1) & 3) << 4);
    const uint32_t bchk  = (uint32_t)((lane >> 3) & 1);      // + ks*2

#define STAGE_COPY(st, kc)                                                      \
    do {                                                                        \
        uint32_t so = sb + (uint32_t)(st) * GBLK;                               \
        size_t ga0 = (size_t)(m0 + cr0) * GK + (kc) + cc0 * 8;                  \
        size_t ga1 = (size_t)(m0 + cr1) * GK + (kc) + cc1 * 8;                  \
        size_t gb0 = (size_t)(n0 + cr0) * GK + (kc) + cc0 * 8;                  \
        size_t gb1 = (size_t)(n0 + cr1) * GK + (kc) + cc1 * 8;                  \
        cp16(so + cd0,            Ah + ga0); cp16(so + cd1,            Ah + ga1); \
        cp16(so + GARR + cd0,     Al + ga0); cp16(so + GARR + cd1,     Al + ga1); \
        cp16(so + 2*GARR + cd0,   Bh + gb0); cp16(so + 2*GARR + cd1,   Bh + gb1); \
        cp16(so + 3*GARR + cd0,   Bl + gb0); cp16(so + 3*GARR + cd1,   Bl + gb1); \
    } while (0)

    STAGE_COPY(0, 0);
    asm volatile("cp.async.commit_group;" ::: "memory");
    STAGE_COPY(1, GBK);
    asm volatile("cp.async.commit_group;" ::: "memory");

    const int nk = GK / GBK;   // 32
    for (int kt = 0; kt < nk; kt++) {
        const int st = kt % 3;
        asm volatile("cp.async.wait_group 1;" ::: "memory");
        __syncthreads();

        if (kt + 2 < nk) { STAGE_COPY((kt + 2) % 3, (kt + 2) * GBK); }
        asm volatile("cp.async.commit_group;" ::: "memory");

        const uint32_t so = sb + (uint32_t)st * GBLK;
        #pragma unroll
        for (int ks = 0; ks < 2; ks++) {
            uint32_t bh[2][4], bl[2][4];
            #pragma unroll
            for (int p = 0; p < 2; p++) {
                uint32_t o = so + 2*GARR + bbase + (uint32_t)(p * 16 * 64)
                           + ((((bchk + ks*2)) << 4) ^ bxor);
                ldsm4(bh[p], o);
                ldsm4(bl[p], o + GARR);
            }
            #pragma unroll
            for (int f = 0; f < 4; f++) {
                uint32_t ah[4], al[4];
                uint32_t o = so + abase + (uint32_t)(f * 16 * 64)
                           + ((((achk + ks*2)) << 4) ^ axor);
                ldsm4(ah, o);
                ldsm4(al, o + GARR);
                // term-outer issue: RAW distance 4 on each accumulator
                #pragma unroll
                for (int j = 0; j < 4; j++) {
                    uint32_t bp[2] = { bh[j >> 1][(j & 1) * 2],
                                       bh[j >> 1][(j & 1) * 2 + 1] };
                    mma16816(acc[f][j], ah, bp);
                }
                #pragma unroll
                for (int j = 0; j < 4; j++) {
                    uint32_t bp[2] = { bl[j >> 1][(j & 1) * 2],
                                       bl[j >> 1][(j & 1) * 2 + 1] };
                    mma16816(acc[f][j], ah, bp);
                }
                #pragma unroll
                for (int j = 0; j < 4; j++) {
                    uint32_t bp[2] = { bh[j >> 1][(j & 1) * 2],
                                       bh[j >> 1][(j & 1) * 2 + 1] };
                    mma16816(acc[f][j], al, bp);
                }
            }
        }
    }

    const int erow = m0 + wm * 64 + (lane >> 2);
    const int ecol = n0 + wn * 32 + (lane & 3) * 2;
    if (Cf) {
        #pragma unroll
        for (int f = 0; f < 4; f++) {
            #pragma unroll
            for (int j = 0; j < 4; j++) {
                float* d0 = Cf + (size_t)(erow + f * 16)     * N + ecol + j * 8;
                float* d1 = Cf + (size_t)(erow + f * 16 + 8) * N + ecol + j * 8;
                *(float2*)d0 = make_float2(acc[f][j][0], acc[f][j][1]);
                *(float2*)d1 = make_float2(acc[f][j][2], acc[f][j][3]);
            }
        }
    } else {
        #pragma unroll
        for (int f = 0; f < 4; f++) {
            #pragma unroll
            for (int j = 0; j < 4; j++) {
                #pragma unroll
                for (int half = 0; half < 2; half++) {
                    size_t o = (size_t)(erow + f*16 + half*8) * N + ecol + j*8;
                    float v0 = acc[f][j][half*2], v1 = acc[f][j][half*2 + 1];
                    __nv_bfloat16 h0,l0,h1,l1;
                    split1(v0,h0,l0); split1(v1,h1,l1);
                    ushort2 hv = { __bfloat16_as_ushort(h0), __bfloat16_as_ushort(h1) };
                    ushort2 lv = { __bfloat16_as_ushort(l0), __bfloat16_as_ushort(l1) };
                    *(ushort2*)(Ch + o) = hv;
                    *(ushort2*)(Cl + o) = lv;
                }
            }
        }
    }
#undef STAGE_COPY
}

// ---------------------------------------------------------------------------
// Kernel 4: flash attention on mma.sync, bf16x3 split.
// 3-stage KV ring, stage 2 aliases the (dead after kt=0) Q region.
// Mask added AFTER the S MMAs (R10 behavior). MMA issue term-outer per
// fragment pair (RAW distance 2 instead of 1).
// ---------------------------------------------------------------------------
#define AST   72                       // smem row stride (bf16 elems)
#define AKB   (64 * AST * 2)           // 9216 B per K/V array
#define AKVST (4 * AKB)                // 36864 B per KV stage {Kh,Kl,Vh,Vl}
#define AQB   (128 * AST * 2)          // 18432 B per Q array
#define ASMEM (3 * AKVST)              // 110592 B; Q region == stage 2

__global__ __launch_bounds__(256, 2) void attn_mma_kernel(
    const __nv_bfloat16* __restrict__ qh_g, const __nv_bfloat16* __restrict__ ql_g,
    const float* __restrict__ mask,
    __nv_bfloat16* __restrict__ ctxh, __nv_bfloat16* __restrict__ ctxl)
{
    extern __shared__ char sma[];
    const uint32_t sb  = (uint32_t)__cvta_generic_to_shared(sma);
    const uint32_t uQh = sb + 2 * AKVST;      // aliases KV stage 2
    const uint32_t uQl = uQh + AQB;

    const int tid = threadIdx.x, lane = tid & 31, wq = tid >> 5;
    const int qt = blockIdx.x, h = blockIdx.y, b = blockIdx.z;
    const int q0 = qt * 128;
    const size_t rowbase = (size_t)b * NSEQ;
    const size_t qkstride = 3 * INNER;

#define KV_COPY(st, kc)                                                        \
    do {                                                                       \
        uint32_t so = sb + (uint32_t)(st) * AKVST;                             \
        _Pragma("unroll")                                                      \
        for (int t = 0; t < 2; t++) {                                          \
            int idx = tid + t * 256;                                           \
            int r = idx >> 3, c = idx & 7;                                     \
            uint32_t d = (uint32_t)(r * AST + c * 8) * 2;                      \
            size_t gk = (rowbase + (kc) + r) * qkstride + INNER   + h*DH + c*8;\
            size_t gv = (rowbase + (kc) + r) * qkstride + 2*INNER + h*DH + c*8;\
            cp16(so + d,         qh_g + gk);                                   \
            cp16(so + AKB + d,   ql_g + gk);                                   \
            cp16(so + 2*AKB + d, qh_g + gv);                                   \
            cp16(so + 3*AKB + d, ql_g + gv);                                   \
        }                                                                      \
    } while (0)

    // prologue: group0 = Q + KV stage0; group1 = KV stage1
    {
        #pragma unroll
        for (int t = 0; t < 4; t++) {
            int idx = tid + t * 256;
            int r = idx >> 3, c = idx & 7;
            uint32_t d = (uint32_t)(r * AST + c * 8) * 2;
            size_t g = (rowbase + q0 + r) * qkstride + h * DH + c * 8;
            cp16(uQh + d, qh_g + g);
            cp16(uQl + d, ql_g + g);
        }
    }
    KV_COPY(0, 0);
    asm volatile("cp.async.commit_group;" ::: "memory");
    KV_COPY(1, 64);
    asm volatile("cp.async.commit_group;" ::: "memory");

    uint32_t qfh[4][4], qfl[4][4];
    float oacc[8][4];
    #pragma unroll
    for (int j = 0; j < 8; j++)
        #pragma unroll
        for (int e = 0; e < 4; e++) oacc[j][e] = 0.f;
    float rmax0 = -1e30f, rmax1 = -1e30f, rsum0 = 0.f, rsum1 = 0.f;

    const uint32_t qoffb = (uint32_t)((wq*16 + (lane & 15)) * AST
                           + (lane >> 4) * 8) * 2;
    const uint32_t koffb = (uint32_t)(((lane & 7) + ((lane >> 4) << 3)) * AST
                           + ((lane >> 3) & 1) * 8) * 2;
    const uint32_t voffb = (uint32_t)(((lane & 15)) * AST + (lane >> 4) * 8) * 2;

    const int nk = NSEQ / 64;   // 32
    for (int kt = 0; kt < nk; kt++) {
        const int st = kt % 3;
        asm volatile("cp.async.wait_group 1;" ::: "memory");
        __syncthreads();

        if (kt == 0) {
            // extract Q fragments; barrier before stage-2 copy overwrites Q
            #pragma unroll
            for (int kk = 0; kk < 4; kk++) {
                ldsm4(qfh[kk], uQh + qoffb + (uint32_t)(kk * 16) * 2);
                ldsm4(qfl[kk], uQl + qoffb + (uint32_t)(kk * 16) * 2);
            }
            __syncthreads();
        }

        if (kt + 2 < nk) { KV_COPY((kt + 2) % 3, (kt + 2) * 64); }
        asm volatile("cp.async.commit_group;" ::: "memory");

        const uint32_t so = sb + (uint32_t)st * AKVST;   // Kh base
        const uint32_t sV = so + 2 * AKB;

        // ---- S = Q K^T (3-term), term-outer per jb (RAW distance 2)
        float sacc[8][4];
        #pragma unroll
        for (int j = 0; j < 8; j++)
            #pragma unroll
            for (int e = 0; e < 4; e++) sacc[j][e] = 0.f;

        #pragma unroll
        for (int kk = 0; kk < 4; kk++) {
            #pragma unroll
            for (int jb = 0; jb < 4; jb++) {
                uint32_t kbh[4], kbl[4];
                uint32_t o = so + koffb + (uint32_t)(jb * 16 * AST + kk * 16) * 2;
                ldsm4(kbh, o);
                ldsm4(kbl, o + AKB);
                const int j0 = jb * 2, j1 = jb * 2 + 1;
                uint32_t bh0[2] = { kbh[0], kbh[1] }, bh1[2] = { kbh[2], kbh[3] };
                uint32_t bl0[2] = { kbl[0], kbl[1] }, bl1[2] = { kbl[2], kbl[3] };
                mma16816(sacc[j0], qfh[kk], bh0);
                mma16816(sacc[j1], qfh[kk], bh1);
                mma16816(sacc[j0], qfh[kk], bl0);
                mma16816(sacc[j1], qfh[kk], bl1);
                mma16816(sacc[j0], qfl[kk], bh0);
                mma16816(sacc[j1], qfl[kk], bh1);
            }
        }

        // ---- mask add (before scale), scale into exp2 domain
        {
            const int qrow = q0 + wq * 16 + (lane >> 2);
            const int kcol = kt * 64 + (lane & 3) * 2;
            const float* mg = mask + ((size_t)b * NSEQ + qrow) * NSEQ + kcol;
            #pragma unroll
            for (int j = 0; j < 8; j++) {
                float2 m0 = *(const float2*)(mg + j * 8);
                float2 m1 = *(const float2*)(mg + 8 * NSEQ + j * 8);
                sacc[j][0] = (sacc[j][0] + m0.x) * SC2;
                sacc[j][1] = (sacc[j][1] + m0.y) * SC2;
                sacc[j][2] = (sacc[j][2] + m1.x) * SC2;
                sacc[j][3] = (sacc[j][3] + m1.y) * SC2;
            }
        }

        // ---- online softmax (exp2 domain, MUFU.EX2)
        float tm0 = -1e30f, tm1 = -1e30f;
        #pragma unroll
        for (int j = 0; j < 8; j++) {
            tm0 = fmaxf(tm0, fmaxf(sacc[j][0], sacc[j][1]));
            tm1 = fmaxf(tm1, fmaxf(sacc[j][2], sacc[j][3]));
        }
        #pragma unroll
        for (int off = 1; off <= 2; off <<= 1) {
            tm0 = fmaxf(tm0, __shfl_xor_sync(0xffffffffu, tm0, off));
            tm1 = fmaxf(tm1, __shfl_xor_sync(0xffffffffu, tm1, off));
        }
        float nm0 = fmaxf(rmax0, tm0), nm1 = fmaxf(rmax1, tm1);
        float corr0 = ex2(rmax0 - nm0), corr1 = ex2(rmax1 - nm1);
        rmax0 = nm0; rmax1 = nm1;

        float ps0 = 0.f, ps1 = 0.f;
        #pragma unroll
        for (int j = 0; j < 8; j++) {
            sacc[j][0] = ex2(sacc[j][0] - nm0);
            sacc[j][1] = ex2(sacc[j][1] - nm0);
            sacc[j][2] = ex2(sacc[j][2] - nm1);
            sacc[j][3] = ex2(sacc[j][3] - nm1);
            ps0 += sacc[j][0] + sacc[j][1];
            ps1 += sacc[j][2] + sacc[j][3];
        }
        #pragma unroll
        for (int off = 1; off <= 2; off <<= 1) {
            ps0 += __shfl_xor_sync(0xffffffffu, ps0, off);
            ps1 += __shfl_xor_sync(0xffffffffu, ps1, off);
        }
        rsum0 = rsum0 * corr0 + ps0;
        rsum1 = rsum1 * corr1 + ps1;

        #pragma unroll
        for (int j = 0; j < 8; j++) {
            oacc[j][0] *= corr0; oacc[j][1] *= corr0;
            oacc[j][2] *= corr1; oacc[j][3] *= corr1;
        }

        // ---- O += P V (3-term); term-outer per db (RAW distance 2)
        #pragma unroll
        for (int kp = 0; kp < 4; kp++) {
            uint32_t pah[4], pal[4];
            {
                const int j0 = kp * 2, j1 = kp * 2 + 1;
                float p00 = sacc[j0][0], p01 = sacc[j0][1];
                float p02 = sacc[j0][2], p03 = sacc[j0][3];
                float p10 = sacc[j1][0], p11 = sacc[j1][1];
                float p12 = sacc[j1][2], p13 = sacc[j1][3];
                pah[0] = packbf2(p00, p01);
                pah[1] = packbf2(p02, p03);
                pah[2] = packbf2(p10, p11);
                pah[3] = packbf2(p12, p13);
                __nv_bfloat162* hp;
                hp = (__nv_bfloat162*)&pah[0];
                pal[0] = packbf2(p00 - __bfloat162float(hp->x), p01 - __bfloat162float(hp->y));
                hp = (__nv_bfloat162*)&pah[1];
                pal[1] = packbf2(p02 - __bfloat162float(hp->x), p03 - __bfloat162float(hp->y));
                hp = (__nv_bfloat162*)&pah[2];
                pal[2] = packbf2(p10 - __bfloat162float(hp->x), p11 - __bfloat162float(hp->y));
                hp = (__nv_bfloat162*)&pah[3];
                pal[3] = packbf2(p12 - __bfloat162float(hp->x), p13 - __bfloat162float(hp->y));
            }
            #pragma unroll
            for (int db = 0; db < 4; db++) {
                uint32_t vbh[4], vbl[4];
                uint32_t o = sV + voffb + (uint32_t)(kp * 16 * AST + db * 16) * 2;
                ldsm4t(vbh, o);
                ldsm4t(vbl, o + AKB);
                const int j0 = db * 2, j1 = db * 2 + 1;
                uint32_t bh0[2] = { vbh[0], vbh[1] }, bh1[2] = { vbh[2], vbh[3] };
                uint32_t bl0[2] = { vbl[0], vbl[1] }, bl1[2] = { vbl[2], vbl[3] };
                mma16816(oacc[j0], pah, bh0);
                mma16816(oacc[j1], pah, bh1);
                mma16816(oacc[j0], pah, bl0);
                mma16816(oacc[j1], pah, bl1);
                mma16816(oacc[j0], pal, bh0);
                mma16816(oacc[j1], pal, bh1);
            }
        }
    }
#undef KV_COPY

    // ---- normalize + write ctx (bf16 hi/lo)
    const float inv0 = 1.0f / rsum0, inv1 = 1.0f / rsum1;
    const int row0 = q0 + wq * 16 + (lane >> 2);
    #pragma unroll
    for (int j = 0; j < 8; j++) {
        const int col = h * DH + j * 8 + (lane & 3) * 2;
        float v0 = oacc[j][0] * inv0, v1 = oacc[j][1] * inv0;
        float v2 = oacc[j][2] * inv1, v3 = oacc[j][3] * inv1;
        __nv_bfloat16 h0,l0,h1,l1,h2,l2,h3,l3;
        split1(v0,h0,l0); split1(v1,h1,l1); split1(v2,h2,l2); split1(v3,h3,l3);
        size_t o0 = (rowbase + row0)     * (size_t)INNER + col;
        size_t o1 = (rowbase + row0 + 8) * (size_t)INNER + col;
        ushort2 a0 = { __bfloat16_as_ushort(h0), __bfloat16_as_ushort(h1) };
        ushort2 b0 = { __bfloat16_as_ushort(l0), __bfloat16_as_ushort(l1) };
        ushort2 a1 = { __bfloat16_as_ushort(h2), __bfloat16_as_ushort(h3) };
        ushort2 b1 = { __bfloat16_as_ushort(l2), __bfloat16_as_ushort(l3) };
        *(ushort2*)(ctxh + o0) = a0;
        *(ushort2*)(ctxl + o0) = b0;
        *(ushort2*)(ctxh + o1) = a1;
        *(ushort2*)(ctxl + o1) = b1;
    }
}

// ---------------------------------------------------------------------------
// launch
// ---------------------------------------------------------------------------
extern "C" void kernel_launch(void* const* d_in, const int* in_sizes, int n_in,
                              void* d_out, int out_size)
{
    const float* x     = (const float*)d_in[0];
    const float* m     = (const float*)d_in[1];
    const float* gamma = (const float*)d_in[2];
    const float* beta  = (const float*)d_in[3];
    const float* Wqkv  = (const float*)d_in[4];
    const float* Wout  = (const float*)d_in[5];
    float* out = (float*)d_out;

    __nv_bfloat16 *xnh, *xnl, *wqh, *wql, *woh, *wol, *qkvh, *qkvl, *ctxh, *ctxl;
    cudaGetSymbolAddress((void**)&xnh,  g_xn_h);
    cudaGetSymbolAddress((void**)&xnl,  g_xn_l);
    cudaGetSymbolAddress((void**)&wqh,  g_wq_h);
    cudaGetSymbolAddress((void**)&wql,  g_wq_l);
    cudaGetSymbolAddress((void**)&woh,  g_wo_h);
    cudaGetSymbolAddress((void**)&wol,  g_wo_l);
    cudaGetSymbolAddress((void**)&qkvh, g_qkv_h);
    cudaGetSymbolAddress((void**)&qkvl, g_qkv_l);
    cudaGetSymbolAddress((void**)&ctxh, g_ctx_h);
    cudaGetSymbolAddress((void**)&ctxl, g_ctx_l);

    cudaFuncSetAttribute(mma_gemm,
                         cudaFuncAttributeMaxDynamicSharedMemorySize, GSMEM);
    cudaFuncSetAttribute(attn_mma_kernel,
                         cudaFuncAttributeMaxDynamicSharedMemorySize, ASMEM);

    // 1. LayerNorm (+ bf16 split)
    ln_kernel<<<NROWS, 256>>>(x, gamma, beta, xnh, xnl);

    // 2. weight transpose + split
    splitT_kernel<<<dim3(3*INNER/32, DMODEL/32), dim3(32,8)>>>(Wqkv, wqh, wql, DMODEL, 3*INNER);
    splitT_kernel<<<dim3(DMODEL/32,  INNER/32),  dim3(32,8)>>>(Wout, woh, wol, INNER, DMODEL);

    // 3. QKV projection -> bf16 hi/lo qkv
    mma_gemm<<<dim3(3*INNER/128, NROWS/128), 256, GSMEM>>>(
        xnh, xnl, wqh, wql, nullptr, qkvh, qkvl, 3*INNER);

    // 4. masked flash attention on tensor cores
    attn_mma_kernel<<<dim3(NSEQ/128, HEADS, BATCH), 256, ASMEM>>>(
        qkvh, qkvl, m, ctxh, ctxl);

    // 5. output projection -> fp32 out
    mma_gemm<<<dim3(DMODEL/128, NROWS/128), 256, GSMEM>>>(
        ctxh, ctxl, woh, wol, out, nullptr, nullptr, DMODEL);
}

// round 13
// speedup vs baseline: 1.1388x; 1.1011x over previous
#include <cuda_runtime.h>
#include <cuda_bf16.h>
#include <math.h>
#include <stdint.h>

// ---------------------------------------------------------------------------
// Problem constants
// ---------------------------------------------------------------------------
#define BATCH   2
#define NSEQ    2048
#define DMODEL  1024
#define HEADS   16
#define DH      64
#define INNER   1024
#define NROWS   (BATCH*NSEQ)   // 4096
#define SCALE   0.125f
#define SC2     (0.125f * 1.4426950408889634f)   // SCALE * log2(e)
#define LN_EPS  1e-5f

// ---------------------------------------------------------------------------
// Scratch (__device__ globals; no allocs allowed)
// ---------------------------------------------------------------------------
__device__ __nv_bfloat16 g_xn_h [(size_t)NROWS * DMODEL];
__device__ __nv_bfloat16 g_xn_l [(size_t)NROWS * DMODEL];
__device__ __nv_bfloat16 g_wq_h [(size_t)3*INNER * DMODEL];   // Wqkv^T [3072][1024]
__device__ __nv_bfloat16 g_wq_l [(size_t)3*INNER * DMODEL];
__device__ __nv_bfloat16 g_wo_h [(size_t)DMODEL * INNER];     // Wout^T
__device__ __nv_bfloat16 g_wo_l [(size_t)DMODEL * INNER];
__device__ __nv_bfloat16 g_qkv_h[(size_t)NROWS * 3 * INNER];  // bf16 hi QKV
__device__ __nv_bfloat16 g_qkv_l[(size_t)NROWS * 3 * INNER];  // bf16 lo QKV
__device__ __nv_bfloat16 g_ctx_h[(size_t)NROWS * INNER];
__device__ __nv_bfloat16 g_ctx_l[(size_t)NROWS * INNER];

// ---------------------------------------------------------------------------
// Helpers
// ---------------------------------------------------------------------------
__device__ __forceinline__ void split1(float v, __nv_bfloat16& h, __nv_bfloat16& l) {
    h = __float2bfloat16(v);
    l = __float2bfloat16(v - __bfloat162float(h));
}

__device__ __forceinline__ float ex2(float x) {
    float y;
    asm("ex2.approx.ftz.f32 %0, %1;" : "=f"(y) : "f"(x));
    return y;
}

__device__ __forceinline__ void ldsm4(uint32_t* r, uint32_t addr) {
    asm volatile("ldmatrix.sync.aligned.m8n8.x4.shared.b16 {%0,%1,%2,%3}, [%4];"
                 : "=r"(r[0]), "=r"(r[1]), "=r"(r[2]), "=r"(r[3]) : "r"(addr));
}

__device__ __forceinline__ void ldsm4t(uint32_t* r, uint32_t addr) {
    asm volatile("ldmatrix.sync.aligned.m8n8.x4.trans.shared.b16 {%0,%1,%2,%3}, [%4];"
                 : "=r"(r[0]), "=r"(r[1]), "=r"(r[2]), "=r"(r[3]) : "r"(addr));
}

__device__ __forceinline__ void mma16816(float* d, const uint32_t* a,
                                         const uint32_t* b) {
    asm volatile(
        "mma.sync.aligned.m16n8k16.row.col.f32.bf16.bf16.f32 "
        "{%0,%1,%2,%3}, {%4,%5,%6,%7}, {%8,%9}, {%0,%1,%2,%3};"
        : "+f"(d[0]), "+f"(d[1]), "+f"(d[2]), "+f"(d[3])
        : "r"(a[0]), "r"(a[1]), "r"(a[2]), "r"(a[3]), "r"(b[0]), "r"(b[1]));
}

__device__ __forceinline__ void cp16(uint32_t dst, const void* src) {
    asm volatile("cp.async.cg.shared.global [%0], [%1], 16;"
                 :: "r"(dst), "l"(__cvta_generic_to_global(src)));
}

__device__ __forceinline__ uint32_t packbf2(float a, float b) {
    __nv_bfloat162 t = __floats2bfloat162_rn(a, b);
    return *(uint32_t*)&t;
}

// ---------------------------------------------------------------------------
// Kernel 1: LayerNorm fused with bf16 hi/lo split output
// ---------------------------------------------------------------------------
__global__ __launch_bounds__(256) void ln_kernel(
    const float* __restrict__ x, const float* __restrict__ gamma,
    const float* __restrict__ beta,
    __nv_bfloat16* __restrict__ xh, __nv_bfloat16* __restrict__ xl)
{
    int row = blockIdx.x;
    int tid = threadIdx.x;
    const float4* xr = (const float4*)(x + (size_t)row * DMODEL);
    float4 v = xr[tid];

    float s  = v.x + v.y + v.z + v.w;
    float ss = v.x*v.x + v.y*v.y + v.z*v.z + v.w*v.w;
    #pragma unroll
    for (int off = 16; off; off >>= 1) {
        s  += __shfl_xor_sync(0xffffffffu, s,  off);
        ss += __shfl_xor_sync(0xffffffffu, ss, off);
    }
    __shared__ float sbuf[8], ssbuf[8];
    int warp = tid >> 5, lane = tid & 31;
    if (lane == 0) { sbuf[warp] = s; ssbuf[warp] = ss; }
    __syncthreads();
    s = 0.f; ss = 0.f;
    #pragma unroll
    for (int w = 0; w < 8; w++) { s += sbuf[w]; ss += ssbuf[w]; }

    float mu  = s * (1.0f / DMODEL);
    float var = ss * (1.0f / DMODEL) - mu * mu;
    float inv = rsqrtf(var + LN_EPS);

    float4 g  = ((const float4*)gamma)[tid];
    float4 be = ((const float4*)beta)[tid];
    float o0 = (v.x - mu) * inv * g.x + be.x;
    float o1 = (v.y - mu) * inv * g.y + be.y;
    float o2 = (v.z - mu) * inv * g.z + be.z;
    float o3 = (v.w - mu) * inv * g.w + be.w;

    __nv_bfloat16 h0,h1,h2,h3,l0,l1,l2,l3;
    split1(o0,h0,l0); split1(o1,h1,l1); split1(o2,h2,l2); split1(o3,h3,l3);
    size_t off = (size_t)row * DMODEL + tid * 4;
    ushort4 hv = { __bfloat16_as_ushort(h0), __bfloat16_as_ushort(h1),
                   __bfloat16_as_ushort(h2), __bfloat16_as_ushort(h3) };
    ushort4 lv = { __bfloat16_as_ushort(l0), __bfloat16_as_ushort(l1),
                   __bfloat16_as_ushort(l2), __bfloat16_as_ushort(l3) };
    *(ushort4*)(xh + off) = hv;
    *(ushort4*)(xl + off) = lv;
}

// ---------------------------------------------------------------------------
// Kernel 2: transpose + bf16 split for weights
// ---------------------------------------------------------------------------
__global__ __launch_bounds__(256) void splitT_kernel(
    const float* __restrict__ W,
    __nv_bfloat16* __restrict__ Th, __nv_bfloat16* __restrict__ Tl,
    int K, int N)
{
    __shared__ float t[32][33];
    int n0 = blockIdx.x * 32, k0 = blockIdx.y * 32;
    int tx = threadIdx.x, ty = threadIdx.y;
    #pragma unroll
    for (int j = 0; j < 4; j++) {
        int r = ty + j * 8;
        t[r][tx] = W[(size_t)(k0 + r) * N + n0 + tx];
    }
    __syncthreads();
    #pragma unroll
    for (int j = 0; j < 4; j++) {
        int r = ty + j * 8;
        float v = t[tx][r];
        __nv_bfloat16 h, l;
        split1(v, h, l);
        size_t o = (size_t)(n0 + r) * K + k0 + tx;
        Th[o] = h; Tl[o] = l;
    }
}

// ---------------------------------------------------------------------------
// Kernel 3: bf16x3-split GEMM on mma.sync.
// 128x128 block, 4 warps @ 64x64 each (halves LDSM traffic per MAC).
// 3-stage cp.async pipeline, ONE __syncthreads per iteration, 2 CTAs/SM.
// Smem: 64-byte rows (32 bf16), XOR chunk swizzle c^=((row>>1)&3).
// ---------------------------------------------------------------------------
#define GK    1024
#define GBK   32
#define GARR  (128 * 64)              // 8192 B per array (128 rows x 64 B)
#define GBLK  (4 * GARR)              // 32768 B per stage {Ah,Al,Bh,Bl}
#define GSMEM (3 * GBLK)              // 98304 B

__global__ __launch_bounds__(128, 2) void mma_gemm(
    const __nv_bfloat16* __restrict__ Ah, const __nv_bfloat16* __restrict__ Al,
    const __nv_bfloat16* __restrict__ Bh, const __nv_bfloat16* __restrict__ Bl,
    float* __restrict__ Cf,
    __nv_bfloat16* __restrict__ Ch, __nv_bfloat16* __restrict__ Cl,
    int N)
{
    extern __shared__ char smg[];
    const uint32_t sb = (uint32_t)__cvta_generic_to_shared(smg);

    const int tid  = threadIdx.x;
    const int lane = tid & 31, wid = tid >> 5;
    const int wm = wid >> 1, wn = wid & 1;            // 2x2 warp grid
    const int m0 = blockIdx.y * 128, n0 = blockIdx.x * 128;

    float acc[4][8][4];
    #pragma unroll
    for (int f = 0; f < 4; f++)
        #pragma unroll
        for (int j = 0; j < 8; j++)
            #pragma unroll
            for (int e = 0; e < 4; e++) acc[f][j][e] = 0.f;

    // A-side ldmatrix lane constants (warp covers rows wm*64 .. +63)
    const int arow = wm * 64 + (lane & 15);
    const uint32_t abase = (uint32_t)(arow * 64);
    const uint32_t axor  = (uint32_t)(((arow >> 1) & 3) << 4);
    const uint32_t achk  = (uint32_t)(lane >> 4);            // + ks*2

    // B-side (warp covers n-rows wn*64 .. +63)
    const int brow = wn * 64 + (lane & 7) + ((lane >> 4) << 3);
    const uint32_t bbase = (uint32_t)(brow * 64);
    const uint32_t bxor  = (uint32_t)(((brow >> 1) & 3) << 4);
    const uint32_t bchk  = (uint32_t)((lane >> 3) & 1);      // + ks*2

    // copy: 2048 16B-chunks per stage, 16 per thread; arr = t>>2 static
#define STAGE_COPY(st, kc)                                                     \
    do {                                                                       \
        uint32_t so = sb + (uint32_t)(st) * GBLK;                              \
        _Pragma("unroll")                                                      \
        for (int t = 0; t < 16; t++) {                                         \
            const int arr = t >> 2;                                            \
            const int r = (t & 3) * 32 + (tid >> 2);                           \
            const int c = tid & 3;                                             \
            uint32_t d = so + (uint32_t)arr * GARR                             \
                       + (uint32_t)(r * 64 + ((c ^ ((r >> 1) & 3)) << 4));     \
            const __nv_bfloat16* srcp =                                        \
                (arr == 0) ? (Ah + (size_t)(m0 + r) * GK + (kc) + c * 8) :     \
                (arr == 1) ? (Al + (size_t)(m0 + r) * GK + (kc) + c * 8) :     \
                (arr == 2) ? (Bh + (size_t)(n0 + r) * GK + (kc) + c * 8) :     \
                             (Bl + (size_t)(n0 + r) * GK + (kc) + c * 8);      \
            cp16(d, srcp);                                                     \
        }                                                                      \
    } while (0)

    STAGE_COPY(0, 0);
    asm volatile("cp.async.commit_group;" ::: "memory");
    STAGE_COPY(1, GBK);
    asm volatile("cp.async.commit_group;" ::: "memory");

    const int nk = GK / GBK;   // 32
    for (int kt = 0; kt < nk; kt++) {
        const int st = kt % 3;
        asm volatile("cp.async.wait_group 1;" ::: "memory");
        __syncthreads();

        if (kt + 2 < nk) { STAGE_COPY((kt + 2) % 3, (kt + 2) * GBK); }
        asm volatile("cp.async.commit_group;" ::: "memory");

        const uint32_t so = sb + (uint32_t)st * GBLK;
        #pragma unroll
        for (int ks = 0; ks < 2; ks++) {
            uint32_t bh[4][4], bl[4][4];
            #pragma unroll
            for (int nb = 0; nb < 4; nb++) {
                uint32_t o = so + 2*GARR + bbase + (uint32_t)(nb * 16 * 64)
                           + ((((bchk + ks*2)) << 4) ^ bxor);
                ldsm4(bh[nb], o);
                ldsm4(bl[nb], o + GARR);
            }
            #pragma unroll
            for (int f = 0; f < 4; f++) {
                uint32_t ah[4], al[4];
                uint32_t o = so + abase + (uint32_t)(f * 16 * 64)
                           + ((((achk + ks*2)) << 4) ^ axor);
                ldsm4(ah, o);
                ldsm4(al, o + GARR);
                // term-outer: RAW distance 8
                #pragma unroll
                for (int j = 0; j < 8; j++) {
                    uint32_t bp[2] = { bh[j >> 1][(j & 1) * 2],
                                       bh[j >> 1][(j & 1) * 2 + 1] };
                    mma16816(acc[f][j], ah, bp);
                }
                #pragma unroll
                for (int j = 0; j < 8; j++) {
                    uint32_t bp[2] = { bl[j >> 1][(j & 1) * 2],
                                       bl[j >> 1][(j & 1) * 2 + 1] };
                    mma16816(acc[f][j], ah, bp);
                }
                #pragma unroll
                for (int j = 0; j < 8; j++) {
                    uint32_t bp[2] = { bh[j >> 1][(j & 1) * 2],
                                       bh[j >> 1][(j & 1) * 2 + 1] };
                    mma16816(acc[f][j], al, bp);
                }
            }
        }
    }

    const int erow = m0 + wm * 64 + (lane >> 2);
    const int ecol = n0 + wn * 64 + (lane & 3) * 2;
    if (Cf) {
        #pragma unroll
        for (int f = 0; f < 4; f++) {
            #pragma unroll
            for (int j = 0; j < 8; j++) {
                float* d0 = Cf + (size_t)(erow + f * 16)     * N + ecol + j * 8;
                float* d1 = Cf + (size_t)(erow + f * 16 + 8) * N + ecol + j * 8;
                *(float2*)d0 = make_float2(acc[f][j][0], acc[f][j][1]);
                *(float2*)d1 = make_float2(acc[f][j][2], acc[f][j][3]);
            }
        }
    } else {
        #pragma unroll
        for (int f = 0; f < 4; f++) {
            #pragma unroll
            for (int j = 0; j < 8; j++) {
                #pragma unroll
                for (int half = 0; half < 2; half++) {
                    size_t o = (size_t)(erow + f*16 + half*8) * N + ecol + j*8;
                    float v0 = acc[f][j][half*2], v1 = acc[f][j][half*2 + 1];
                    __nv_bfloat16 h0,l0,h1,l1;
                    split1(v0,h0,l0); split1(v1,h1,l1);
                    ushort2 hv = { __bfloat16_as_ushort(h0), __bfloat16_as_ushort(h1) };
                    ushort2 lv = { __bfloat16_as_ushort(l0), __bfloat16_as_ushort(l1) };
                    *(ushort2*)(Ch + o) = hv;
                    *(ushort2*)(Cl + o) = lv;
                }
            }
        }
    }
#undef STAGE_COPY
}

// ---------------------------------------------------------------------------
// Kernel 4: flash attention on mma.sync, bf16x3 split.
// BQ=128, 4 warps @ 32 q-rows each (halves K/V LDSM redundancy).
// Q in own smem region (reloaded per kk); 2-stage KV ring, distance-1
// prefetch, wait_group 0 + ONE sync per iteration. 2 CTAs/SM.
// ---------------------------------------------------------------------------
#define AST   72                       // smem row stride (bf16 elems)
#define AKB   (64 * AST * 2)           // 9216 B per K/V array
#define AKVST (4 * AKB)                // 36864 B per KV stage {Kh,Kl,Vh,Vl}
#define AQB   (128 * AST * 2)          // 18432 B per Q array
#define ASMEM (2 * AKVST + 2 * AQB)    // 110592 B

__global__ __launch_bounds__(128, 2) void attn_mma_kernel(
    const __nv_bfloat16* __restrict__ qh_g, const __nv_bfloat16* __restrict__ ql_g,
    const float* __restrict__ mask,
    __nv_bfloat16* __restrict__ ctxh, __nv_bfloat16* __restrict__ ctxl)
{
    extern __shared__ char sma[];
    const uint32_t sb  = (uint32_t)__cvta_generic_to_shared(sma);
    const uint32_t uQh = sb + 2 * AKVST;
    const uint32_t uQl = uQh + AQB;

    const int tid = threadIdx.x, lane = tid & 31, wq = tid >> 5;  // 4 warps
    const int qt = blockIdx.x, h = blockIdx.y, b = blockIdx.z;
    const int q0 = qt * 128;
    const size_t rowbase = (size_t)b * NSEQ;
    const size_t qkstride = 3 * INNER;

#define KV_COPY(st, kc)                                                        \
    do {                                                                       \
        uint32_t so = sb + (uint32_t)(st) * AKVST;                             \
        _Pragma("unroll")                                                      \
        for (int t = 0; t < 16; t++) {                                         \
            const int arr = t >> 2;                                            \
            const int r = (t & 3) * 16 + (tid >> 3);                           \
            const int c = tid & 7;                                             \
            uint32_t d = so + (uint32_t)arr * AKB                              \
                       + (uint32_t)(r * AST + c * 8) * 2;                      \
            size_t col = ((arr < 2) ? INNER : 2*INNER) + h*DH + c*8;           \
            size_t g = (rowbase + (kc) + r) * qkstride + col;                  \
            const __nv_bfloat16* srcp = (arr & 1) ? (ql_g + g) : (qh_g + g);   \
            cp16(d, srcp);                                                     \
        }                                                                      \
    } while (0)

    // prologue: Q copy + KV stage 0, one group
    {
        #pragma unroll
        for (int t = 0; t < 16; t++) {
            const int arr = t >> 3;                       // 0 = hi, 1 = lo
            const int r = (t & 7) * 16 + (tid >> 3);
            const int c = tid & 7;
            uint32_t d = uQh + (uint32_t)arr * AQB + (uint32_t)(r * AST + c * 8) * 2;
            size_t g = (rowbase + q0 + r) * qkstride + h * DH + c * 8;
            cp16(d, arr ? (ql_g + g) : (qh_g + g));
        }
    }
    KV_COPY(0, 0);
    asm volatile("cp.async.commit_group;" ::: "memory");

    float oacc[2][8][4];
    #pragma unroll
    for (int mf = 0; mf < 2; mf++)
        #pragma unroll
        for (int j = 0; j < 8; j++)
            #pragma unroll
            for (int e = 0; e < 4; e++) oacc[mf][j][e] = 0.f;
    float rmax[4] = {-1e30f, -1e30f, -1e30f, -1e30f};
    float rsum[4] = {0.f, 0.f, 0.f, 0.f};

    // per-lane smem offsets
    const uint32_t qoff0 = (uint32_t)((wq*32 + (lane & 15)) * AST
                           + (lane >> 4) * 8) * 2;          // mf adds 16*AST*2
    const uint32_t koffb = (uint32_t)(((lane & 7) + ((lane >> 4) << 3)) * AST
                           + ((lane >> 3) & 1) * 8) * 2;
    const uint32_t voffb = (uint32_t)(((lane & 15)) * AST + (lane >> 4) * 8) * 2;

    const int nk = NSEQ / 64;   // 32
    for (int kt = 0; kt < nk; kt++) {
        const int st = kt & 1;
        asm volatile("cp.async.wait_group 0;" ::: "memory");
        __syncthreads();

        if (kt + 1 < nk) { KV_COPY(st ^ 1, (kt + 1) * 64); }
        asm volatile("cp.async.commit_group;" ::: "memory");

        const uint32_t so = sb + (uint32_t)st * AKVST;   // Kh base
        const uint32_t sV = so + 2 * AKB;

        // ---- S = Q K^T (3-term), 2 m-frags per warp
        float sacc[2][8][4];
        #pragma unroll
        for (int mf = 0; mf < 2; mf++)
            #pragma unroll
            for (int j = 0; j < 8; j++)
                #pragma unroll
                for (int e = 0; e < 4; e++) sacc[mf][j][e] = 0.f;

        #pragma unroll
        for (int kk = 0; kk < 4; kk++) {
            uint32_t qh[2][4], ql[2][4];
            #pragma unroll
            for (int mf = 0; mf < 2; mf++) {
                uint32_t qo = (mf ? (uQh + (uint32_t)(16 * AST * 2)) : uQh)
                            + qoff0 + (uint32_t)(kk * 16) * 2;
                ldsm4(qh[mf], qo);
                ldsm4(ql[mf], qo + AQB);
            }
            #pragma unroll
            for (int jb = 0; jb < 4; jb++) {
                uint32_t kbh[4], kbl[4];
                uint32_t o = so + koffb + (uint32_t)(jb * 16 * AST + kk * 16) * 2;
                ldsm4(kbh, o);
                ldsm4(kbl, o + AKB);
                const int j0 = jb * 2, j1 = jb * 2 + 1;
                uint32_t bh0[2] = { kbh[0], kbh[1] }, bh1[2] = { kbh[2], kbh[3] };
                uint32_t bl0[2] = { kbl[0], kbl[1] }, bl1[2] = { kbl[2], kbl[3] };
                // distance-4 issue: each term sweeps (mf,sub)
                mma16816(sacc[0][j0], qh[0], bh0);
                mma16816(sacc[0][j1], qh[0], bh1);
                mma16816(sacc[1][j0], qh[1], bh0);
                mma16816(sacc[1][j1], qh[1], bh1);
                mma16816(sacc[0][j0], qh[0], bl0);
                mma16816(sacc[0][j1], qh[0], bl1);
                mma16816(sacc[1][j0], qh[1], bl0);
                mma16816(sacc[1][j1], qh[1], bl1);
                mma16816(sacc[0][j0], ql[0], bh0);
                mma16816(sacc[0][j1], ql[0], bh1);
                mma16816(sacc[1][j0], ql[1], bh0);
                mma16816(sacc[1][j1], ql[1], bh1);
            }
        }

        // ---- mask add (before scale), scale into exp2 domain; softmax per mf
        #pragma unroll
        for (int mf = 0; mf < 2; mf++) {
            const int qrow = q0 + wq * 32 + mf * 16 + (lane >> 2);
            const int kcol = kt * 64 + (lane & 3) * 2;
            const float* mg = mask + ((size_t)b * NSEQ + qrow) * NSEQ + kcol;
            #pragma unroll
            for (int j = 0; j < 8; j++) {
                float2 m0 = *(const float2*)(mg + j * 8);
                float2 m1 = *(const float2*)(mg + 8 * NSEQ + j * 8);
                sacc[mf][j][0] = (sacc[mf][j][0] + m0.x) * SC2;
                sacc[mf][j][1] = (sacc[mf][j][1] + m0.y) * SC2;
                sacc[mf][j][2] = (sacc[mf][j][2] + m1.x) * SC2;
                sacc[mf][j][3] = (sacc[mf][j][3] + m1.y) * SC2;
            }

            float tm0 = -1e30f, tm1 = -1e30f;
            #pragma unroll
            for (int j = 0; j < 8; j++) {
                tm0 = fmaxf(tm0, fmaxf(sacc[mf][j][0], sacc[mf][j][1]));
                tm1 = fmaxf(tm1, fmaxf(sacc[mf][j][2], sacc[mf][j][3]));
            }
            #pragma unroll
            for (int off = 1; off <= 2; off <<= 1) {
                tm0 = fmaxf(tm0, __shfl_xor_sync(0xffffffffu, tm0, off));
                tm1 = fmaxf(tm1, __shfl_xor_sync(0xffffffffu, tm1, off));
            }
            float nm0 = fmaxf(rmax[mf*2],   tm0);
            float nm1 = fmaxf(rmax[mf*2+1], tm1);
            float corr0 = ex2(rmax[mf*2]   - nm0);
            float corr1 = ex2(rmax[mf*2+1] - nm1);
            rmax[mf*2] = nm0; rmax[mf*2+1] = nm1;

            float ps0 = 0.f, ps1 = 0.f;
            #pragma unroll
            for (int j = 0; j < 8; j++) {
                sacc[mf][j][0] = ex2(sacc[mf][j][0] - nm0);
                sacc[mf][j][1] = ex2(sacc[mf][j][1] - nm0);
                sacc[mf][j][2] = ex2(sacc[mf][j][2] - nm1);
                sacc[mf][j][3] = ex2(sacc[mf][j][3] - nm1);
                ps0 += sacc[mf][j][0] + sacc[mf][j][1];
                ps1 += sacc[mf][j][2] + sacc[mf][j][3];
            }
            #pragma unroll
            for (int off = 1; off <= 2; off <<= 1) {
                ps0 += __shfl_xor_sync(0xffffffffu, ps0, off);
                ps1 += __shfl_xor_sync(0xffffffffu, ps1, off);
            }
            rsum[mf*2]   = rsum[mf*2]   * corr0 + ps0;
            rsum[mf*2+1] = rsum[mf*2+1] * corr1 + ps1;

            #pragma unroll
            for (int j = 0; j < 8; j++) {
                oacc[mf][j][0] *= corr0; oacc[mf][j][1] *= corr0;
                oacc[mf][j][2] *= corr1; oacc[mf][j][3] *= corr1;
            }
        }

        // ---- O += P V (3-term)
        #pragma unroll
        for (int kp = 0; kp < 4; kp++) {
            uint32_t pah[2][4], pal[2][4];
            #pragma unroll
            for (int mf = 0; mf < 2; mf++) {
                const int j0 = kp * 2, j1 = kp * 2 + 1;
                float p00 = sacc[mf][j0][0], p01 = sacc[mf][j0][1];
                float p02 = sacc[mf][j0][2], p03 = sacc[mf][j0][3];
                float p10 = sacc[mf][j1][0], p11 = sacc[mf][j1][1];
                float p12 = sacc[mf][j1][2], p13 = sacc[mf][j1][3];
                pah[mf][0] = packbf2(p00, p01);
                pah[mf][1] = packbf2(p02, p03);
                pah[mf][2] = packbf2(p10, p11);
                pah[mf][3] = packbf2(p12, p13);
                __nv_bfloat162* hp;
                hp = (__nv_bfloat162*)&pah[mf][0];
                pal[mf][0] = packbf2(p00 - __bfloat162float(hp->x), p01 - __bfloat162float(hp->y));
                hp = (__nv_bfloat162*)&pah[mf][1];
                pal[mf][1] = packbf2(p02 - __bfloat162float(hp->x), p03 - __bfloat162float(hp->y));
                hp = (__nv_bfloat162*)&pah[mf][2];
                pal[mf][2] = packbf2(p10 - __bfloat162float(hp->x), p11 - __bfloat162float(hp->y));
                hp = (__nv_bfloat162*)&pah[mf][3];
                pal[mf][3] = packbf2(p12 - __bfloat162float(hp->x), p13 - __bfloat162float(hp->y));
            }
            #pragma unroll
            for (int db = 0; db < 4; db++) {
                uint32_t vbh[4], vbl[4];
                uint32_t o = sV + voffb + (uint32_t)(kp * 16 * AST + db * 16) * 2;
                ldsm4t(vbh, o);
                ldsm4t(vbl, o + AKB);
                const int j0 = db * 2, j1 = db * 2 + 1;
                uint32_t bh0[2] = { vbh[0], vbh[1] }, bh1[2] = { vbh[2], vbh[3] };
                uint32_t bl0[2] = { vbl[0], vbl[1] }, bl1[2] = { vbl[2], vbl[3] };
                mma16816(oacc[0][j0], pah[0], bh0);
                mma16816(oacc[0][j1], pah[0], bh1);
                mma16816(oacc[1][j0], pah[1], bh0);
                mma16816(oacc[1][j1], pah[1], bh1);
                mma16816(oacc[0][j0], pah[0], bl0);
                mma16816(oacc[0][j1], pah[0], bl1);
                mma16816(oacc[1][j0], pah[1], bl0);
                mma16816(oacc[1][j1], pah[1], bl1);
                mma16816(oacc[0][j0], pal[0], bh0);
                mma16816(oacc[0][j1], pal[0], bh1);
                mma16816(oacc[1][j0], pal[1], bh0);
                mma16816(oacc[1][j1], pal[1], bh1);
            }
        }
    }
#undef KV_COPY

    // ---- normalize + write ctx (bf16 hi/lo)
    #pragma unroll
    for (int mf = 0; mf < 2; mf++) {
        const float inv0 = 1.0f / rsum[mf*2], inv1 = 1.0f / rsum[mf*2+1];
        const int row0 = q0 + wq * 32 + mf * 16 + (lane >> 2);
        #pragma unroll
        for (int j = 0; j < 8; j++) {
            const int col = h * DH + j * 8 + (lane & 3) * 2;
            float v0 = oacc[mf][j][0] * inv0, v1 = oacc[mf][j][1] * inv0;
            float v2 = oacc[mf][j][2] * inv1, v3 = oacc[mf][j][3] * inv1;
            __nv_bfloat16 h0,l0,h1,l1,h2,l2,h3,l3;
            split1(v0,h0,l0); split1(v1,h1,l1); split1(v2,h2,l2); split1(v3,h3,l3);
            size_t o0 = (rowbase + row0)     * (size_t)INNER + col;
            size_t o1 = (rowbase + row0 + 8) * (size_t)INNER + col;
            ushort2 a0 = { __bfloat16_as_ushort(h0), __bfloat16_as_ushort(h1) };
            ushort2 b0 = { __bfloat16_as_ushort(l0), __bfloat16_as_ushort(l1) };
            ushort2 a1 = { __bfloat16_as_ushort(h2), __bfloat16_as_ushort(h3) };
            ushort2 b1 = { __bfloat16_as_ushort(l2), __bfloat16_as_ushort(l3) };
            *(ushort2*)(ctxh + o0) = a0;
            *(ushort2*)(ctxl + o0) = b0;
            *(ushort2*)(ctxh + o1) = a1;
            *(ushort2*)(ctxl + o1) = b1;
        }
    }
}

// ---------------------------------------------------------------------------
// launch
// ---------------------------------------------------------------------------
extern "C" void kernel_launch(void* const* d_in, const int* in_sizes, int n_in,
                              void* d_out, int out_size)
{
    const float* x     = (const float*)d_in[0];
    const float* m     = (const float*)d_in[1];
    const float* gamma = (const float*)d_in[2];
    const float* beta  = (const float*)d_in[3];
    const float* Wqkv  = (const float*)d_in[4];
    const float* Wout  = (const float*)d_in[5];
    float* out = (float*)d_out;

    __nv_bfloat16 *xnh, *xnl, *wqh, *wql, *woh, *wol, *qkvh, *qkvl, *ctxh, *ctxl;
    cudaGetSymbolAddress((void**)&xnh,  g_xn_h);
    cudaGetSymbolAddress((void**)&xnl,  g_xn_l);
    cudaGetSymbolAddress((void**)&wqh,  g_wq_h);
    cudaGetSymbolAddress((void**)&wql,  g_wq_l);
    cudaGetSymbolAddress((void**)&woh,  g_wo_h);
    cudaGetSymbolAddress((void**)&wol,  g_wo_l);
    cudaGetSymbolAddress((void**)&qkvh, g_qkv_h);
    cudaGetSymbolAddress((void**)&qkvl, g_qkv_l);
    cudaGetSymbolAddress((void**)&ctxh, g_ctx_h);
    cudaGetSymbolAddress((void**)&ctxl, g_ctx_l);

    cudaFuncSetAttribute(mma_gemm,
                         cudaFuncAttributeMaxDynamicSharedMemorySize, GSMEM);
    cudaFuncSetAttribute(attn_mma_kernel,
                         cudaFuncAttributeMaxDynamicSharedMemorySize, ASMEM);

    // 1. LayerNorm (+ bf16 split)
    ln_kernel<<<NROWS, 256>>>(x, gamma, beta, xnh, xnl);

    // 2. weight transpose + split
    splitT_kernel<<<dim3(3*INNER/32, DMODEL/32), dim3(32,8)>>>(Wqkv, wqh, wql, DMODEL, 3*INNER);
    splitT_kernel<<<dim3(DMODEL/32,  INNER/32),  dim3(32,8)>>>(Wout, woh, wol, INNER, DMODEL);

    // 3. QKV projection -> bf16 hi/lo qkv
    mma_gemm<<<dim3(3*INNER/128, NROWS/128), 128, GSMEM>>>(
        xnh, xnl, wqh, wql, nullptr, qkvh, qkvl, 3*INNER);

    // 4. masked flash attention on tensor cores
    attn_mma_kernel<<<dim3(NSEQ/128, HEADS, BATCH), 128, ASMEM>>>(
        qkvh, qkvl, m, ctxh, ctxl);

    // 5. output projection -> fp32 out
    mma_gemm<<<dim3(DMODEL/128, NROWS/128), 128, GSMEM>>>(
        ctxh, ctxl, woh, wol, out, nullptr, nullptr, DMODEL);
}

// round 14
// speedup vs baseline: 1.3100x; 1.1503x over previous
#include <cuda_runtime.h>
#include <cuda_bf16.h>
#include <cuda_fp16.h>
#include <math.h>
#include <stdint.h>

// ---------------------------------------------------------------------------
// Problem constants
// ---------------------------------------------------------------------------
#define BATCH   2
#define NSEQ    2048
#define DMODEL  1024
#define HEADS   16
#define DH      64
#define INNER   1024
#define NROWS   (BATCH*NSEQ)   // 4096
#define SCALE   0.125f
#define SC2     (0.125f * 1.4426950408889634f)   // SCALE * log2(e)
#define LN_EPS  1e-5f

typedef unsigned short us;

// ---------------------------------------------------------------------------
// Scratch (__device__ globals; no allocs allowed). All 16-bit buffers are raw
// storage; Q/K sections hold bf16 bits, V section + ctx + Wout hold fp16 bits.
// ---------------------------------------------------------------------------
__device__ us g_xn_h [(size_t)NROWS * DMODEL];
__device__ us g_xn_l [(size_t)NROWS * DMODEL];
__device__ us g_wq_h [(size_t)3*INNER * DMODEL];   // Wqkv^T (bf16)
__device__ us g_wq_l [(size_t)3*INNER * DMODEL];
__device__ us g_wo_h [(size_t)DMODEL * INNER];     // Wout^T (fp16 hi only)
__device__ us g_qkv_h[(size_t)NROWS * 3 * INNER];  // Q,K bf16-hi | V fp16
__device__ us g_qkv_l[(size_t)NROWS * 3 * INNER];  // Q,K bf16-lo | unused V
__device__ us g_ctx_h[(size_t)NROWS * INNER];      // fp16 hi
__device__ us g_ctx_l[(size_t)NROWS * INNER];      // fp16 lo

// ---------------------------------------------------------------------------
// Helpers
// ---------------------------------------------------------------------------
__device__ __forceinline__ void split_bf(float v, us& h, us& l) {
    __nv_bfloat16 hb = __float2bfloat16(v);
    __nv_bfloat16 lb = __float2bfloat16(v - __bfloat162float(hb));
    h = *(us*)&hb; l = *(us*)&lb;
}
__device__ __forceinline__ void split_h(float v, us& h, us& l) {
    __half hh = __float2half_rn(v);
    __half lh = __float2half_rn(v - __half2float(hh));
    h = *(us*)&hh; l = *(us*)&lh;
}
__device__ __forceinline__ us to_h(float v) {
    __half hh = __float2half_rn(v);
    return *(us*)&hh;
}
__device__ __forceinline__ float ex2(float x) {
    float y;
    asm("ex2.approx.ftz.f32 %0, %1;" : "=f"(y) : "f"(x));
    return y;
}
__device__ __forceinline__ void ldsm4(uint32_t* r, uint32_t addr) {
    asm volatile("ldmatrix.sync.aligned.m8n8.x4.shared.b16 {%0,%1,%2,%3}, [%4];"
                 : "=r"(r[0]), "=r"(r[1]), "=r"(r[2]), "=r"(r[3]) : "r"(addr));
}
__device__ __forceinline__ void ldsm4t(uint32_t* r, uint32_t addr) {
    asm volatile("ldmatrix.sync.aligned.m8n8.x4.trans.shared.b16 {%0,%1,%2,%3}, [%4];"
                 : "=r"(r[0]), "=r"(r[1]), "=r"(r[2]), "=r"(r[3]) : "r"(addr));
}
__device__ __forceinline__ void mma_bf16(float* d, const uint32_t* a,
                                         const uint32_t* b) {
    asm volatile(
        "mma.sync.aligned.m16n8k16.row.col.f32.bf16.bf16.f32 "
        "{%0,%1,%2,%3}, {%4,%5,%6,%7}, {%8,%9}, {%0,%1,%2,%3};"
        : "+f"(d[0]), "+f"(d[1]), "+f"(d[2]), "+f"(d[3])
        : "r"(a[0]), "r"(a[1]), "r"(a[2]), "r"(a[3]), "r"(b[0]), "r"(b[1]));
}
__device__ __forceinline__ void mma_fp16(float* d, const uint32_t* a,
                                         const uint32_t* b) {
    asm volatile(
        "mma.sync.aligned.m16n8k16.row.col.f32.f16.f16.f32 "
        "{%0,%1,%2,%3}, {%4,%5,%6,%7}, {%8,%9}, {%0,%1,%2,%3};"
        : "+f"(d[0]), "+f"(d[1]), "+f"(d[2]), "+f"(d[3])
        : "r"(a[0]), "r"(a[1]), "r"(a[2]), "r"(a[3]), "r"(b[0]), "r"(b[1]));
}
__device__ __forceinline__ void cp16(uint32_t dst, const void* src) {
    asm volatile("cp.async.cg.shared.global [%0], [%1], 16;"
                 :: "r"(dst), "l"(__cvta_generic_to_global(src)));
}
__device__ __forceinline__ uint32_t packh2(float a, float b) {
    __half2 t = __floats2half2_rn(a, b);
    return *(uint32_t*)&t;
}

// ---------------------------------------------------------------------------
// Kernel 1: LayerNorm fused with bf16 hi/lo split output
// ---------------------------------------------------------------------------
__global__ __launch_bounds__(256) void ln_kernel(
    const float* __restrict__ x, const float* __restrict__ gamma,
    const float* __restrict__ beta,
    us* __restrict__ xh, us* __restrict__ xl)
{
    int row = blockIdx.x;
    int tid = threadIdx.x;
    const float4* xr = (const float4*)(x + (size_t)row * DMODEL);
    float4 v = xr[tid];

    float s  = v.x + v.y + v.z + v.w;
    float ss = v.x*v.x + v.y*v.y + v.z*v.z + v.w*v.w;
    #pragma unroll
    for (int off = 16; off; off >>= 1) {
        s  += __shfl_xor_sync(0xffffffffu, s,  off);
        ss += __shfl_xor_sync(0xffffffffu, ss, off);
    }
    __shared__ float sbuf[8], ssbuf[8];
    int warp = tid >> 5, lane = tid & 31;
    if (lane == 0) { sbuf[warp] = s; ssbuf[warp] = ss; }
    __syncthreads();
    s = 0.f; ss = 0.f;
    #pragma unroll
    for (int w = 0; w < 8; w++) { s += sbuf[w]; ss += ssbuf[w]; }

    float mu  = s * (1.0f / DMODEL);
    float var = ss * (1.0f / DMODEL) - mu * mu;
    float inv = rsqrtf(var + LN_EPS);

    float4 g  = ((const float4*)gamma)[tid];
    float4 be = ((const float4*)beta)[tid];
    float o[4];
    o[0] = (v.x - mu) * inv * g.x + be.x;
    o[1] = (v.y - mu) * inv * g.y + be.y;
    o[2] = (v.z - mu) * inv * g.z + be.z;
    o[3] = (v.w - mu) * inv * g.w + be.w;

    ushort4 hv, lv;
    split_bf(o[0], hv.x, lv.x); split_bf(o[1], hv.y, lv.y);
    split_bf(o[2], hv.z, lv.z); split_bf(o[3], hv.w, lv.w);
    size_t off = (size_t)row * DMODEL + tid * 4;
    *(ushort4*)(xh + off) = hv;
    *(ushort4*)(xl + off) = lv;
}

// ---------------------------------------------------------------------------
// Kernel 2: transpose + split for weights. mode 0: bf16 hi+lo. mode 1: fp16 hi.
// ---------------------------------------------------------------------------
__global__ __launch_bounds__(256) void splitT_kernel(
    const float* __restrict__ W,
    us* __restrict__ Th, us* __restrict__ Tl,
    int K, int N, int mode)
{
    __shared__ float t[32][33];
    int n0 = blockIdx.x * 32, k0 = blockIdx.y * 32;
    int tx = threadIdx.x, ty = threadIdx.y;
    #pragma unroll
    for (int j = 0; j < 4; j++) {
        int r = ty + j * 8;
        t[r][tx] = W[(size_t)(k0 + r) * N + n0 + tx];
    }
    __syncthreads();
    #pragma unroll
    for (int j = 0; j < 4; j++) {
        int r = ty + j * 8;
        float v = t[tx][r];
        size_t o = (size_t)(n0 + r) * K + k0 + tx;
        if (mode == 0) {
            us h, l; split_bf(v, h, l);
            Th[o] = h; Tl[o] = l;
        } else {
            Th[o] = to_h(v);
        }
    }
}

// ---------------------------------------------------------------------------
// Kernel 3: split GEMM on mma.sync. 128x128 block, 4 warps @ 64x64.
// TERMS=3: AhBh + AhBl + AlBh.  TERMS=2: AhBh + AlBh (Bl never loaded).
// FP16 selects mma flavor. Epilogue: fp32 (Cf) | bf16 h/l | fp16 hi for
// column blocks >= vstart (the V section of the QKV projection).
// ---------------------------------------------------------------------------
#define GK    1024
#define GBK   32
#define GARR  (128 * 64)              // 8192 B per array
#define GBLK  (4 * GARR)              // 32768 B per stage
#define GSMEM (3 * GBLK)              // 98304 B

template<int TERMS, bool FP16>
__global__ __launch_bounds__(128, 2) void mma_gemm(
    const us* __restrict__ Ah, const us* __restrict__ Al,
    const us* __restrict__ Bh, const us* __restrict__ Bl,
    float* __restrict__ Cf, us* __restrict__ Ch, us* __restrict__ Cl,
    int N, int vstart)
{
    extern __shared__ char smg[];
    const uint32_t sb = (uint32_t)__cvta_generic_to_shared(smg);

    const int tid  = threadIdx.x;
    const int lane = tid & 31, wid = tid >> 5;
    const int wm = wid >> 1, wn = wid & 1;
    const int m0 = blockIdx.y * 128, n0 = blockIdx.x * 128;

    float acc[4][8][4];
    #pragma unroll
    for (int f = 0; f < 4; f++)
        #pragma unroll
        for (int j = 0; j < 8; j++)
            #pragma unroll
            for (int e = 0; e < 4; e++) acc[f][j][e] = 0.f;

    const int arow = wm * 64 + (lane & 15);
    const uint32_t abase = (uint32_t)(arow * 64);
    const uint32_t axor  = (uint32_t)(((arow >> 1) & 3) << 4);
    const uint32_t achk  = (uint32_t)(lane >> 4);

    const int brow = wn * 64 + (lane & 7) + ((lane >> 4) << 3);
    const uint32_t bbase = (uint32_t)(brow * 64);
    const uint32_t bxor  = (uint32_t)(((brow >> 1) & 3) << 4);
    const uint32_t bchk  = (uint32_t)((lane >> 3) & 1);

#define STAGE_COPY(st, kc)                                                     \
    do {                                                                       \
        uint32_t so = sb + (uint32_t)(st) * GBLK;                              \
        _Pragma("unroll")                                                      \
        for (int t = 0; t < 16; t++) {                                         \
            const int arr = t >> 2;                                            \
            if (TERMS == 2 && arr == 1) continue;   /* Al still needed; skip Bl */ \
            if (TERMS == 2 && arr == 3) continue;                              \
            const int r = (t & 3) * 32 + (tid >> 2);                           \
            const int c = tid & 3;                                             \
            uint32_t d = so + (uint32_t)arr * GARR                             \
                       + (uint32_t)(r * 64 + ((c ^ ((r >> 1) & 3)) << 4));     \
            const us* srcp =                                                   \
                (arr == 0) ? (Ah + (size_t)(m0 + r) * GK + (kc) + c * 8) :     \
                (arr == 1) ? (Al + (size_t)(m0 + r) * GK + (kc) + c * 8) :     \
                (arr == 2) ? (Bh + (size_t)(n0 + r) * GK + (kc) + c * 8) :     \
                             (Bl + (size_t)(n0 + r) * GK + (kc) + c * 8);      \
            cp16(d, srcp);                                                     \
        }                                                                      \
        if (TERMS == 2) {                                                      \
            _Pragma("unroll")                                                  \
            for (int t = 4; t < 8; t++) {                                      \
                const int r = (t & 3) * 32 + (tid >> 2);                       \
                const int c = tid & 3;                                         \
                uint32_t d = so + (uint32_t)GARR                               \
                           + (uint32_t)(r * 64 + ((c ^ ((r >> 1) & 3)) << 4)); \
                cp16(d, Al + (size_t)(m0 + r) * GK + (kc) + c * 8);            \
            }                                                                  \
        }                                                                      \
    } while (0)

    STAGE_COPY(0, 0);
    asm volatile("cp.async.commit_group;" ::: "memory");
    STAGE_COPY(1, GBK);
    asm volatile("cp.async.commit_group;" ::: "memory");

    const int nk = GK / GBK;
    for (int kt = 0; kt < nk; kt++) {
        const int st = kt % 3;
        asm volatile("cp.async.wait_group 1;" ::: "memory");
        __syncthreads();

        if (kt + 2 < nk) { STAGE_COPY((kt + 2) % 3, (kt + 2) * GBK); }
        asm volatile("cp.async.commit_group;" ::: "memory");

        const uint32_t so = sb + (uint32_t)st * GBLK;
        #pragma unroll
        for (int ks = 0; ks < 2; ks++) {
            uint32_t bh[4][4], bl[4][4];
            #pragma unroll
            for (int nb = 0; nb < 4; nb++) {
                uint32_t o = so + 2*GARR + bbase + (uint32_t)(nb * 16 * 64)
                           + ((((bchk + ks*2)) << 4) ^ bxor);
                ldsm4(bh[nb], o);
                if (TERMS == 3) ldsm4(bl[nb], o + GARR);
            }
            #pragma unroll
            for (int f = 0; f < 4; f++) {
                uint32_t ah[4], al[4];
                uint32_t o = so + abase + (uint32_t)(f * 16 * 64)
                           + ((((achk + ks*2)) << 4) ^ axor);
                ldsm4(ah, o);
                ldsm4(al, o + GARR);
                #pragma unroll
                for (int j = 0; j < 8; j++) {
                    uint32_t bp[2] = { bh[j >> 1][(j & 1) * 2],
                                       bh[j >> 1][(j & 1) * 2 + 1] };
                    if (FP16) mma_fp16(acc[f][j], ah, bp);
                    else      mma_bf16(acc[f][j], ah, bp);
                }
                if (TERMS == 3) {
                    #pragma unroll
                    for (int j = 0; j < 8; j++) {
                        uint32_t bp[2] = { bl[j >> 1][(j & 1) * 2],
                                           bl[j >> 1][(j & 1) * 2 + 1] };
                        if (FP16) mma_fp16(acc[f][j], ah, bp);
                        else      mma_bf16(acc[f][j], ah, bp);
                    }
                }
                #pragma unroll
                for (int j = 0; j < 8; j++) {
                    uint32_t bp[2] = { bh[j >> 1][(j & 1) * 2],
                                       bh[j >> 1][(j & 1) * 2 + 1] };
                    if (FP16) mma_fp16(acc[f][j], al, bp);
                    else      mma_bf16(acc[f][j], al, bp);
                }
            }
        }
    }

    const int erow = m0 + wm * 64 + (lane >> 2);
    const int ecol = n0 + wn * 64 + (lane & 3) * 2;
    if (Cf) {
        #pragma unroll
        for (int f = 0; f < 4; f++) {
            #pragma unroll
            for (int j = 0; j < 8; j++) {
                float* d0 = Cf + (size_t)(erow + f * 16)     * N + ecol + j * 8;
                float* d1 = Cf + (size_t)(erow + f * 16 + 8) * N + ecol + j * 8;
                *(float2*)d0 = make_float2(acc[f][j][0], acc[f][j][1]);
                *(float2*)d1 = make_float2(acc[f][j][2], acc[f][j][3]);
            }
        }
    } else if (n0 >= vstart) {
        // V section: fp16 hi only
        #pragma unroll
        for (int f = 0; f < 4; f++) {
            #pragma unroll
            for (int j = 0; j < 8; j++) {
                #pragma unroll
                for (int half = 0; half < 2; half++) {
                    size_t o = (size_t)(erow + f*16 + half*8) * N + ecol + j*8;
                    ushort2 hv = { to_h(acc[f][j][half*2]),
                                   to_h(acc[f][j][half*2 + 1]) };
                    *(ushort2*)(Ch + o) = hv;
                }
            }
        }
    } else {
        #pragma unroll
        for (int f = 0; f < 4; f++) {
            #pragma unroll
            for (int j = 0; j < 8; j++) {
                #pragma unroll
                for (int half = 0; half < 2; half++) {
                    size_t o = (size_t)(erow + f*16 + half*8) * N + ecol + j*8;
                    ushort2 hv, lv;
                    split_bf(acc[f][j][half*2],     hv.x, lv.x);
                    split_bf(acc[f][j][half*2 + 1], hv.y, lv.y);
                    *(ushort2*)(Ch + o) = hv;
                    *(ushort2*)(Cl + o) = lv;
                }
            }
        }
    }
#undef STAGE_COPY
}

// ---------------------------------------------------------------------------
// Kernel 4: flash attention. S = bf16 3-term; PV = fp16 2-term ((Ph+Pl)*Vh).
// BQ=128, 4 warps @ 32 q-rows. 2-stage KV ring {Kh,Kl,Vh}, Q separate.
// ---------------------------------------------------------------------------
#define AST   72                       // smem row stride (16-bit elems)
#define AKB   (64 * AST * 2)           // 9216 B per K/V array
#define AKVST (3 * AKB)                // 27648 B per stage {Kh,Kl,Vh}
#define AQB   (128 * AST * 2)          // 18432 B per Q array
#define ASMEM (2 * AKVST + 2 * AQB)    // 92160 B

__global__ __launch_bounds__(128, 2) void attn_mma_kernel(
    const us* __restrict__ qh_g, const us* __restrict__ ql_g,
    const float* __restrict__ mask,
    us* __restrict__ ctxh, us* __restrict__ ctxl)
{
    extern __shared__ char sma[];
    const uint32_t sb  = (uint32_t)__cvta_generic_to_shared(sma);
    const uint32_t uQh = sb + 2 * AKVST;
    const uint32_t uQl = uQh + AQB;

    const int tid = threadIdx.x, lane = tid & 31, wq = tid >> 5;
    const int qt = blockIdx.x, h = blockIdx.y, b = blockIdx.z;
    const int q0 = qt * 128;
    const size_t rowbase = (size_t)b * NSEQ;
    const size_t qkstride = 3 * INNER;

#define KV_COPY(st, kc)                                                        \
    do {                                                                       \
        uint32_t so = sb + (uint32_t)(st) * AKVST;                             \
        _Pragma("unroll")                                                      \
        for (int t = 0; t < 12; t++) {                                         \
            const int arr = t >> 2;   /* 0=Kh 1=Kl 2=Vh */                     \
            const int r = (t & 3) * 16 + (tid >> 3);                           \
            const int c = tid & 7;                                             \
            uint32_t d = so + (uint32_t)arr * AKB                              \
                       + (uint32_t)(r * AST + c * 8) * 2;                      \
            size_t col = ((arr < 2) ? INNER : 2*INNER) + h*DH + c*8;           \
            size_t g = (rowbase + (kc) + r) * qkstride + col;                  \
            const us* srcp = (arr == 1) ? (ql_g + g) : (qh_g + g);             \
            cp16(d, srcp);                                                     \
        }                                                                      \
    } while (0)

    // prologue: Q copy + KV stage 0
    {
        #pragma unroll
        for (int t = 0; t < 16; t++) {
            const int arr = t >> 3;
            const int r = (t & 7) * 16 + (tid >> 3);
            const int c = tid & 7;
            uint32_t d = uQh + (uint32_t)arr * AQB + (uint32_t)(r * AST + c * 8) * 2;
            size_t g = (rowbase + q0 + r) * qkstride + h * DH + c * 8;
            cp16(d, arr ? (ql_g + g) : (qh_g + g));
        }
    }
    KV_COPY(0, 0);
    asm volatile("cp.async.commit_group;" ::: "memory");

    float oacc[2][8][4];
    #pragma unroll
    for (int mf = 0; mf < 2; mf++)
        #pragma unroll
        for (int j = 0; j < 8; j++)
            #pragma unroll
            for (int e = 0; e < 4; e++) oacc[mf][j][e] = 0.f;
    float rmax[4] = {-1e30f, -1e30f, -1e30f, -1e30f};
    float rsum[4] = {0.f, 0.f, 0.f, 0.f};

    const uint32_t qoff0 = (uint32_t)((wq*32 + (lane & 15)) * AST
                           + (lane >> 4) * 8) * 2;
    const uint32_t koffb = (uint32_t)(((lane & 7) + ((lane >> 4) << 3)) * AST
                           + ((lane >> 3) & 1) * 8) * 2;
    const uint32_t voffb = (uint32_t)(((lane & 15)) * AST + (lane >> 4) * 8) * 2;

    const int nk = NSEQ / 64;   // 32
    for (int kt = 0; kt < nk; kt++) {
        const int st = kt & 1;
        asm volatile("cp.async.wait_group 0;" ::: "memory");
        __syncthreads();

        if (kt + 1 < nk) { KV_COPY(st ^ 1, (kt + 1) * 64); }
        asm volatile("cp.async.commit_group;" ::: "memory");

        const uint32_t so = sb + (uint32_t)st * AKVST;   // Kh base
        const uint32_t sV = so + 2 * AKB;

        // ---- S = Q K^T (bf16, 3-term), 2 m-frags per warp
        float sacc[2][8][4];
        #pragma unroll
        for (int mf = 0; mf < 2; mf++)
            #pragma unroll
            for (int j = 0; j < 8; j++)
                #pragma unroll
                for (int e = 0; e < 4; e++) sacc[mf][j][e] = 0.f;

        #pragma unroll
        for (int kk = 0; kk < 4; kk++) {
            uint32_t qh[2][4], ql[2][4];
            #pragma unroll
            for (int mf = 0; mf < 2; mf++) {
                uint32_t qo = (mf ? (uQh + (uint32_t)(16 * AST * 2)) : uQh)
                            + qoff0 + (uint32_t)(kk * 16) * 2;
                ldsm4(qh[mf], qo);
                ldsm4(ql[mf], qo + AQB);
            }
            #pragma unroll
            for (int jb = 0; jb < 4; jb++) {
                uint32_t kbh[4], kbl[4];
                uint32_t o = so + koffb + (uint32_t)(jb * 16 * AST + kk * 16) * 2;
                ldsm4(kbh, o);
                ldsm4(kbl, o + AKB);
                const int j0 = jb * 2, j1 = jb * 2 + 1;
                uint32_t bh0[2] = { kbh[0], kbh[1] }, bh1[2] = { kbh[2], kbh[3] };
                uint32_t bl0[2] = { kbl[0], kbl[1] }, bl1[2] = { kbl[2], kbl[3] };
                mma_bf16(sacc[0][j0], qh[0], bh0);
                mma_bf16(sacc[0][j1], qh[0], bh1);
                mma_bf16(sacc[1][j0], qh[1], bh0);
                mma_bf16(sacc[1][j1], qh[1], bh1);
                mma_bf16(sacc[0][j0], qh[0], bl0);
                mma_bf16(sacc[0][j1], qh[0], bl1);
                mma_bf16(sacc[1][j0], qh[1], bl0);
                mma_bf16(sacc[1][j1], qh[1], bl1);
                mma_bf16(sacc[0][j0], ql[0], bh0);
                mma_bf16(sacc[0][j1], ql[0], bh1);
                mma_bf16(sacc[1][j0], ql[1], bh0);
                mma_bf16(sacc[1][j1], ql[1], bh1);
            }
        }

        // ---- mask add (before scale), scale into exp2 domain; softmax per mf
        #pragma unroll
        for (int mf = 0; mf < 2; mf++) {
            const int qrow = q0 + wq * 32 + mf * 16 + (lane >> 2);
            const int kcol = kt * 64 + (lane & 3) * 2;
            const float* mg = mask + ((size_t)b * NSEQ + qrow) * NSEQ + kcol;
            #pragma unroll
            for (int j = 0; j < 8; j++) {
                float2 m0 = *(const float2*)(mg + j * 8);
                float2 m1 = *(const float2*)(mg + 8 * NSEQ + j * 8);
                sacc[mf][j][0] = (sacc[mf][j][0] + m0.x) * SC2;
                sacc[mf][j][1] = (sacc[mf][j][1] + m0.y) * SC2;
                sacc[mf][j][2] = (sacc[mf][j][2] + m1.x) * SC2;
                sacc[mf][j][3] = (sacc[mf][j][3] + m1.y) * SC2;
            }

            float tm0 = -1e30f, tm1 = -1e30f;
            #pragma unroll
            for (int j = 0; j < 8; j++) {
                tm0 = fmaxf(tm0, fmaxf(sacc[mf][j][0], sacc[mf][j][1]));
                tm1 = fmaxf(tm1, fmaxf(sacc[mf][j][2], sacc[mf][j][3]));
            }
            #pragma unroll
            for (int off = 1; off <= 2; off <<= 1) {
                tm0 = fmaxf(tm0, __shfl_xor_sync(0xffffffffu, tm0, off));
                tm1 = fmaxf(tm1, __shfl_xor_sync(0xffffffffu, tm1, off));
            }
            float nm0 = fmaxf(rmax[mf*2],   tm0);
            float nm1 = fmaxf(rmax[mf*2+1], tm1);
            float corr0 = ex2(rmax[mf*2]   - nm0);
            float corr1 = ex2(rmax[mf*2+1] - nm1);
            rmax[mf*2] = nm0; rmax[mf*2+1] = nm1;

            float ps0 = 0.f, ps1 = 0.f;
            #pragma unroll
            for (int j = 0; j < 8; j++) {
                sacc[mf][j][0] = ex2(sacc[mf][j][0] - nm0);
                sacc[mf][j][1] = ex2(sacc[mf][j][1] - nm0);
                sacc[mf][j][2] = ex2(sacc[mf][j][2] - nm1);
                sacc[mf][j][3] = ex2(sacc[mf][j][3] - nm1);
                ps0 += sacc[mf][j][0] + sacc[mf][j][1];
                ps1 += sacc[mf][j][2] + sacc[mf][j][3];
            }
            #pragma unroll
            for (int off = 1; off <= 2; off <<= 1) {
                ps0 += __shfl_xor_sync(0xffffffffu, ps0, off);
                ps1 += __shfl_xor_sync(0xffffffffu, ps1, off);
            }
            rsum[mf*2]   = rsum[mf*2]   * corr0 + ps0;
            rsum[mf*2+1] = rsum[mf*2+1] * corr1 + ps1;

            #pragma unroll
            for (int j = 0; j < 8; j++) {
                oacc[mf][j][0] *= corr0; oacc[mf][j][1] *= corr0;
                oacc[mf][j][2] *= corr1; oacc[mf][j][3] *= corr1;
            }
        }

        // ---- O += (Ph + Pl) Vh (fp16, 2-term)
        #pragma unroll
        for (int kp = 0; kp < 4; kp++) {
            uint32_t pah[2][4], pal[2][4];
            #pragma unroll
            for (int mf = 0; mf < 2; mf++) {
                const int j0 = kp * 2, j1 = kp * 2 + 1;
                float p00 = sacc[mf][j0][0], p01 = sacc[mf][j0][1];
                float p02 = sacc[mf][j0][2], p03 = sacc[mf][j0][3];
                float p10 = sacc[mf][j1][0], p11 = sacc[mf][j1][1];
                float p12 = sacc[mf][j1][2], p13 = sacc[mf][j1][3];
                pah[mf][0] = packh2(p00, p01);
                pah[mf][1] = packh2(p02, p03);
                pah[mf][2] = packh2(p10, p11);
                pah[mf][3] = packh2(p12, p13);
                __half2* hp;
                hp = (__half2*)&pah[mf][0];
                pal[mf][0] = packh2(p00 - __half2float(hp->x), p01 - __half2float(hp->y));
                hp = (__half2*)&pah[mf][1];
                pal[mf][1] = packh2(p02 - __half2float(hp->x), p03 - __half2float(hp->y));
                hp = (__half2*)&pah[mf][2];
                pal[mf][2] = packh2(p10 - __half2float(hp->x), p11 - __half2float(hp->y));
                hp = (__half2*)&pah[mf][3];
                pal[mf][3] = packh2(p12 - __half2float(hp->x), p13 - __half2float(hp->y));
            }
            #pragma unroll
            for (int db = 0; db < 4; db++) {
                uint32_t vbh[4];
                uint32_t o = sV + voffb + (uint32_t)(kp * 16 * AST + db * 16) * 2;
                ldsm4t(vbh, o);
                const int j0 = db * 2, j1 = db * 2 + 1;
                uint32_t bh0[2] = { vbh[0], vbh[1] }, bh1[2] = { vbh[2], vbh[3] };
                mma_fp16(oacc[0][j0], pah[0], bh0);
                mma_fp16(oacc[0][j1], pah[0], bh1);
                mma_fp16(oacc[1][j0], pah[1], bh0);
                mma_fp16(oacc[1][j1], pah[1], bh1);
                mma_fp16(oacc[0][j0], pal[0], bh0);
                mma_fp16(oacc[0][j1], pal[0], bh1);
                mma_fp16(oacc[1][j0], pal[1], bh0);
                mma_fp16(oacc[1][j1], pal[1], bh1);
            }
        }
    }
#undef KV_COPY

    // ---- normalize + write ctx (fp16 hi/lo)
    #pragma unroll
    for (int mf = 0; mf < 2; mf++) {
        const float inv0 = 1.0f / rsum[mf*2], inv1 = 1.0f / rsum[mf*2+1];
        const int row0 = q0 + wq * 32 + mf * 16 + (lane >> 2);
        #pragma unroll
        for (int j = 0; j < 8; j++) {
            const int col = h * DH + j * 8 + (lane & 3) * 2;
            float v0 = oacc[mf][j][0] * inv0, v1 = oacc[mf][j][1] * inv0;
            float v2 = oacc[mf][j][2] * inv1, v3 = oacc[mf][j][3] * inv1;
            ushort2 a0, b0, a1, b1;
            split_h(v0, a0.x, b0.x); split_h(v1, a0.y, b0.y);
            split_h(v2, a1.x, b1.x); split_h(v3, a1.y, b1.y);
            size_t o0 = (rowbase + row0)     * (size_t)INNER + col;
            size_t o1 = (rowbase + row0 + 8) * (size_t)INNER + col;
            *(ushort2*)(ctxh + o0) = a0;
            *(ushort2*)(ctxl + o0) = b0;
            *(ushort2*)(ctxh + o1) = a1;
            *(ushort2*)(ctxl + o1) = b1;
        }
    }
}

// ---------------------------------------------------------------------------
// launch
// ---------------------------------------------------------------------------
extern "C" void kernel_launch(void* const* d_in, const int* in_sizes, int n_in,
                              void* d_out, int out_size)
{
    const float* x     = (const float*)d_in[0];
    const float* m     = (const float*)d_in[1];
    const float* gamma = (const float*)d_in[2];
    const float* beta  = (const float*)d_in[3];
    const float* Wqkv  = (const float*)d_in[4];
    const float* Wout  = (const float*)d_in[5];
    float* out = (float*)d_out;

    us *xnh, *xnl, *wqh, *wql, *woh, *qkvh, *qkvl, *ctxh, *ctxl;
    cudaGetSymbolAddress((void**)&xnh,  g_xn_h);
    cudaGetSymbolAddress((void**)&xnl,  g_xn_l);
    cudaGetSymbolAddress((void**)&wqh,  g_wq_h);
    cudaGetSymbolAddress((void**)&wql,  g_wq_l);
    cudaGetSymbolAddress((void**)&woh,  g_wo_h);
    cudaGetSymbolAddress((void**)&qkvh, g_qkv_h);
    cudaGetSymbolAddress((void**)&qkvl, g_qkv_l);
    cudaGetSymbolAddress((void**)&ctxh, g_ctx_h);
    cudaGetSymbolAddress((void**)&ctxl, g_ctx_l);

    cudaFuncSetAttribute(mma_gemm<3,false>,
                         cudaFuncAttributeMaxDynamicSharedMemorySize, GSMEM);
    cudaFuncSetAttribute(mma_gemm<2,true>,
                         cudaFuncAttributeMaxDynamicSharedMemorySize, GSMEM);
    cudaFuncSetAttribute(attn_mma_kernel,
                         cudaFuncAttributeMaxDynamicSharedMemorySize, ASMEM);

    // 1. LayerNorm (+ bf16 split)
    ln_kernel<<<NROWS, 256>>>(x, gamma, beta, xnh, xnl);

    // 2. weight transpose + split (Wqkv: bf16 h/l; Wout: fp16 hi only)
    splitT_kernel<<<dim3(3*INNER/32, DMODEL/32), dim3(32,8)>>>(
        Wqkv, wqh, wql, DMODEL, 3*INNER, 0);
    splitT_kernel<<<dim3(DMODEL/32,  INNER/32),  dim3(32,8)>>>(
        Wout, woh, nullptr, INNER, DMODEL, 1);

    // 3. QKV projection (bf16 3-term); V column block written as fp16
    mma_gemm<3,false><<<dim3(3*INNER/128, NROWS/128), 128, GSMEM>>>(
        xnh, xnl, wqh, wql, nullptr, qkvh, qkvl, 3*INNER, 2*INNER);

    // 4. masked flash attention (S bf16 3-term, PV fp16 2-term)
    attn_mma_kernel<<<dim3(NSEQ/128, HEADS, BATCH), 128, ASMEM>>>(
        qkvh, qkvl, m, ctxh, ctxl);

    // 5. output projection (fp16 2-term) -> fp32 out
    mma_gemm<2,true><<<dim3(DMODEL/128, NROWS/128), 128, GSMEM>>>(
        ctxh, ctxl, woh, woh, out, nullptr, nullptr, DMODEL, 1 << 30);
}

// round 15
// speedup vs baseline: 1.4303x; 1.0919x over previous
#include <cuda_runtime.h>
#include <cuda_bf16.h>
#include <cuda_fp16.h>
#include <math.h>
#include <stdint.h>

// ---------------------------------------------------------------------------
// Problem constants
// ---------------------------------------------------------------------------
#define BATCH   2
#define NSEQ    2048
#define DMODEL  1024
#define HEADS   16
#define DH      64
#define INNER   1024
#define NROWS   (BATCH*NSEQ)   // 4096
#define SCALE   0.125f
#define SC2     (0.125f * 1.4426950408889634f)   // SCALE * log2(e)
#define LN_EPS  1e-5f

typedef unsigned short us;

// ---------------------------------------------------------------------------
// Scratch (__device__ globals; no allocs allowed). Raw 16-bit storage:
// xn fp16 h/l; Wqkv fp16 hi; Q,K bf16 h/l; V fp16; ctx fp16 h/l; Wout fp16 hi.
// ---------------------------------------------------------------------------
__device__ us g_xn_h [(size_t)NROWS * DMODEL];
__device__ us g_xn_l [(size_t)NROWS * DMODEL];
__device__ us g_wq_h [(size_t)3*INNER * DMODEL];   // Wqkv^T (fp16 hi)
__device__ us g_wo_h [(size_t)DMODEL * INNER];     // Wout^T (fp16 hi)
__device__ us g_qkv_h[(size_t)NROWS * 3 * INNER];  // Q,K bf16-hi | V fp16
__device__ us g_qkv_l[(size_t)NROWS * 3 * INNER];  // Q,K bf16-lo | unused V
__device__ us g_ctx_h[(size_t)NROWS * INNER];      // fp16 hi
__device__ us g_ctx_l[(size_t)NROWS * INNER];      // fp16 lo

// ---------------------------------------------------------------------------
// Helpers
// ---------------------------------------------------------------------------
__device__ __forceinline__ void split_bf(float v, us& h, us& l) {
    __nv_bfloat16 hb = __float2bfloat16(v);
    __nv_bfloat16 lb = __float2bfloat16(v - __bfloat162float(hb));
    h = *(us*)&hb; l = *(us*)&lb;
}
__device__ __forceinline__ void split_h(float v, us& h, us& l) {
    __half hh = __float2half_rn(v);
    __half lh = __float2half_rn(v - __half2float(hh));
    h = *(us*)&hh; l = *(us*)&lh;
}
__device__ __forceinline__ us to_h(float v) {
    __half hh = __float2half_rn(v);
    return *(us*)&hh;
}
__device__ __forceinline__ float ex2(float x) {
    float y;
    asm("ex2.approx.ftz.f32 %0, %1;" : "=f"(y) : "f"(x));
    return y;
}
__device__ __forceinline__ void ldsm4(uint32_t* r, uint32_t addr) {
    asm volatile("ldmatrix.sync.aligned.m8n8.x4.shared.b16 {%0,%1,%2,%3}, [%4];"
                 : "=r"(r[0]), "=r"(r[1]), "=r"(r[2]), "=r"(r[3]) : "r"(addr));
}
__device__ __forceinline__ void ldsm4t(uint32_t* r, uint32_t addr) {
    asm volatile("ldmatrix.sync.aligned.m8n8.x4.trans.shared.b16 {%0,%1,%2,%3}, [%4];"
                 : "=r"(r[0]), "=r"(r[1]), "=r"(r[2]), "=r"(r[3]) : "r"(addr));
}
__device__ __forceinline__ void mma_bf16(float* d, const uint32_t* a,
                                         const uint32_t* b) {
    asm volatile(
        "mma.sync.aligned.m16n8k16.row.col.f32.bf16.bf16.f32 "
        "{%0,%1,%2,%3}, {%4,%5,%6,%7}, {%8,%9}, {%0,%1,%2,%3};"
        : "+f"(d[0]), "+f"(d[1]), "+f"(d[2]), "+f"(d[3])
        : "r"(a[0]), "r"(a[1]), "r"(a[2]), "r"(a[3]), "r"(b[0]), "r"(b[1]));
}
__device__ __forceinline__ void mma_fp16(float* d, const uint32_t* a,
                                         const uint32_t* b) {
    asm volatile(
        "mma.sync.aligned.m16n8k16.row.col.f32.f16.f16.f32 "
        "{%0,%1,%2,%3}, {%4,%5,%6,%7}, {%8,%9}, {%0,%1,%2,%3};"
        : "+f"(d[0]), "+f"(d[1]), "+f"(d[2]), "+f"(d[3])
        : "r"(a[0]), "r"(a[1]), "r"(a[2]), "r"(a[3]), "r"(b[0]), "r"(b[1]));
}
__device__ __forceinline__ void cp16(uint32_t dst, const void* src) {
    asm volatile("cp.async.cg.shared.global [%0], [%1], 16;"
                 :: "r"(dst), "l"(__cvta_generic_to_global(src)));
}
__device__ __forceinline__ uint32_t packh2(float a, float b) {
    __half2 t = __floats2half2_rn(a, b);
    return *(uint32_t*)&t;
}

// ---------------------------------------------------------------------------
// Kernel 1: LayerNorm fused with fp16 hi/lo split output
// ---------------------------------------------------------------------------
__global__ __launch_bounds__(256) void ln_kernel(
    const float* __restrict__ x, const float* __restrict__ gamma,
    const float* __restrict__ beta,
    us* __restrict__ xh, us* __restrict__ xl)
{
    int row = blockIdx.x;
    int tid = threadIdx.x;
    const float4* xr = (const float4*)(x + (size_t)row * DMODEL);
    float4 v = xr[tid];

    float s  = v.x + v.y + v.z + v.w;
    float ss = v.x*v.x + v.y*v.y + v.z*v.z + v.w*v.w;
    #pragma unroll
    for (int off = 16; off; off >>= 1) {
        s  += __shfl_xor_sync(0xffffffffu, s,  off);
        ss += __shfl_xor_sync(0xffffffffu, ss, off);
    }
    __shared__ float sbuf[8], ssbuf[8];
    int warp = tid >> 5, lane = tid & 31;
    if (lane == 0) { sbuf[warp] = s; ssbuf[warp] = ss; }
    __syncthreads();
    s = 0.f; ss = 0.f;
    #pragma unroll
    for (int w = 0; w < 8; w++) { s += sbuf[w]; ss += ssbuf[w]; }

    float mu  = s * (1.0f / DMODEL);
    float var = ss * (1.0f / DMODEL) - mu * mu;
    float inv = rsqrtf(var + LN_EPS);

    float4 g  = ((const float4*)gamma)[tid];
    float4 be = ((const float4*)beta)[tid];
    float o[4];
    o[0] = (v.x - mu) * inv * g.x + be.x;
    o[1] = (v.y - mu) * inv * g.y + be.y;
    o[2] = (v.z - mu) * inv * g.z + be.z;
    o[3] = (v.w - mu) * inv * g.w + be.w;

    ushort4 hv, lv;
    split_h(o[0], hv.x, lv.x); split_h(o[1], hv.y, lv.y);
    split_h(o[2], hv.z, lv.z); split_h(o[3], hv.w, lv.w);
    size_t off = (size_t)row * DMODEL + tid * 4;
    *(ushort4*)(xh + off) = hv;
    *(ushort4*)(xl + off) = lv;
}

// ---------------------------------------------------------------------------
// Kernel 2: transpose + fp16-hi for weights
// ---------------------------------------------------------------------------
__global__ __launch_bounds__(256) void splitT_kernel(
    const float* __restrict__ W, us* __restrict__ Th, int K, int N)
{
    __shared__ float t[32][33];
    int n0 = blockIdx.x * 32, k0 = blockIdx.y * 32;
    int tx = threadIdx.x, ty = threadIdx.y;
    #pragma unroll
    for (int j = 0; j < 4; j++) {
        int r = ty + j * 8;
        t[r][tx] = W[(size_t)(k0 + r) * N + n0 + tx];
    }
    __syncthreads();
    #pragma unroll
    for (int j = 0; j < 4; j++) {
        int r = ty + j * 8;
        Th[(size_t)(n0 + r) * K + k0 + tx] = to_h(t[tx][r]);
    }
}

// ---------------------------------------------------------------------------
// Kernel 3: fp16 2-term GEMM on mma.sync: C = (Ah+Al) @ Bh^T, fp32 acc.
// 128x128 block, 4 warps @ 64x64; 3-stage pipeline; 2 CTAs/SM.
// Epilogue: fp32 (Cf) | bf16 h/l | fp16 hi for column blocks >= vstart.
// ---------------------------------------------------------------------------
#define GK    1024
#define GBK   32
#define GARR  (128 * 64)              // 8192 B per array
#define GBLK  (3 * GARR)              // 24576 B per stage {Ah,Al,Bh}
#define GSMEM (3 * GBLK)              // 73728 B

__global__ __launch_bounds__(128, 2) void mma_gemm(
    const us* __restrict__ Ah, const us* __restrict__ Al,
    const us* __restrict__ Bh,
    float* __restrict__ Cf, us* __restrict__ Ch, us* __restrict__ Cl,
    int N, int vstart)
{
    extern __shared__ char smg[];
    const uint32_t sb = (uint32_t)__cvta_generic_to_shared(smg);

    const int tid  = threadIdx.x;
    const int lane = tid & 31, wid = tid >> 5;
    const int wm = wid >> 1, wn = wid & 1;
    const int m0 = blockIdx.y * 128, n0 = blockIdx.x * 128;

    float acc[4][8][4];
    #pragma unroll
    for (int f = 0; f < 4; f++)
        #pragma unroll
        for (int j = 0; j < 8; j++)
            #pragma unroll
            for (int e = 0; e < 4; e++) acc[f][j][e] = 0.f;

    const int arow = wm * 64 + (lane & 15);
    const uint32_t abase = (uint32_t)(arow * 64);
    const uint32_t axor  = (uint32_t)(((arow >> 1) & 3) << 4);
    const uint32_t achk  = (uint32_t)(lane >> 4);

    const int brow = wn * 64 + (lane & 7) + ((lane >> 4) << 3);
    const uint32_t bbase = (uint32_t)(brow * 64);
    const uint32_t bxor  = (uint32_t)(((brow >> 1) & 3) << 4);
    const uint32_t bchk  = (uint32_t)((lane >> 3) & 1);

#define STAGE_COPY(st, kc)                                                     \
    do {                                                                       \
        uint32_t so = sb + (uint32_t)(st) * GBLK;                              \
        _Pragma("unroll")                                                      \
        for (int t = 0; t < 12; t++) {                                         \
            const int arr = t >> 2;       /* 0=Ah 1=Al 2=Bh */                 \
            const int r = (t & 3) * 32 + (tid >> 2);                           \
            const int c = tid & 3;                                             \
            uint32_t d = so + (uint32_t)arr * GARR                             \
                       + (uint32_t)(r * 64 + ((c ^ ((r >> 1) & 3)) << 4));     \
            const us* srcp =                                                   \
                (arr == 0) ? (Ah + (size_t)(m0 + r) * GK + (kc) + c * 8) :     \
                (arr == 1) ? (Al + (size_t)(m0 + r) * GK + (kc) + c * 8) :     \
                             (Bh + (size_t)(n0 + r) * GK + (kc) + c * 8);      \
            cp16(d, srcp);                                                     \
        }                                                                      \
    } while (0)

    STAGE_COPY(0, 0);
    asm volatile("cp.async.commit_group;" ::: "memory");
    STAGE_COPY(1, GBK);
    asm volatile("cp.async.commit_group;" ::: "memory");

    const int nk = GK / GBK;
    for (int kt = 0; kt < nk; kt++) {
        const int st = kt % 3;
        asm volatile("cp.async.wait_group 1;" ::: "memory");
        __syncthreads();

        if (kt + 2 < nk) { STAGE_COPY((kt + 2) % 3, (kt + 2) * GBK); }
        asm volatile("cp.async.commit_group;" ::: "memory");

        const uint32_t so = sb + (uint32_t)st * GBLK;
        #pragma unroll
        for (int ks = 0; ks < 2; ks++) {
            uint32_t bh[4][4];
            #pragma unroll
            for (int nb = 0; nb < 4; nb++) {
                uint32_t o = so + 2*GARR + bbase + (uint32_t)(nb * 16 * 64)
                           + ((((bchk + ks*2)) << 4) ^ bxor);
                ldsm4(bh[nb], o);
            }
            #pragma unroll
            for (int f = 0; f < 4; f++) {
                uint32_t ah[4], al[4];
                uint32_t o = so + abase + (uint32_t)(f * 16 * 64)
                           + ((((achk + ks*2)) << 4) ^ axor);
                ldsm4(ah, o);
                ldsm4(al, o + GARR);
                #pragma unroll
                for (int j = 0; j < 8; j++) {
                    uint32_t bp[2] = { bh[j >> 1][(j & 1) * 2],
                                       bh[j >> 1][(j & 1) * 2 + 1] };
                    mma_fp16(acc[f][j], ah, bp);
                }
                #pragma unroll
                for (int j = 0; j < 8; j++) {
                    uint32_t bp[2] = { bh[j >> 1][(j & 1) * 2],
                                       bh[j >> 1][(j & 1) * 2 + 1] };
                    mma_fp16(acc[f][j], al, bp);
                }
            }
        }
    }

    const int erow = m0 + wm * 64 + (lane >> 2);
    const int ecol = n0 + wn * 64 + (lane & 3) * 2;
    if (Cf) {
        #pragma unroll
        for (int f = 0; f < 4; f++) {
            #pragma unroll
            for (int j = 0; j < 8; j++) {
                float* d0 = Cf + (size_t)(erow + f * 16)     * N + ecol + j * 8;
                float* d1 = Cf + (size_t)(erow + f * 16 + 8) * N + ecol + j * 8;
                *(float2*)d0 = make_float2(acc[f][j][0], acc[f][j][1]);
                *(float2*)d1 = make_float2(acc[f][j][2], acc[f][j][3]);
            }
        }
    } else if (n0 >= vstart) {
        // V section: fp16 hi only
        #pragma unroll
        for (int f = 0; f < 4; f++) {
            #pragma unroll
            for (int j = 0; j < 8; j++) {
                #pragma unroll
                for (int half = 0; half < 2; half++) {
                    size_t o = (size_t)(erow + f*16 + half*8) * N + ecol + j*8;
                    ushort2 hv = { to_h(acc[f][j][half*2]),
                                   to_h(acc[f][j][half*2 + 1]) };
                    *(ushort2*)(Ch + o) = hv;
                }
            }
        }
    } else {
        // Q,K section: bf16 hi/lo
        #pragma unroll
        for (int f = 0; f < 4; f++) {
            #pragma unroll
            for (int j = 0; j < 8; j++) {
                #pragma unroll
                for (int half = 0; half < 2; half++) {
                    size_t o = (size_t)(erow + f*16 + half*8) * N + ecol + j*8;
                    ushort2 hv, lv;
                    split_bf(acc[f][j][half*2],     hv.x, lv.x);
                    split_bf(acc[f][j][half*2 + 1], hv.y, lv.y);
                    *(ushort2*)(Ch + o) = hv;
                    *(ushort2*)(Cl + o) = lv;
                }
            }
        }
    }
#undef STAGE_COPY
}

// ---------------------------------------------------------------------------
// Kernel 4: flash attention. S = bf16 3-term; PV = fp16 2-term ((Ph+Pl)*Vh).
// BQ=128, 4 warps @ 32 q-rows. 2-stage KV ring {Kh,Kl,Vh}, Q separate.
// ---------------------------------------------------------------------------
#define AST   72                       // smem row stride (16-bit elems)
#define AKB   (64 * AST * 2)           // 9216 B per K/V array
#define AKVST (3 * AKB)                // 27648 B per stage {Kh,Kl,Vh}
#define AQB   (128 * AST * 2)          // 18432 B per Q array
#define ASMEM (2 * AKVST + 2 * AQB)    // 92160 B

__global__ __launch_bounds__(128, 2) void attn_mma_kernel(
    const us* __restrict__ qh_g, const us* __restrict__ ql_g,
    const float* __restrict__ mask,
    us* __restrict__ ctxh, us* __restrict__ ctxl)
{
    extern __shared__ char sma[];
    const uint32_t sb  = (uint32_t)__cvta_generic_to_shared(sma);
    const uint32_t uQh = sb + 2 * AKVST;
    const uint32_t uQl = uQh + AQB;

    const int tid = threadIdx.x, lane = tid & 31, wq = tid >> 5;
    const int qt = blockIdx.x, h = blockIdx.y, b = blockIdx.z;
    const int q0 = qt * 128;
    const size_t rowbase = (size_t)b * NSEQ;
    const size_t qkstride = 3 * INNER;

#define KV_COPY(st, kc)                                                        \
    do {                                                                       \
        uint32_t so = sb + (uint32_t)(st) * AKVST;                             \
        _Pragma("unroll")                                                      \
        for (int t = 0; t < 12; t++) {                                         \
            const int arr = t >> 2;   /* 0=Kh 1=Kl 2=Vh */                     \
            const int r = (t & 3) * 16 + (tid >> 3);                           \
            const int c = tid & 7;                                             \
            uint32_t d = so + (uint32_t)arr * AKB                              \
                       + (uint32_t)(r * AST + c * 8) * 2;                      \
            size_t col = ((arr < 2) ? INNER : 2*INNER) + h*DH + c*8;           \
            size_t g = (rowbase + (kc) + r) * qkstride + col;                  \
            const us* srcp = (arr == 1) ? (ql_g + g) : (qh_g + g);             \
            cp16(d, srcp);                                                     \
        }                                                                      \
    } while (0)

    // prologue: Q copy + KV stage 0
    {
        #pragma unroll
        for (int t = 0; t < 16; t++) {
            const int arr = t >> 3;
            const int r = (t & 7) * 16 + (tid >> 3);
            const int c = tid & 7;
            uint32_t d = uQh + (uint32_t)arr * AQB + (uint32_t)(r * AST + c * 8) * 2;
            size_t g = (rowbase + q0 + r) * qkstride + h * DH + c * 8;
            cp16(d, arr ? (ql_g + g) : (qh_g + g));
        }
    }
    KV_COPY(0, 0);
    asm volatile("cp.async.commit_group;" ::: "memory");

    float oacc[2][8][4];
    #pragma unroll
    for (int mf = 0; mf < 2; mf++)
        #pragma unroll
        for (int j = 0; j < 8; j++)
            #pragma unroll
            for (int e = 0; e < 4; e++) oacc[mf][j][e] = 0.f;
    float rmax[4] = {-1e30f, -1e30f, -1e30f, -1e30f};
    float rsum[4] = {0.f, 0.f, 0.f, 0.f};

    const uint32_t qoff0 = (uint32_t)((wq*32 + (lane & 15)) * AST
                           + (lane >> 4) * 8) * 2;
    const uint32_t koffb = (uint32_t)(((lane & 7) + ((lane >> 4) << 3)) * AST
                           + ((lane >> 3) & 1) * 8) * 2;
    const uint32_t voffb = (uint32_t)(((lane & 15)) * AST + (lane >> 4) * 8) * 2;

    const int nk = NSEQ / 64;   // 32
    for (int kt = 0; kt < nk; kt++) {
        const int st = kt & 1;
        asm volatile("cp.async.wait_group 0;" ::: "memory");
        __syncthreads();

        if (kt + 1 < nk) { KV_COPY(st ^ 1, (kt + 1) * 64); }
        asm volatile("cp.async.commit_group;" ::: "memory");

        const uint32_t so = sb + (uint32_t)st * AKVST;   // Kh base
        const uint32_t sV = so + 2 * AKB;

        // ---- S = Q K^T (bf16, 3-term), 2 m-frags per warp
        float sacc[2][8][4];
        #pragma unroll
        for (int mf = 0; mf < 2; mf++)
            #pragma unroll
            for (int j = 0; j < 8; j++)
                #pragma unroll
                for (int e = 0; e < 4; e++) sacc[mf][j][e] = 0.f;

        #pragma unroll
        for (int kk = 0; kk < 4; kk++) {
            uint32_t qh[2][4], ql[2][4];
            #pragma unroll
            for (int mf = 0; mf < 2; mf++) {
                uint32_t qo = (mf ? (uQh + (uint32_t)(16 * AST * 2)) : uQh)
                            + qoff0 + (uint32_t)(kk * 16) * 2;
                ldsm4(qh[mf], qo);
                ldsm4(ql[mf], qo + AQB);
            }
            #pragma unroll
            for (int jb = 0; jb < 4; jb++) {
                uint32_t kbh[4], kbl[4];
                uint32_t o = so + koffb + (uint32_t)(jb * 16 * AST + kk * 16) * 2;
                ldsm4(kbh, o);
                ldsm4(kbl, o + AKB);
                const int j0 = jb * 2, j1 = jb * 2 + 1;
                uint32_t bh0[2] = { kbh[0], kbh[1] }, bh1[2] = { kbh[2], kbh[3] };
                uint32_t bl0[2] = { kbl[0], kbl[1] }, bl1[2] = { kbl[2], kbl[3] };
                mma_bf16(sacc[0][j0], qh[0], bh0);
                mma_bf16(sacc[0][j1], qh[0], bh1);
                mma_bf16(sacc[1][j0], qh[1], bh0);
                mma_bf16(sacc[1][j1], qh[1], bh1);
                mma_bf16(sacc[0][j0], qh[0], bl0);
                mma_bf16(sacc[0][j1], qh[0], bl1);
                mma_bf16(sacc[1][j0], qh[1], bl0);
                mma_bf16(sacc[1][j1], qh[1], bl1);
                mma_bf16(sacc[0][j0], ql[0], bh0);
                mma_bf16(sacc[0][j1], ql[0], bh1);
                mma_bf16(sacc[1][j0], ql[1], bh0);
                mma_bf16(sacc[1][j1], ql[1], bh1);
            }
        }

        // ---- mask add (before scale), scale into exp2 domain; softmax per mf
        #pragma unroll
        for (int mf = 0; mf < 2; mf++) {
            const int qrow = q0 + wq * 32 + mf * 16 + (lane >> 2);
            const int kcol = kt * 64 + (lane & 3) * 2;
            const float* mg = mask + ((size_t)b * NSEQ + qrow) * NSEQ + kcol;
            #pragma unroll
            for (int j = 0; j < 8; j++) {
                float2 m0 = *(const float2*)(mg + j * 8);
                float2 m1 = *(const float2*)(mg + 8 * NSEQ + j * 8);
                sacc[mf][j][0] = (sacc[mf][j][0] + m0.x) * SC2;
                sacc[mf][j][1] = (sacc[mf][j][1] + m0.y) * SC2;
                sacc[mf][j][2] = (sacc[mf][j][2] + m1.x) * SC2;
                sacc[mf][j][3] = (sacc[mf][j][3] + m1.y) * SC2;
            }

            float tm0 = -1e30f, tm1 = -1e30f;
            #pragma unroll
            for (int j = 0; j < 8; j++) {
                tm0 = fmaxf(tm0, fmaxf(sacc[mf][j][0], sacc[mf][j][1]));
                tm1 = fmaxf(tm1, fmaxf(sacc[mf][j][2], sacc[mf][j][3]));
            }
            #pragma unroll
            for (int off = 1; off <= 2; off <<= 1) {
                tm0 = fmaxf(tm0, __shfl_xor_sync(0xffffffffu, tm0, off));
                tm1 = fmaxf(tm1, __shfl_xor_sync(0xffffffffu, tm1, off));
            }
            float nm0 = fmaxf(rmax[mf*2],   tm0);
            float nm1 = fmaxf(rmax[mf*2+1], tm1);
            float corr0 = ex2(rmax[mf*2]   - nm0);
            float corr1 = ex2(rmax[mf*2+1] - nm1);
            rmax[mf*2] = nm0; rmax[mf*2+1] = nm1;

            float ps0 = 0.f, ps1 = 0.f;
            #pragma unroll
            for (int j = 0; j < 8; j++) {
                sacc[mf][j][0] = ex2(sacc[mf][j][0] - nm0);
                sacc[mf][j][1] = ex2(sacc[mf][j][1] - nm0);
                sacc[mf][j][2] = ex2(sacc[mf][j][2] - nm1);
                sacc[mf][j][3] = ex2(sacc[mf][j][3] - nm1);
                ps0 += sacc[mf][j][0] + sacc[mf][j][1];
                ps1 += sacc[mf][j][2] + sacc[mf][j][3];
            }
            #pragma unroll
            for (int off = 1; off <= 2; off <<= 1) {
                ps0 += __shfl_xor_sync(0xffffffffu, ps0, off);
                ps1 += __shfl_xor_sync(0xffffffffu, ps1, off);
            }
            rsum[mf*2]   = rsum[mf*2]   * corr0 + ps0;
            rsum[mf*2+1] = rsum[mf*2+1] * corr1 + ps1;

            #pragma unroll
            for (int j = 0; j < 8; j++) {
                oacc[mf][j][0] *= corr0; oacc[mf][j][1] *= corr0;
                oacc[mf][j][2] *= corr1; oacc[mf][j][3] *= corr1;
            }
        }

        // ---- O += (Ph + Pl) Vh (fp16, 2-term)
        #pragma unroll
        for (int kp = 0; kp < 4; kp++) {
            uint32_t pah[2][4], pal[2][4];
            #pragma unroll
            for (int mf = 0; mf < 2; mf++) {
                const int j0 = kp * 2, j1 = kp * 2 + 1;
                float p00 = sacc[mf][j0][0], p01 = sacc[mf][j0][1];
                float p02 = sacc[mf][j0][2], p03 = sacc[mf][j0][3];
                float p10 = sacc[mf][j1][0], p11 = sacc[mf][j1][1];
                float p12 = sacc[mf][j1][2], p13 = sacc[mf][j1][3];
                pah[mf][0] = packh2(p00, p01);
                pah[mf][1] = packh2(p02, p03);
                pah[mf][2] = packh2(p10, p11);
                pah[mf][3] = packh2(p12, p13);
                __half2* hp;
                hp = (__half2*)&pah[mf][0];
                pal[mf][0] = packh2(p00 - __half2float(hp->x), p01 - __half2float(hp->y));
                hp = (__half2*)&pah[mf][1];
                pal[mf][1] = packh2(p02 - __half2float(hp->x), p03 - __half2float(hp->y));
                hp = (__half2*)&pah[mf][2];
                pal[mf][2] = packh2(p10 - __half2float(hp->x), p11 - __half2float(hp->y));
                hp = (__half2*)&pah[mf][3];
                pal[mf][3] = packh2(p12 - __half2float(hp->x), p13 - __half2float(hp->y));
            }
            #pragma unroll
            for (int db = 0; db < 4; db++) {
                uint32_t vbh[4];
                uint32_t o = sV + voffb + (uint32_t)(kp * 16 * AST + db * 16) * 2;
                ldsm4t(vbh, o);
                const int j0 = db * 2, j1 = db * 2 + 1;
                uint32_t bh0[2] = { vbh[0], vbh[1] }, bh1[2] = { vbh[2], vbh[3] };
                mma_fp16(oacc[0][j0], pah[0], bh0);
                mma_fp16(oacc[0][j1], pah[0], bh1);
                mma_fp16(oacc[1][j0], pah[1], bh0);
                mma_fp16(oacc[1][j1], pah[1], bh1);
                mma_fp16(oacc[0][j0], pal[0], bh0);
                mma_fp16(oacc[0][j1], pal[0], bh1);
                mma_fp16(oacc[1][j0], pal[1], bh0);
                mma_fp16(oacc[1][j1], pal[1], bh1);
            }
        }
    }
#undef KV_COPY

    // ---- normalize + write ctx (fp16 hi/lo)
    #pragma unroll
    for (int mf = 0; mf < 2; mf++) {
        const float inv0 = 1.0f / rsum[mf*2], inv1 = 1.0f / rsum[mf*2+1];
        const int row0 = q0 + wq * 32 + mf * 16 + (lane >> 2);
        #pragma unroll
        for (int j = 0; j < 8; j++) {
            const int col = h * DH + j * 8 + (lane & 3) * 2;
            float v0 = oacc[mf][j][0] * inv0, v1 = oacc[mf][j][1] * inv0;
            float v2 = oacc[mf][j][2] * inv1, v3 = oacc[mf][j][3] * inv1;
            ushort2 a0, b0, a1, b1;
            split_h(v0, a0.x, b0.x); split_h(v1, a0.y, b0.y);
            split_h(v2, a1.x, b1.x); split_h(v3, a1.y, b1.y);
            size_t o0 = (rowbase + row0)     * (size_t)INNER + col;
            size_t o1 = (rowbase + row0 + 8) * (size_t)INNER + col;
            *(ushort2*)(ctxh + o0) = a0;
            *(ushort2*)(ctxl + o0) = b0;
            *(ushort2*)(ctxh + o1) = a1;
            *(ushort2*)(ctxl + o1) = b1;
        }
    }
}

// ---------------------------------------------------------------------------
// launch
// ---------------------------------------------------------------------------
extern "C" void kernel_launch(void* const* d_in, const int* in_sizes, int n_in,
                              void* d_out, int out_size)
{
    const float* x     = (const float*)d_in[0];
    const float* m     = (const float*)d_in[1];
    const float* gamma = (const float*)d_in[2];
    const float* beta  = (const float*)d_in[3];
    const float* Wqkv  = (const float*)d_in[4];
    const float* Wout  = (const float*)d_in[5];
    float* out = (float*)d_out;

    us *xnh, *xnl, *wqh, *woh, *qkvh, *qkvl, *ctxh, *ctxl;
    cudaGetSymbolAddress((void**)&xnh,  g_xn_h);
    cudaGetSymbolAddress((void**)&xnl,  g_xn_l);
    cudaGetSymbolAddress((void**)&wqh,  g_wq_h);
    cudaGetSymbolAddress((void**)&woh,  g_wo_h);
    cudaGetSymbolAddress((void**)&qkvh, g_qkv_h);
    cudaGetSymbolAddress((void**)&qkvl, g_qkv_l);
    cudaGetSymbolAddress((void**)&ctxh, g_ctx_h);
    cudaGetSymbolAddress((void**)&ctxl, g_ctx_l);

    cudaFuncSetAttribute(mma_gemm,
                         cudaFuncAttributeMaxDynamicSharedMemorySize, GSMEM);
    cudaFuncSetAttribute(attn_mma_kernel,
                         cudaFuncAttributeMaxDynamicSharedMemorySize, ASMEM);

    // 1. LayerNorm (+ fp16 split)
    ln_kernel<<<NROWS, 256>>>(x, gamma, beta, xnh, xnl);

    // 2. weight transpose (fp16 hi only for both)
    splitT_kernel<<<dim3(3*INNER/32, DMODEL/32), dim3(32,8)>>>(
        Wqkv, wqh, DMODEL, 3*INNER);
    splitT_kernel<<<dim3(DMODEL/32,  INNER/32),  dim3(32,8)>>>(
        Wout, woh, INNER, DMODEL);

    // 3. QKV projection (fp16 2-term); Q,K -> bf16 h/l, V -> fp16
    mma_gemm<<<dim3(3*INNER/128, NROWS/128), 128, GSMEM>>>(
        xnh, xnl, wqh, nullptr, qkvh, qkvl, 3*INNER, 2*INNER);

    // 4. masked flash attention (S bf16 3-term, PV fp16 2-term)
    attn_mma_kernel<<<dim3(NSEQ/128, HEADS, BATCH), 128, ASMEM>>>(
        qkvh, qkvl, m, ctxh, ctxl);

    // 5. output projection (fp16 2-term) -> fp32 out
    mma_gemm<<<dim3(DMODEL/128, NROWS/128), 128, GSMEM>>>(
        ctxh, ctxl, woh, out, nullptr, nullptr, DMODEL, 1 << 30);
}

// round 16
// speedup vs baseline: 1.5063x; 1.0532x over previous
#include <cuda_runtime.h>
#include <cuda_bf16.h>
#include <cuda_fp16.h>
#include <math.h>
#include <stdint.h>

// ---------------------------------------------------------------------------
// Problem constants
// ---------------------------------------------------------------------------
#define BATCH   2
#define NSEQ    2048
#define DMODEL  1024
#define HEADS   16
#define DH      64
#define INNER   1024
#define NROWS   (BATCH*NSEQ)   // 4096
#define SCALE   0.125f
#define SC2     (0.125f * 1.4426950408889634f)   // SCALE * log2(e)
#define LN_EPS  1e-5f

typedef unsigned short us;

// ---------------------------------------------------------------------------
// Scratch (__device__ globals). Raw 16-bit storage, all fp16 now:
// xn h/l; Wqkv hi; Q,K h/l; V hi; ctx h/l; Wout hi.
// ---------------------------------------------------------------------------
__device__ us g_xn_h [(size_t)NROWS * DMODEL];
__device__ us g_xn_l [(size_t)NROWS * DMODEL];
__device__ us g_wq_h [(size_t)3*INNER * DMODEL];   // Wqkv^T (fp16 hi)
__device__ us g_wo_h [(size_t)DMODEL * INNER];     // Wout^T (fp16 hi)
__device__ us g_qkv_h[(size_t)NROWS * 3 * INNER];  // Q,K,V fp16 hi
__device__ us g_qkv_l[(size_t)NROWS * 3 * INNER];  // Q,K fp16 lo (V unused)
__device__ us g_ctx_h[(size_t)NROWS * INNER];      // fp16 hi
__device__ us g_ctx_l[(size_t)NROWS * INNER];      // fp16 lo

// ---------------------------------------------------------------------------
// Helpers
// ---------------------------------------------------------------------------
__device__ __forceinline__ void split_h(float v, us& h, us& l) {
    __half hh = __float2half_rn(v);
    __half lh = __float2half_rn(v - __half2float(hh));
    h = *(us*)&hh; l = *(us*)&lh;
}
__device__ __forceinline__ us to_h(float v) {
    __half hh = __float2half_rn(v);
    return *(us*)&hh;
}
__device__ __forceinline__ float ex2(float x) {
    float y;
    asm("ex2.approx.ftz.f32 %0, %1;" : "=f"(y) : "f"(x));
    return y;
}
__device__ __forceinline__ void ldsm4(uint32_t* r, uint32_t addr) {
    asm volatile("ldmatrix.sync.aligned.m8n8.x4.shared.b16 {%0,%1,%2,%3}, [%4];"
                 : "=r"(r[0]), "=r"(r[1]), "=r"(r[2]), "=r"(r[3]) : "r"(addr));
}
__device__ __forceinline__ void ldsm4t(uint32_t* r, uint32_t addr) {
    asm volatile("ldmatrix.sync.aligned.m8n8.x4.trans.shared.b16 {%0,%1,%2,%3}, [%4];"
                 : "=r"(r[0]), "=r"(r[1]), "=r"(r[2]), "=r"(r[3]) : "r"(addr));
}
__device__ __forceinline__ void mma_fp16(float* d, const uint32_t* a,
                                         const uint32_t* b) {
    asm volatile(
        "mma.sync.aligned.m16n8k16.row.col.f32.f16.f16.f32 "
        "{%0,%1,%2,%3}, {%4,%5,%6,%7}, {%8,%9}, {%0,%1,%2,%3};"
        : "+f"(d[0]), "+f"(d[1]), "+f"(d[2]), "+f"(d[3])
        : "r"(a[0]), "r"(a[1]), "r"(a[2]), "r"(a[3]), "r"(b[0]), "r"(b[1]));
}
__device__ __forceinline__ void cp16(uint32_t dst, const void* src) {
    asm volatile("cp.async.cg.shared.global [%0], [%1], 16;"
                 :: "r"(dst), "l"(__cvta_generic_to_global(src)));
}
__device__ __forceinline__ uint32_t packh2(float a, float b) {
    __half2 t = __floats2half2_rn(a, b);
    return *(uint32_t*)&t;
}

// ---------------------------------------------------------------------------
// Kernel 1: LayerNorm fused with fp16 hi/lo split output
// ---------------------------------------------------------------------------
__global__ __launch_bounds__(256) void ln_kernel(
    const float* __restrict__ x, const float* __restrict__ gamma,
    const float* __restrict__ beta,
    us* __restrict__ xh, us* __restrict__ xl)
{
    int row = blockIdx.x;
    int tid = threadIdx.x;
    const float4* xr = (const float4*)(x + (size_t)row * DMODEL);
    float4 v = xr[tid];

    float s  = v.x + v.y + v.z + v.w;
    float ss = v.x*v.x + v.y*v.y + v.z*v.z + v.w*v.w;
    #pragma unroll
    for (int off = 16; off; off >>= 1) {
        s  += __shfl_xor_sync(0xffffffffu, s,  off);
        ss += __shfl_xor_sync(0xffffffffu, ss, off);
    }
    __shared__ float sbuf[8], ssbuf[8];
    int warp = tid >> 5, lane = tid & 31;
    if (lane == 0) { sbuf[warp] = s; ssbuf[warp] = ss; }
    __syncthreads();
    s = 0.f; ss = 0.f;
    #pragma unroll
    for (int w = 0; w < 8; w++) { s += sbuf[w]; ss += ssbuf[w]; }

    float mu  = s * (1.0f / DMODEL);
    float var = ss * (1.0f / DMODEL) - mu * mu;
    float inv = rsqrtf(var + LN_EPS);

    float4 g  = ((const float4*)gamma)[tid];
    float4 be = ((const float4*)beta)[tid];
    float o[4];
    o[0] = (v.x - mu) * inv * g.x + be.x;
    o[1] = (v.y - mu) * inv * g.y + be.y;
    o[2] = (v.z - mu) * inv * g.z + be.z;
    o[3] = (v.w - mu) * inv * g.w + be.w;

    ushort4 hv, lv;
    split_h(o[0], hv.x, lv.x); split_h(o[1], hv.y, lv.y);
    split_h(o[2], hv.z, lv.z); split_h(o[3], hv.w, lv.w);
    size_t off = (size_t)row * DMODEL + tid * 4;
    *(ushort4*)(xh + off) = hv;
    *(ushort4*)(xl + off) = lv;
}

// ---------------------------------------------------------------------------
// Kernel 2: transpose + fp16-hi for weights
// ---------------------------------------------------------------------------
__global__ __launch_bounds__(256) void splitT_kernel(
    const float* __restrict__ W, us* __restrict__ Th, int K, int N)
{
    __shared__ float t[32][33];
    int n0 = blockIdx.x * 32, k0 = blockIdx.y * 32;
    int tx = threadIdx.x, ty = threadIdx.y;
    #pragma unroll
    for (int j = 0; j < 4; j++) {
        int r = ty + j * 8;
        t[r][tx] = W[(size_t)(k0 + r) * N + n0 + tx];
    }
    __syncthreads();
    #pragma unroll
    for (int j = 0; j < 4; j++) {
        int r = ty + j * 8;
        Th[(size_t)(n0 + r) * K + k0 + tx] = to_h(t[tx][r]);
    }
}

// ---------------------------------------------------------------------------
// Kernel 3: fp16 2-term GEMM: C = (Ah+Al) @ Bh^T, fp32 acc.
// 128x128 block, 4 warps @ 64x64; 3-stage pipeline; 2 CTAs/SM.
// Epilogue: fp32 (Cf) | fp16 h/l | fp16 hi only for columns >= vstart (V).
// ---------------------------------------------------------------------------
#define GK    1024
#define GBK   32
#define GARR  (128 * 64)              // 8192 B per array
#define GBLK  (3 * GARR)              // 24576 B per stage {Ah,Al,Bh}
#define GSMEM (3 * GBLK)              // 73728 B

__global__ __launch_bounds__(128, 2) void mma_gemm(
    const us* __restrict__ Ah, const us* __restrict__ Al,
    const us* __restrict__ Bh,
    float* __restrict__ Cf, us* __restrict__ Ch, us* __restrict__ Cl,
    int N, int vstart)
{
    extern __shared__ char smg[];
    const uint32_t sb = (uint32_t)__cvta_generic_to_shared(smg);

    const int tid  = threadIdx.x;
    const int lane = tid & 31, wid = tid >> 5;
    const int wm = wid >> 1, wn = wid & 1;
    const int m0 = blockIdx.y * 128, n0 = blockIdx.x * 128;

    float acc[4][8][4];
    #pragma unroll
    for (int f = 0; f < 4; f++)
        #pragma unroll
        for (int j = 0; j < 8; j++)
            #pragma unroll
            for (int e = 0; e < 4; e++) acc[f][j][e] = 0.f;

    const int arow = wm * 64 + (lane & 15);
    const uint32_t abase = (uint32_t)(arow * 64);
    const uint32_t axor  = (uint32_t)(((arow >> 1) & 3) << 4);
    const uint32_t achk  = (uint32_t)(lane >> 4);

    const int brow = wn * 64 + (lane & 7) + ((lane >> 4) << 3);
    const uint32_t bbase = (uint32_t)(brow * 64);
    const uint32_t bxor  = (uint32_t)(((brow >> 1) & 3) << 4);
    const uint32_t bchk  = (uint32_t)((lane >> 3) & 1);

#define STAGE_COPY(st, kc)                                                     \
    do {                                                                       \
        uint32_t so = sb + (uint32_t)(st) * GBLK;                              \
        _Pragma("unroll")                                                      \
        for (int t = 0; t < 12; t++) {                                         \
            const int arr = t >> 2;       /* 0=Ah 1=Al 2=Bh */                 \
            const int r = (t & 3) * 32 + (tid >> 2);                           \
            const int c = tid & 3;                                             \
            uint32_t d = so + (uint32_t)arr * GARR                             \
                       + (uint32_t)(r * 64 + ((c ^ ((r >> 1) & 3)) << 4));     \
            const us* srcp =                                                   \
                (arr == 0) ? (Ah + (size_t)(m0 + r) * GK + (kc) + c * 8) :     \
                (arr == 1) ? (Al + (size_t)(m0 + r) * GK + (kc) + c * 8) :     \
                             (Bh + (size_t)(n0 + r) * GK + (kc) + c * 8);      \
            cp16(d, srcp);                                                     \
        }                                                                      \
    } while (0)

    STAGE_COPY(0, 0);
    asm volatile("cp.async.commit_group;" ::: "memory");
    STAGE_COPY(1, GBK);
    asm volatile("cp.async.commit_group;" ::: "memory");

    const int nk = GK / GBK;
    for (int kt = 0; kt < nk; kt++) {
        const int st = kt % 3;
        asm volatile("cp.async.wait_group 1;" ::: "memory");
        __syncthreads();

        if (kt + 2 < nk) { STAGE_COPY((kt + 2) % 3, (kt + 2) * GBK); }
        asm volatile("cp.async.commit_group;" ::: "memory");

        const uint32_t so = sb + (uint32_t)st * GBLK;
        #pragma unroll
        for (int ks = 0; ks < 2; ks++) {
            uint32_t bh[4][4];
            #pragma unroll
            for (int nb = 0; nb < 4; nb++) {
                uint32_t o = so + 2*GARR + bbase + (uint32_t)(nb * 16 * 64)
                           + ((((bchk + ks*2)) << 4) ^ bxor);
                ldsm4(bh[nb], o);
            }
            #pragma unroll
            for (int f = 0; f < 4; f++) {
                uint32_t ah[4], al[4];
                uint32_t o = so + abase + (uint32_t)(f * 16 * 64)
                           + ((((achk + ks*2)) << 4) ^ axor);
                ldsm4(ah, o);
                ldsm4(al, o + GARR);
                #pragma unroll
                for (int j = 0; j < 8; j++) {
                    uint32_t bp[2] = { bh[j >> 1][(j & 1) * 2],
                                       bh[j >> 1][(j & 1) * 2 + 1] };
                    mma_fp16(acc[f][j], ah, bp);
                }
                #pragma unroll
                for (int j = 0; j < 8; j++) {
                    uint32_t bp[2] = { bh[j >> 1][(j & 1) * 2],
                                       bh[j >> 1][(j & 1) * 2 + 1] };
                    mma_fp16(acc[f][j], al, bp);
                }
            }
        }
    }

    const int erow = m0 + wm * 64 + (lane >> 2);
    const int ecol = n0 + wn * 64 + (lane & 3) * 2;
    if (Cf) {
        #pragma unroll
        for (int f = 0; f < 4; f++) {
            #pragma unroll
            for (int j = 0; j < 8; j++) {
                float* d0 = Cf + (size_t)(erow + f * 16)     * N + ecol + j * 8;
                float* d1 = Cf + (size_t)(erow + f * 16 + 8) * N + ecol + j * 8;
                *(float2*)d0 = make_float2(acc[f][j][0], acc[f][j][1]);
                *(float2*)d1 = make_float2(acc[f][j][2], acc[f][j][3]);
            }
        }
    } else if (n0 >= vstart) {
        // V section: fp16 hi only
        #pragma unroll
        for (int f = 0; f < 4; f++) {
            #pragma unroll
            for (int j = 0; j < 8; j++) {
                #pragma unroll
                for (int half = 0; half < 2; half++) {
                    size_t o = (size_t)(erow + f*16 + half*8) * N + ecol + j*8;
                    ushort2 hv = { to_h(acc[f][j][half*2]),
                                   to_h(acc[f][j][half*2 + 1]) };
                    *(ushort2*)(Ch + o) = hv;
                }
            }
        }
    } else {
        // Q,K section: fp16 hi/lo
        #pragma unroll
        for (int f = 0; f < 4; f++) {
            #pragma unroll
            for (int j = 0; j < 8; j++) {
                #pragma unroll
                for (int half = 0; half < 2; half++) {
                    size_t o = (size_t)(erow + f*16 + half*8) * N + ecol + j*8;
                    ushort2 hv, lv;
                    split_h(acc[f][j][half*2],     hv.x, lv.x);
                    split_h(acc[f][j][half*2 + 1], hv.y, lv.y);
                    *(ushort2*)(Ch + o) = hv;
                    *(ushort2*)(Cl + o) = lv;
                }
            }
        }
    }
#undef STAGE_COPY
}

// ---------------------------------------------------------------------------
// Kernel 4: flash attention, all fp16 2-term:
// S = (Qh+Ql) Kh^T ; PV = (Ph+Pl) Vh. KV stage = {Kh, Vh} only.
// BQ=128, 4 warps @ 32 q-rows; 2-stage KV ring; Q separate; 2 CTAs/SM.
// ---------------------------------------------------------------------------
#define AST   72                       // smem row stride (16-bit elems)
#define AKB   (64 * AST * 2)           // 9216 B per K/V array
#define AKVST (2 * AKB)                // 18432 B per stage {Kh,Vh}
#define AQB   (128 * AST * 2)          // 18432 B per Q array
#define ASMEM (2 * AKVST + 2 * AQB)    // 73728 B

__global__ __launch_bounds__(128, 2) void attn_mma_kernel(
    const us* __restrict__ qh_g, const us* __restrict__ ql_g,
    const float* __restrict__ mask,
    us* __restrict__ ctxh, us* __restrict__ ctxl)
{
    extern __shared__ char sma[];
    const uint32_t sb  = (uint32_t)__cvta_generic_to_shared(sma);
    const uint32_t uQh = sb + 2 * AKVST;
    const uint32_t uQl = uQh + AQB;

    const int tid = threadIdx.x, lane = tid & 31, wq = tid >> 5;
    const int qt = blockIdx.x, h = blockIdx.y, b = blockIdx.z;
    const int q0 = qt * 128;
    const size_t rowbase = (size_t)b * NSEQ;
    const size_t qkstride = 3 * INNER;

#define KV_COPY(st, kc)                                                        \
    do {                                                                       \
        uint32_t so = sb + (uint32_t)(st) * AKVST;                             \
        _Pragma("unroll")                                                      \
        for (int t = 0; t < 8; t++) {                                          \
            const int arr = t >> 2;   /* 0=Kh 1=Vh */                          \
            const int r = (t & 3) * 16 + (tid >> 3);                           \
            const int c = tid & 7;                                             \
            uint32_t d = so + (uint32_t)arr * AKB                              \
                       + (uint32_t)(r * AST + c * 8) * 2;                      \
            size_t col = ((arr == 0) ? INNER : 2*INNER) + h*DH + c*8;          \
            size_t g = (rowbase + (kc) + r) * qkstride + col;                  \
            cp16(d, qh_g + g);                                                 \
        }                                                                      \
    } while (0)

    // prologue: Q copy (h + l) + KV stage 0
    {
        #pragma unroll
        for (int t = 0; t < 16; t++) {
            const int arr = t >> 3;
            const int r = (t & 7) * 16 + (tid >> 3);
            const int c = tid & 7;
            uint32_t d = uQh + (uint32_t)arr * AQB + (uint32_t)(r * AST + c * 8) * 2;
            size_t g = (rowbase + q0 + r) * qkstride + h * DH + c * 8;
            cp16(d, arr ? (ql_g + g) : (qh_g + g));
        }
    }
    KV_COPY(0, 0);
    asm volatile("cp.async.commit_group;" ::: "memory");

    float oacc[2][8][4];
    #pragma unroll
    for (int mf = 0; mf < 2; mf++)
        #pragma unroll
        for (int j = 0; j < 8; j++)
            #pragma unroll
            for (int e = 0; e < 4; e++) oacc[mf][j][e] = 0.f;
    float rmax[4] = {-1e30f, -1e30f, -1e30f, -1e30f};
    float rsum[4] = {0.f, 0.f, 0.f, 0.f};

    const uint32_t qoff0 = (uint32_t)((wq*32 + (lane & 15)) * AST
                           + (lane >> 4) * 8) * 2;
    const uint32_t koffb = (uint32_t)(((lane & 7) + ((lane >> 4) << 3)) * AST
                           + ((lane >> 3) & 1) * 8) * 2;
    const uint32_t voffb = (uint32_t)(((lane & 15)) * AST + (lane >> 4) * 8) * 2;

    const int nk = NSEQ / 64;   // 32
    for (int kt = 0; kt < nk; kt++) {
        const int st = kt & 1;
        asm volatile("cp.async.wait_group 0;" ::: "memory");
        __syncthreads();

        if (kt + 1 < nk) { KV_COPY(st ^ 1, (kt + 1) * 64); }
        asm volatile("cp.async.commit_group;" ::: "memory");

        const uint32_t so = sb + (uint32_t)st * AKVST;   // Kh base
        const uint32_t sV = so + AKB;

        // ---- S = (Qh+Ql) Kh^T (fp16, 2-term), 2 m-frags per warp
        float sacc[2][8][4];
        #pragma unroll
        for (int mf = 0; mf < 2; mf++)
            #pragma unroll
            for (int j = 0; j < 8; j++)
                #pragma unroll
                for (int e = 0; e < 4; e++) sacc[mf][j][e] = 0.f;

        #pragma unroll
        for (int kk = 0; kk < 4; kk++) {
            uint32_t qh[2][4], ql[2][4];
            #pragma unroll
            for (int mf = 0; mf < 2; mf++) {
                uint32_t qo = (mf ? (uQh + (uint32_t)(16 * AST * 2)) : uQh)
                            + qoff0 + (uint32_t)(kk * 16) * 2;
                ldsm4(qh[mf], qo);
                ldsm4(ql[mf], qo + AQB);
            }
            #pragma unroll
            for (int jb = 0; jb < 4; jb++) {
                uint32_t kbh[4];
                uint32_t o = so + koffb + (uint32_t)(jb * 16 * AST + kk * 16) * 2;
                ldsm4(kbh, o);
                const int j0 = jb * 2, j1 = jb * 2 + 1;
                uint32_t bh0[2] = { kbh[0], kbh[1] }, bh1[2] = { kbh[2], kbh[3] };
                mma_fp16(sacc[0][j0], qh[0], bh0);
                mma_fp16(sacc[0][j1], qh[0], bh1);
                mma_fp16(sacc[1][j0], qh[1], bh0);
                mma_fp16(sacc[1][j1], qh[1], bh1);
                mma_fp16(sacc[0][j0], ql[0], bh0);
                mma_fp16(sacc[0][j1], ql[0], bh1);
                mma_fp16(sacc[1][j0], ql[1], bh0);
                mma_fp16(sacc[1][j1], ql[1], bh1);
            }
        }

        // ---- mask add (before scale), scale into exp2 domain; softmax per mf
        #pragma unroll
        for (int mf = 0; mf < 2; mf++) {
            const int qrow = q0 + wq * 32 + mf * 16 + (lane >> 2);
            const int kcol = kt * 64 + (lane & 3) * 2;
            const float* mg = mask + ((size_t)b * NSEQ + qrow) * NSEQ + kcol;
            #pragma unroll
            for (int j = 0; j < 8; j++) {
                float2 m0 = *(const float2*)(mg + j * 8);
                float2 m1 = *(const float2*)(mg + 8 * NSEQ + j * 8);
                sacc[mf][j][0] = (sacc[mf][j][0] + m0.x) * SC2;
                sacc[mf][j][1] = (sacc[mf][j][1] + m0.y) * SC2;
                sacc[mf][j][2] = (sacc[mf][j][2] + m1.x) * SC2;
                sacc[mf][j][3] = (sacc[mf][j][3] + m1.y) * SC2;
            }

            float tm0 = -1e30f, tm1 = -1e30f;
            #pragma unroll
            for (int j = 0; j < 8; j++) {
                tm0 = fmaxf(tm0, fmaxf(sacc[mf][j][0], sacc[mf][j][1]));
                tm1 = fmaxf(tm1, fmaxf(sacc[mf][j][2], sacc[mf][j][3]));
            }
            #pragma unroll
            for (int off = 1; off <= 2; off <<= 1) {
                tm0 = fmaxf(tm0, __shfl_xor_sync(0xffffffffu, tm0, off));
                tm1 = fmaxf(tm1, __shfl_xor_sync(0xffffffffu, tm1, off));
            }
            float nm0 = fmaxf(rmax[mf*2],   tm0);
            float nm1 = fmaxf(rmax[mf*2+1], tm1);
            float corr0 = ex2(rmax[mf*2]   - nm0);
            float corr1 = ex2(rmax[mf*2+1] - nm1);
            rmax[mf*2] = nm0; rmax[mf*2+1] = nm1;

            float ps0 = 0.f, ps1 = 0.f;
            #pragma unroll
            for (int j = 0; j < 8; j++) {
                sacc[mf][j][0] = ex2(sacc[mf][j][0] - nm0);
                sacc[mf][j][1] = ex2(sacc[mf][j][1] - nm0);
                sacc[mf][j][2] = ex2(sacc[mf][j][2] - nm1);
                sacc[mf][j][3] = ex2(sacc[mf][j][3] - nm1);
                ps0 += sacc[mf][j][0] + sacc[mf][j][1];
                ps1 += sacc[mf][j][2] + sacc[mf][j][3];
            }
            #pragma unroll
            for (int off = 1; off <= 2; off <<= 1) {
                ps0 += __shfl_xor_sync(0xffffffffu, ps0, off);
                ps1 += __shfl_xor_sync(0xffffffffu, ps1, off);
            }
            rsum[mf*2]   = rsum[mf*2]   * corr0 + ps0;
            rsum[mf*2+1] = rsum[mf*2+1] * corr1 + ps1;

            #pragma unroll
            for (int j = 0; j < 8; j++) {
                oacc[mf][j][0] *= corr0; oacc[mf][j][1] *= corr0;
                oacc[mf][j][2] *= corr1; oacc[mf][j][3] *= corr1;
            }
        }

        // ---- O += (Ph + Pl) Vh (fp16, 2-term)
        #pragma unroll
        for (int kp = 0; kp < 4; kp++) {
            uint32_t pah[2][4], pal[2][4];
            #pragma unroll
            for (int mf = 0; mf < 2; mf++) {
                const int j0 = kp * 2, j1 = kp * 2 + 1;
                float p00 = sacc[mf][j0][0], p01 = sacc[mf][j0][1];
                float p02 = sacc[mf][j0][2], p03 = sacc[mf][j0][3];
                float p10 = sacc[mf][j1][0], p11 = sacc[mf][j1][1];
                float p12 = sacc[mf][j1][2], p13 = sacc[mf][j1][3];
                pah[mf][0] = packh2(p00, p01);
                pah[mf][1] = packh2(p02, p03);
                pah[mf][2] = packh2(p10, p11);
                pah[mf][3] = packh2(p12, p13);
                __half2* hp;
                hp = (__half2*)&pah[mf][0];
                pal[mf][0] = packh2(p00 - __half2float(hp->x), p01 - __half2float(hp->y));
                hp = (__half2*)&pah[mf][1];
                pal[mf][1] = packh2(p02 - __half2float(hp->x), p03 - __half2float(hp->y));
                hp = (__half2*)&pah[mf][2];
                pal[mf][2] = packh2(p10 - __half2float(hp->x), p11 - __half2float(hp->y));
                hp = (__half2*)&pah[mf][3];
                pal[mf][3] = packh2(p12 - __half2float(hp->x), p13 - __half2float(hp->y));
            }
            #pragma unroll
            for (int db = 0; db < 4; db++) {
                uint32_t vbh[4];
                uint32_t o = sV + voffb + (uint32_t)(kp * 16 * AST + db * 16) * 2;
                ldsm4t(vbh, o);
                const int j0 = db * 2, j1 = db * 2 + 1;
                uint32_t bh0[2] = { vbh[0], vbh[1] }, bh1[2] = { vbh[2], vbh[3] };
                mma_fp16(oacc[0][j0], pah[0], bh0);
                mma_fp16(oacc[0][j1], pah[0], bh1);
                mma_fp16(oacc[1][j0], pah[1], bh0);
                mma_fp16(oacc[1][j1], pah[1], bh1);
                mma_fp16(oacc[0][j0], pal[0], bh0);
                mma_fp16(oacc[0][j1], pal[0], bh1);
                mma_fp16(oacc[1][j0], pal[1], bh0);
                mma_fp16(oacc[1][j1], pal[1], bh1);
            }
        }
    }
#undef KV_COPY

    // ---- normalize + write ctx (fp16 hi/lo)
    #pragma unroll
    for (int mf = 0; mf < 2; mf++) {
        const float inv0 = 1.0f / rsum[mf*2], inv1 = 1.0f / rsum[mf*2+1];
        const int row0 = q0 + wq * 32 + mf * 16 + (lane >> 2);
        #pragma unroll
        for (int j = 0; j < 8; j++) {
            const int col = h * DH + j * 8 + (lane & 3) * 2;
            float v0 = oacc[mf][j][0] * inv0, v1 = oacc[mf][j][1] * inv0;
            float v2 = oacc[mf][j][2] * inv1, v3 = oacc[mf][j][3] * inv1;
            ushort2 a0, b0, a1, b1;
            split_h(v0, a0.x, b0.x); split_h(v1, a0.y, b0.y);
            split_h(v2, a1.x, b1.x); split_h(v3, a1.y, b1.y);
            size_t o0 = (rowbase + row0)     * (size_t)INNER + col;
            size_t o1 = (rowbase + row0 + 8) * (size_t)INNER + col;
            *(ushort2*)(ctxh + o0) = a0;
            *(ushort2*)(ctxl + o0) = b0;
            *(ushort2*)(ctxh + o1) = a1;
            *(ushort2*)(ctxl + o1) = b1;
        }
    }
}

// ---------------------------------------------------------------------------
// launch
// ---------------------------------------------------------------------------
extern "C" void kernel_launch(void* const* d_in, const int* in_sizes, int n_in,
                              void* d_out, int out_size)
{
    const float* x     = (const float*)d_in[0];
    const float* m     = (const float*)d_in[1];
    const float* gamma = (const float*)d_in[2];
    const float* beta  = (const float*)d_in[3];
    const float* Wqkv  = (const float*)d_in[4];
    const float* Wout  = (const float*)d_in[5];
    float* out = (float*)d_out;

    us *xnh, *xnl, *wqh, *woh, *qkvh, *qkvl, *ctxh, *ctxl;
    cudaGetSymbolAddress((void**)&xnh,  g_xn_h);
    cudaGetSymbolAddress((void**)&xnl,  g_xn_l);
    cudaGetSymbolAddress((void**)&wqh,  g_wq_h);
    cudaGetSymbolAddress((void**)&woh,  g_wo_h);
    cudaGetSymbolAddress((void**)&qkvh, g_qkv_h);
    cudaGetSymbolAddress((void**)&qkvl, g_qkv_l);
    cudaGetSymbolAddress((void**)&ctxh, g_ctx_h);
    cudaGetSymbolAddress((void**)&ctxl, g_ctx_l);

    cudaFuncSetAttribute(mma_gemm,
                         cudaFuncAttributeMaxDynamicSharedMemorySize, GSMEM);
    cudaFuncSetAttribute(attn_mma_kernel,
                         cudaFuncAttributeMaxDynamicSharedMemorySize, ASMEM);

    // 1. LayerNorm (+ fp16 split)
    ln_kernel<<<NROWS, 256>>>(x, gamma, beta, xnh, xnl);

    // 2. weight transpose (fp16 hi only)
    splitT_kernel<<<dim3(3*INNER/32, DMODEL/32), dim3(32,8)>>>(
        Wqkv, wqh, DMODEL, 3*INNER);
    splitT_kernel<<<dim3(DMODEL/32,  INNER/32),  dim3(32,8)>>>(
        Wout, woh, INNER, DMODEL);

    // 3. QKV projection (fp16 2-term); Q,K -> fp16 h/l, V -> fp16 hi
    mma_gemm<<<dim3(3*INNER/128, NROWS/128), 128, GSMEM>>>(
        xnh, xnl, wqh, nullptr, qkvh, qkvl, 3*INNER, 2*INNER);

    // 4. masked flash attention (all fp16 2-term)
    attn_mma_kernel<<<dim3(NSEQ/128, HEADS, BATCH), 128, ASMEM>>>(
        qkvh, qkvl, m, ctxh, ctxl);

    // 5. output projection (fp16 2-term) -> fp32 out
    mma_gemm<<<dim3(DMODEL/128, NROWS/128), 128, GSMEM>>>(
        ctxh, ctxl, woh, out, nullptr, nullptr, DMODEL, 1 << 30);
}

// round 17
// speedup vs baseline: 1.5147x; 1.0055x over previous
#include <cuda_runtime.h>
#include <cuda_bf16.h>
#include <cuda_fp16.h>
#include <math.h>
#include <stdint.h>

// ---------------------------------------------------------------------------
// Problem constants
// ---------------------------------------------------------------------------
#define BATCH   2
#define NSEQ    2048
#define DMODEL  1024
#define HEADS   16
#define DH      64
#define INNER   1024
#define NROWS   (BATCH*NSEQ)   // 4096
#define SCALE   0.125f
#define SC2     (0.125f * 1.4426950408889634f)   // SCALE * log2(e)
#define LN_EPS  1e-5f

typedef unsigned short us;

// ---------------------------------------------------------------------------
// Scratch (__device__ globals). Raw 16-bit storage, all fp16:
// xn h/l; Wqkv hi; Q,K h/l; V hi; ctx h/l; Wout hi.
// ---------------------------------------------------------------------------
__device__ us g_xn_h [(size_t)NROWS * DMODEL];
__device__ us g_xn_l [(size_t)NROWS * DMODEL];
__device__ us g_wq_h [(size_t)3*INNER * DMODEL];   // Wqkv^T (fp16 hi)
__device__ us g_wo_h [(size_t)DMODEL * INNER];     // Wout^T (fp16 hi)
__device__ us g_qkv_h[(size_t)NROWS * 3 * INNER];  // Q,K,V fp16 hi
__device__ us g_qkv_l[(size_t)NROWS * 3 * INNER];  // Q,K fp16 lo (V unused)
__device__ us g_ctx_h[(size_t)NROWS * INNER];      // fp16 hi
__device__ us g_ctx_l[(size_t)NROWS * INNER];      // fp16 lo

// ---------------------------------------------------------------------------
// Helpers
// ---------------------------------------------------------------------------
__device__ __forceinline__ void split_h(float v, us& h, us& l) {
    __half hh = __float2half_rn(v);
    __half lh = __float2half_rn(v - __half2float(hh));
    h = *(us*)&hh; l = *(us*)&lh;
}
__device__ __forceinline__ us to_h(float v) {
    __half hh = __float2half_rn(v);
    return *(us*)&hh;
}
__device__ __forceinline__ float ex2(float x) {
    float y;
    asm("ex2.approx.ftz.f32 %0, %1;" : "=f"(y) : "f"(x));
    return y;
}
__device__ __forceinline__ void ldsm4(uint32_t* r, uint32_t addr) {
    asm volatile("ldmatrix.sync.aligned.m8n8.x4.shared.b16 {%0,%1,%2,%3}, [%4];"
                 : "=r"(r[0]), "=r"(r[1]), "=r"(r[2]), "=r"(r[3]) : "r"(addr));
}
__device__ __forceinline__ void ldsm4t(uint32_t* r, uint32_t addr) {
    asm volatile("ldmatrix.sync.aligned.m8n8.x4.trans.shared.b16 {%0,%1,%2,%3}, [%4];"
                 : "=r"(r[0]), "=r"(r[1]), "=r"(r[2]), "=r"(r[3]) : "r"(addr));
}
__device__ __forceinline__ void mma_fp16(float* d, const uint32_t* a,
                                         const uint32_t* b) {
    asm volatile(
        "mma.sync.aligned.m16n8k16.row.col.f32.f16.f16.f32 "
        "{%0,%1,%2,%3}, {%4,%5,%6,%7}, {%8,%9}, {%0,%1,%2,%3};"
        : "+f"(d[0]), "+f"(d[1]), "+f"(d[2]), "+f"(d[3])
        : "r"(a[0]), "r"(a[1]), "r"(a[2]), "r"(a[3]), "r"(b[0]), "r"(b[1]));
}
__device__ __forceinline__ void cp16(uint32_t dst, const void* src) {
    asm volatile("cp.async.cg.shared.global [%0], [%1], 16;"
                 :: "r"(dst), "l"(__cvta_generic_to_global(src)));
}
__device__ __forceinline__ uint32_t packh2(float a, float b) {
    __half2 t = __floats2half2_rn(a, b);
    return *(uint32_t*)&t;
}

// ---------------------------------------------------------------------------
// Kernel 1: LayerNorm fused with fp16 hi/lo split output
// ---------------------------------------------------------------------------
__global__ __launch_bounds__(256) void ln_kernel(
    const float* __restrict__ x, const float* __restrict__ gamma,
    const float* __restrict__ beta,
    us* __restrict__ xh, us* __restrict__ xl)
{
    int row = blockIdx.x;
    int tid = threadIdx.x;
    const float4* xr = (const float4*)(x + (size_t)row * DMODEL);
    float4 v = xr[tid];

    float s  = v.x + v.y + v.z + v.w;
    float ss = v.x*v.x + v.y*v.y + v.z*v.z + v.w*v.w;
    #pragma unroll
    for (int off = 16; off; off >>= 1) {
        s  += __shfl_xor_sync(0xffffffffu, s,  off);
        ss += __shfl_xor_sync(0xffffffffu, ss, off);
    }
    __shared__ float sbuf[8], ssbuf[8];
    int warp = tid >> 5, lane = tid & 31;
    if (lane == 0) { sbuf[warp] = s; ssbuf[warp] = ss; }
    __syncthreads();
    s = 0.f; ss = 0.f;
    #pragma unroll
    for (int w = 0; w < 8; w++) { s += sbuf[w]; ss += ssbuf[w]; }

    float mu  = s * (1.0f / DMODEL);
    float var = ss * (1.0f / DMODEL) - mu * mu;
    float inv = rsqrtf(var + LN_EPS);

    float4 g  = ((const float4*)gamma)[tid];
    float4 be = ((const float4*)beta)[tid];
    float o[4];
    o[0] = (v.x - mu) * inv * g.x + be.x;
    o[1] = (v.y - mu) * inv * g.y + be.y;
    o[2] = (v.z - mu) * inv * g.z + be.z;
    o[3] = (v.w - mu) * inv * g.w + be.w;

    ushort4 hv, lv;
    split_h(o[0], hv.x, lv.x); split_h(o[1], hv.y, lv.y);
    split_h(o[2], hv.z, lv.z); split_h(o[3], hv.w, lv.w);
    size_t off = (size_t)row * DMODEL + tid * 4;
    *(ushort4*)(xh + off) = hv;
    *(ushort4*)(xl + off) = lv;
}

// ---------------------------------------------------------------------------
// Kernel 2: transpose + fp16-hi for weights
// ---------------------------------------------------------------------------
__global__ __launch_bounds__(256) void splitT_kernel(
    const float* __restrict__ W, us* __restrict__ Th, int K, int N)
{
    __shared__ float t[32][33];
    int n0 = blockIdx.x * 32, k0 = blockIdx.y * 32;
    int tx = threadIdx.x, ty = threadIdx.y;
    #pragma unroll
    for (int j = 0; j < 4; j++) {
        int r = ty + j * 8;
        t[r][tx] = W[(size_t)(k0 + r) * N + n0 + tx];
    }
    __syncthreads();
    #pragma unroll
    for (int j = 0; j < 4; j++) {
        int r = ty + j * 8;
        Th[(size_t)(n0 + r) * K + k0 + tx] = to_h(t[tx][r]);
    }
}

// ---------------------------------------------------------------------------
// Kernel 3: fp16 2-term GEMM: C = (Ah+Al) @ Bh^T, fp32 acc.
// 128x128 block, 4 warps @ 64x64; GBK=64, 2-stage distance-1 ring (16 iters,
// half the syncs); 2 CTAs/SM. Rows 128 B, chunk swizzle c ^= (r & 7).
// Epilogue: fp32 (Cf) | fp16 h/l | fp16 hi only for columns >= vstart (V).
// ---------------------------------------------------------------------------
#define GK    1024
#define GBK   64
#define GARR  (128 * 128)             // 16384 B per array (128 rows x 128 B)
#define GBLK  (3 * GARR)              // 49152 B per stage {Ah,Al,Bh}
#define GSMEM (2 * GBLK)              // 98304 B

__global__ __launch_bounds__(128, 2) void mma_gemm(
    const us* __restrict__ Ah, const us* __restrict__ Al,
    const us* __restrict__ Bh,
    float* __restrict__ Cf, us* __restrict__ Ch, us* __restrict__ Cl,
    int N, int vstart)
{
    extern __shared__ char smg[];
    const uint32_t sb = (uint32_t)__cvta_generic_to_shared(smg);

    const int tid  = threadIdx.x;
    const int lane = tid & 31, wid = tid >> 5;
    const int wm = wid >> 1, wn = wid & 1;
    const int m0 = blockIdx.y * 128, n0 = blockIdx.x * 128;

    float acc[4][8][4];
    #pragma unroll
    for (int f = 0; f < 4; f++)
        #pragma unroll
        for (int j = 0; j < 8; j++)
            #pragma unroll
            for (int e = 0; e < 4; e++) acc[f][j][e] = 0.f;

    const int arow = wm * 64 + (lane & 15);
    const uint32_t abase = (uint32_t)(arow * 128);
    const uint32_t axor  = (uint32_t)(arow & 7);       // chunk-index XOR
    const uint32_t achk  = (uint32_t)(lane >> 4);      // + ks*2

    const int brow = wn * 64 + (lane & 7) + ((lane >> 4) << 3);
    const uint32_t bbase = (uint32_t)(brow * 128);
    const uint32_t bxor  = (uint32_t)(brow & 7);
    const uint32_t bchk  = (uint32_t)((lane >> 3) & 1);

    // copy: 3 arrays x 1024 chunks per stage, 8 chunks/thread/array
#define STAGE_COPY(st, kc)                                                     \
    do {                                                                       \
        uint32_t so = sb + (uint32_t)(st) * GBLK;                              \
        _Pragma("unroll")                                                      \
        for (int t = 0; t < 24; t++) {                                         \
            const int arr = t >> 3;       /* 0=Ah 1=Al 2=Bh */                 \
            const int idx = tid + (t & 7) * 128;                               \
            const int r = idx >> 3, c = idx & 7;                               \
            uint32_t d = so + (uint32_t)arr * GARR                             \
                       + (uint32_t)(r * 128 + ((c ^ (r & 7)) << 4));           \
            const us* srcp =                                                   \
                (arr == 0) ? (Ah + (size_t)(m0 + r) * GK + (kc) + c * 8) :     \
                (arr == 1) ? (Al + (size_t)(m0 + r) * GK + (kc) + c * 8) :     \
                             (Bh + (size_t)(n0 + r) * GK + (kc) + c * 8);      \
            cp16(d, srcp);                                                     \
        }                                                                      \
    } while (0)

    STAGE_COPY(0, 0);
    asm volatile("cp.async.commit_group;" ::: "memory");

    const int nk = GK / GBK;   // 16
    for (int kt = 0; kt < nk; kt++) {
        const int st = kt & 1;
        asm volatile("cp.async.wait_group 0;" ::: "memory");
        __syncthreads();

        if (kt + 1 < nk) { STAGE_COPY(st ^ 1, (kt + 1) * GBK); }
        asm volatile("cp.async.commit_group;" ::: "memory");

        const uint32_t so = sb + (uint32_t)st * GBLK;
        #pragma unroll
        for (int ks = 0; ks < 4; ks++) {
            uint32_t bh[4][4];
            #pragma unroll
            for (int nb = 0; nb < 4; nb++) {
                uint32_t o = so + 2*GARR + bbase + (uint32_t)(nb * 16 * 128)
                           + (((bchk + ks*2) ^ bxor) << 4);
                ldsm4(bh[nb], o);
            }
            #pragma unroll
            for (int f = 0; f < 4; f++) {
                uint32_t ah[4], al[4];
                uint32_t o = so + abase + (uint32_t)(f * 16 * 128)
                           + (((achk + ks*2) ^ axor) << 4);
                ldsm4(ah, o);
                ldsm4(al, o + GARR);
                #pragma unroll
                for (int j = 0; j < 8; j++) {
                    uint32_t bp[2] = { bh[j >> 1][(j & 1) * 2],
                                       bh[j >> 1][(j & 1) * 2 + 1] };
                    mma_fp16(acc[f][j], ah, bp);
                }
                #pragma unroll
                for (int j = 0; j < 8; j++) {
                    uint32_t bp[2] = { bh[j >> 1][(j & 1) * 2],
                                       bh[j >> 1][(j & 1) * 2 + 1] };
                    mma_fp16(acc[f][j], al, bp);
                }
            }
        }
    }

    const int erow = m0 + wm * 64 + (lane >> 2);
    const int ecol = n0 + wn * 64 + (lane & 3) * 2;
    if (Cf) {
        #pragma unroll
        for (int f = 0; f < 4; f++) {
            #pragma unroll
            for (int j = 0; j < 8; j++) {
                float* d0 = Cf + (size_t)(erow + f * 16)     * N + ecol + j * 8;
                float* d1 = Cf + (size_t)(erow + f * 16 + 8) * N + ecol + j * 8;
                *(float2*)d0 = make_float2(acc[f][j][0], acc[f][j][1]);
                *(float2*)d1 = make_float2(acc[f][j][2], acc[f][j][3]);
            }
        }
    } else if (n0 >= vstart) {
        // V section: fp16 hi only
        #pragma unroll
        for (int f = 0; f < 4; f++) {
            #pragma unroll
            for (int j = 0; j < 8; j++) {
                #pragma unroll
                for (int half = 0; half < 2; half++) {
                    size_t o = (size_t)(erow + f*16 + half*8) * N + ecol + j*8;
                    ushort2 hv = { to_h(acc[f][j][half*2]),
                                   to_h(acc[f][j][half*2 + 1]) };
                    *(ushort2*)(Ch + o) = hv;
                }
            }
        }
    } else {
        // Q,K section: fp16 hi/lo
        #pragma unroll
        for (int f = 0; f < 4; f++) {
            #pragma unroll
            for (int j = 0; j < 8; j++) {
                #pragma unroll
                for (int half = 0; half < 2; half++) {
                    size_t o = (size_t)(erow + f*16 + half*8) * N + ecol + j*8;
                    ushort2 hv, lv;
                    split_h(acc[f][j][half*2],     hv.x, lv.x);
                    split_h(acc[f][j][half*2 + 1], hv.y, lv.y);
                    *(ushort2*)(Ch + o) = hv;
                    *(ushort2*)(Cl + o) = lv;
                }
            }
        }
    }
#undef STAGE_COPY
}

// ---------------------------------------------------------------------------
// Kernel 4: flash attention, all fp16 2-term.
// KV stage now 128 rows {Kh,Vh}; 16 outer iterations, two 64-col subtiles per
// iteration (register shapes unchanged). 2-stage distance-1 ring; 2 CTAs/SM.
// ---------------------------------------------------------------------------
#define AST    72                       // smem row stride (16-bit elems)
#define AKB    (128 * AST * 2)          // 18432 B per K/V array (128 rows)
#define AKVST  (2 * AKB)                // 36864 B per stage {Kh,Vh}
#define AQB    (128 * AST * 2)          // 18432 B per Q array
#define ASMEM  (2 * AKVST + 2 * AQB)    // 110592 B
#define ASUB   (64 * AST * 2)           // 64-row subtile byte offset

__global__ __launch_bounds__(128, 2) void attn_mma_kernel(
    const us* __restrict__ qh_g, const us* __restrict__ ql_g,
    const float* __restrict__ mask,
    us* __restrict__ ctxh, us* __restrict__ ctxl)
{
    extern __shared__ char sma[];
    const uint32_t sb  = (uint32_t)__cvta_generic_to_shared(sma);
    const uint32_t uQh = sb + 2 * AKVST;
    const uint32_t uQl = uQh + AQB;

    const int tid = threadIdx.x, lane = tid & 31, wq = tid >> 5;
    const int qt = blockIdx.x, h = blockIdx.y, b = blockIdx.z;
    const int q0 = qt * 128;
    const size_t rowbase = (size_t)b * NSEQ;
    const size_t qkstride = 3 * INNER;

    // copy 128 rows of Kh and Vh: 2 arrays x 1024 chunks, 8/thread/array
#define KV_COPY(st, kc)                                                        \
    do {                                                                       \
        uint32_t so = sb + (uint32_t)(st) * AKVST;                             \
        _Pragma("unroll")                                                      \
        for (int t = 0; t < 16; t++) {                                         \
            const int arr = t >> 3;   /* 0=Kh 1=Vh */                          \
            const int idx = tid + (t & 7) * 128;                               \
            const int r = idx >> 3, c = idx & 7;                               \
            uint32_t d = so + (uint32_t)arr * AKB                              \
                       + (uint32_t)(r * AST + c * 8) * 2;                      \
            size_t col = ((arr == 0) ? INNER : 2*INNER) + h*DH + c*8;          \
            size_t g = (rowbase + (kc) + r) * qkstride + col;                  \
            cp16(d, qh_g + g);                                                 \
        }                                                                      \
    } while (0)

    // prologue: Q copy (h + l) + KV stage 0
    {
        #pragma unroll
        for (int t = 0; t < 16; t++) {
            const int arr = t >> 3;
            const int r = (t & 7) * 16 + (tid >> 3);
            const int c = tid & 7;
            uint32_t d = uQh + (uint32_t)arr * AQB + (uint32_t)(r * AST + c * 8) * 2;
            size_t g = (rowbase + q0 + r) * qkstride + h * DH + c * 8;
            cp16(d, arr ? (ql_g + g) : (qh_g + g));
        }
    }
    KV_COPY(0, 0);
    asm volatile("cp.async.commit_group;" ::: "memory");

    float oacc[2][8][4];
    #pragma unroll
    for (int mf = 0; mf < 2; mf++)
        #pragma unroll
        for (int j = 0; j < 8; j++)
            #pragma unroll
            for (int e = 0; e < 4; e++) oacc[mf][j][e] = 0.f;
    float rmax[4] = {-1e30f, -1e30f, -1e30f, -1e30f};
    float rsum[4] = {0.f, 0.f, 0.f, 0.f};

    const uint32_t qoff0 = (uint32_t)((wq*32 + (lane & 15)) * AST
                           + (lane >> 4) * 8) * 2;
    const uint32_t koffb = (uint32_t)(((lane & 7) + ((lane >> 4) << 3)) * AST
                           + ((lane >> 3) & 1) * 8) * 2;
    const uint32_t voffb = (uint32_t)(((lane & 15)) * AST + (lane >> 4) * 8) * 2;

    const int nk = NSEQ / 128;   // 16
    for (int kt = 0; kt < nk; kt++) {
        const int st = kt & 1;
        asm volatile("cp.async.wait_group 0;" ::: "memory");
        __syncthreads();

        if (kt + 1 < nk) { KV_COPY(st ^ 1, (kt + 1) * 128); }
        asm volatile("cp.async.commit_group;" ::: "memory");

        const uint32_t stbase = sb + (uint32_t)st * AKVST;

        #pragma unroll
        for (int sub = 0; sub < 2; sub++) {
            const uint32_t so = stbase + (uint32_t)sub * ASUB;      // Kh rows
            const uint32_t sV = stbase + AKB + (uint32_t)sub * ASUB; // Vh rows

            // ---- S = (Qh+Ql) Kh^T (fp16, 2-term), 2 m-frags per warp
            float sacc[2][8][4];
            #pragma unroll
            for (int mf = 0; mf < 2; mf++)
                #pragma unroll
                for (int j = 0; j < 8; j++)
                    #pragma unroll
                    for (int e = 0; e < 4; e++) sacc[mf][j][e] = 0.f;

            #pragma unroll
            for (int kk = 0; kk < 4; kk++) {
                uint32_t qh[2][4], ql[2][4];
                #pragma unroll
                for (int mf = 0; mf < 2; mf++) {
                    uint32_t qo = (mf ? (uQh + (uint32_t)(16 * AST * 2)) : uQh)
                                + qoff0 + (uint32_t)(kk * 16) * 2;
                    ldsm4(qh[mf], qo);
                    ldsm4(ql[mf], qo + AQB);
                }
                #pragma unroll
                for (int jb = 0; jb < 4; jb++) {
                    uint32_t kbh[4];
                    uint32_t o = so + koffb + (uint32_t)(jb * 16 * AST + kk * 16) * 2;
                    ldsm4(kbh, o);
                    const int j0 = jb * 2, j1 = jb * 2 + 1;
                    uint32_t bh0[2] = { kbh[0], kbh[1] }, bh1[2] = { kbh[2], kbh[3] };
                    mma_fp16(sacc[0][j0], qh[0], bh0);
                    mma_fp16(sacc[0][j1], qh[0], bh1);
                    mma_fp16(sacc[1][j0], qh[1], bh0);
                    mma_fp16(sacc[1][j1], qh[1], bh1);
                    mma_fp16(sacc[0][j0], ql[0], bh0);
                    mma_fp16(sacc[0][j1], ql[0], bh1);
                    mma_fp16(sacc[1][j0], ql[1], bh0);
                    mma_fp16(sacc[1][j1], ql[1], bh1);
                }
            }

            // ---- mask add (before scale), scale to exp2 domain; softmax
            #pragma unroll
            for (int mf = 0; mf < 2; mf++) {
                const int qrow = q0 + wq * 32 + mf * 16 + (lane >> 2);
                const int kcol = kt * 128 + sub * 64 + (lane & 3) * 2;
                const float* mg = mask + ((size_t)b * NSEQ + qrow) * NSEQ + kcol;
                #pragma unroll
                for (int j = 0; j < 8; j++) {
                    float2 m0 = *(const float2*)(mg + j * 8);
                    float2 m1 = *(const float2*)(mg + 8 * NSEQ + j * 8);
                    sacc[mf][j][0] = (sacc[mf][j][0] + m0.x) * SC2;
                    sacc[mf][j][1] = (sacc[mf][j][1] + m0.y) * SC2;
                    sacc[mf][j][2] = (sacc[mf][j][2] + m1.x) * SC2;
                    sacc[mf][j][3] = (sacc[mf][j][3] + m1.y) * SC2;
                }

                float tm0 = -1e30f, tm1 = -1e30f;
                #pragma unroll
                for (int j = 0; j < 8; j++) {
                    tm0 = fmaxf(tm0, fmaxf(sacc[mf][j][0], sacc[mf][j][1]));
                    tm1 = fmaxf(tm1, fmaxf(sacc[mf][j][2], sacc[mf][j][3]));
                }
                #pragma unroll
                for (int off = 1; off <= 2; off <<= 1) {
                    tm0 = fmaxf(tm0, __shfl_xor_sync(0xffffffffu, tm0, off));
                    tm1 = fmaxf(tm1, __shfl_xor_sync(0xffffffffu, tm1, off));
                }
                float nm0 = fmaxf(rmax[mf*2],   tm0);
                float nm1 = fmaxf(rmax[mf*2+1], tm1);
                float corr0 = ex2(rmax[mf*2]   - nm0);
                float corr1 = ex2(rmax[mf*2+1] - nm1);
                rmax[mf*2] = nm0; rmax[mf*2+1] = nm1;

                float ps0 = 0.f, ps1 = 0.f;
                #pragma unroll
                for (int j = 0; j < 8; j++) {
                    sacc[mf][j][0] = ex2(sacc[mf][j][0] - nm0);
                    sacc[mf][j][1] = ex2(sacc[mf][j][1] - nm0);
                    sacc[mf][j][2] = ex2(sacc[mf][j][2] - nm1);
                    sacc[mf][j][3] = ex2(sacc[mf][j][3] - nm1);
                    ps0 += sacc[mf][j][0] + sacc[mf][j][1];
                    ps1 += sacc[mf][j][2] + sacc[mf][j][3];
                }
                #pragma unroll
                for (int off = 1; off <= 2; off <<= 1) {
                    ps0 += __shfl_xor_sync(0xffffffffu, ps0, off);
                    ps1 += __shfl_xor_sync(0xffffffffu, ps1, off);
                }
                rsum[mf*2]   = rsum[mf*2]   * corr0 + ps0;
                rsum[mf*2+1] = rsum[mf*2+1] * corr1 + ps1;

                #pragma unroll
                for (int j = 0; j < 8; j++) {
                    oacc[mf][j][0] *= corr0; oacc[mf][j][1] *= corr0;
                    oacc[mf][j][2] *= corr1; oacc[mf][j][3] *= corr1;
                }
            }

            // ---- O += (Ph + Pl) Vh (fp16, 2-term)
            #pragma unroll
            for (int kp = 0; kp < 4; kp++) {
                uint32_t pah[2][4], pal[2][4];
                #pragma unroll
                for (int mf = 0; mf < 2; mf++) {
                    const int j0 = kp * 2, j1 = kp * 2 + 1;
                    float p00 = sacc[mf][j0][0], p01 = sacc[mf][j0][1];
                    float p02 = sacc[mf][j0][2], p03 = sacc[mf][j0][3];
                    float p10 = sacc[mf][j1][0], p11 = sacc[mf][j1][1];
                    float p12 = sacc[mf][j1][2], p13 = sacc[mf][j1][3];
                    pah[mf][0] = packh2(p00, p01);
                    pah[mf][1] = packh2(p02, p03);
                    pah[mf][2] = packh2(p10, p11);
                    pah[mf][3] = packh2(p12, p13);
                    __half2* hp;
                    hp = (__half2*)&pah[mf][0];
                    pal[mf][0] = packh2(p00 - __half2float(hp->x), p01 - __half2float(hp->y));
                    hp = (__half2*)&pah[mf][1];
                    pal[mf][1] = packh2(p02 - __half2float(hp->x), p03 - __half2float(hp->y));
                    hp = (__half2*)&pah[mf][2];
                    pal[mf][2] = packh2(p10 - __half2float(hp->x), p11 - __half2float(hp->y));
                    hp = (__half2*)&pah[mf][3];
                    pal[mf][3] = packh2(p12 - __half2float(hp->x), p13 - __half2float(hp->y));
                }
                #pragma unroll
                for (int db = 0; db < 4; db++) {
                    uint32_t vbh[4];
                    uint32_t o = sV + voffb + (uint32_t)(kp * 16 * AST + db * 16) * 2;
                    ldsm4t(vbh, o);
                    const int j0 = db * 2, j1 = db * 2 + 1;
                    uint32_t bh0[2] = { vbh[0], vbh[1] }, bh1[2] = { vbh[2], vbh[3] };
                    mma_fp16(oacc[0][j0], pah[0], bh0);
                    mma_fp16(oacc[0][j1], pah[0], bh1);
                    mma_fp16(oacc[1][j0], pah[1], bh0);
                    mma_fp16(oacc[1][j1], pah[1], bh1);
                    mma_fp16(oacc[0][j0], pal[0], bh0);
                    mma_fp16(oacc[0][j1], pal[0], bh1);
                    mma_fp16(oacc[1][j0], pal[1], bh0);
                    mma_fp16(oacc[1][j1], pal[1], bh1);
                }
            }
        }
    }
#undef KV_COPY

    // ---- normalize + write ctx (fp16 hi/lo)
    #pragma unroll
    for (int mf = 0; mf < 2; mf++) {
        const float inv0 = 1.0f / rsum[mf*2], inv1 = 1.0f / rsum[mf*2+1];
        const int row0 = q0 + wq * 32 + mf * 16 + (lane >> 2);
        #pragma unroll
        for (int j = 0; j < 8; j++) {
            const int col = h * DH + j * 8 + (lane & 3) * 2;
            float v0 = oacc[mf][j][0] * inv0, v1 = oacc[mf][j][1] * inv0;
            float v2 = oacc[mf][j][2] * inv1, v3 = oacc[mf][j][3] * inv1;
            ushort2 a0, b0, a1, b1;
            split_h(v0, a0.x, b0.x); split_h(v1, a0.y, b0.y);
            split_h(v2, a1.x, b1.x); split_h(v3, a1.y, b1.y);
            size_t o0 = (rowbase + row0)     * (size_t)INNER + col;
            size_t o1 = (rowbase + row0 + 8) * (size_t)INNER + col;
            *(ushort2*)(ctxh + o0) = a0;
            *(ushort2*)(ctxl + o0) = b0;
            *(ushort2*)(ctxh + o1) = a1;
            *(ushort2*)(ctxl + o1) = b1;
        }
    }
}

// ---------------------------------------------------------------------------
// launch
// ---------------------------------------------------------------------------
extern "C" void kernel_launch(void* const* d_in, const int* in_sizes, int n_in,
                              void* d_out, int out_size)
{
    const float* x     = (const float*)d_in[0];
    const float* m     = (const float*)d_in[1];
    const float* gamma = (const float*)d_in[2];
    const float* beta  = (const float*)d_in[3];
    const float* Wqkv  = (const float*)d_in[4];
    const float* Wout  = (const float*)d_in[5];
    float* out = (float*)d_out;

    us *xnh, *xnl, *wqh, *woh, *qkvh, *qkvl, *ctxh, *ctxl;
    cudaGetSymbolAddress((void**)&xnh,  g_xn_h);
    cudaGetSymbolAddress((void**)&xnl,  g_xn_l);
    cudaGetSymbolAddress((void**)&wqh,  g_wq_h);
    cudaGetSymbolAddress((void**)&woh,  g_wo_h);
    cudaGetSymbolAddress((void**)&qkvh, g_qkv_h);
    cudaGetSymbolAddress((void**)&qkvl, g_qkv_l);
    cudaGetSymbolAddress((void**)&ctxh, g_ctx_h);
    cudaGetSymbolAddress((void**)&ctxl, g_ctx_l);

    cudaFuncSetAttribute(mma_gemm,
                         cudaFuncAttributeMaxDynamicSharedMemorySize, GSMEM);
    cudaFuncSetAttribute(attn_mma_kernel,
                         cudaFuncAttributeMaxDynamicSharedMemorySize, ASMEM);

    // 1. LayerNorm (+ fp16 split)
    ln_kernel<<<NROWS, 256>>>(x, gamma, beta, xnh, xnl);

    // 2. weight transpose (fp16 hi only)
    splitT_kernel<<<dim3(3*INNER/32, DMODEL/32), dim3(32,8)>>>(
        Wqkv, wqh, DMODEL, 3*INNER);
    splitT_kernel<<<dim3(DMODEL/32,  INNER/32),  dim3(32,8)>>>(
        Wout, woh, INNER, DMODEL);

    // 3. QKV projection (fp16 2-term); Q,K -> fp16 h/l, V -> fp16 hi
    mma_gemm<<<dim3(3*INNER/128, NROWS/128), 128, GSMEM>>>(
        xnh, xnl, wqh, nullptr, qkvh, qkvl, 3*INNER, 2*INNER);

    // 4. masked flash attention (all fp16 2-term)
    attn_mma_kernel<<<dim3(NSEQ/128, HEADS, BATCH), 128, ASMEM>>>(
        qkvh, qkvl, m, ctxh, ctxl);

    // 5. output projection (fp16 2-term) -> fp32 out
    mma_gemm<<<dim3(DMODEL/128, NROWS/128), 128, GSMEM>>>(
        ctxh, ctxl, woh, out, nullptr, nullptr, DMODEL, 1 << 30);
}